// round 7
// baseline (speedup 1.0000x reference)
#include <cuda_runtime.h>
#include <cuda_fp16.h>
#include <math.h>

#define B   16
#define S   1024
#define NF  5
#define D   64
#define H   8
#define HD  8
#define NL  2
#define FF  128
#define NQ  8
#define QL  3
#define BS  (B*S)
#define CK2  512          // keys per chunk (2 chunks)
#define VPAD2 520         // padded V row (halves): 260 uints, mod 32 = 4

typedef unsigned long long ull;
typedef unsigned int uint;

// ---------------- device scratch ----------------
__device__ float g_h  [BS*D];
__device__ float g_q  [BS*D];
__device__ float g_k  [BS*D];
__device__ float g_v  [BS*D];
__device__ float g_pe [S*D];
__device__ float g_part[(size_t)2*128*S*12];   // 12.6 MB partials

// ---------------- mma / f16 helpers ----------------
__device__ __forceinline__ void mma16n8k8(float& d0, float& d1, float& d2, float& d3,
                                          uint a0, uint a1, uint b0,
                                          float c0, float c1, float c2, float c3) {
    asm volatile("mma.sync.aligned.m16n8k8.row.col.f32.f16.f16.f32 "
        "{%0,%1,%2,%3}, {%4,%5}, {%6}, {%7,%8,%9,%10};"
        : "=f"(d0), "=f"(d1), "=f"(d2), "=f"(d3)
        : "r"(a0), "r"(a1), "r"(b0), "f"(c0), "f"(c1), "f"(c2), "f"(c3));
}
__device__ __forceinline__ void mma16n8k16(float* d,
                                           uint a0, uint a1, uint a2, uint a3,
                                           uint b0, uint b1) {
    asm volatile("mma.sync.aligned.m16n8k16.row.col.f32.f16.f16.f32 "
        "{%0,%1,%2,%3}, {%4,%5,%6,%7}, {%8,%9}, {%0,%1,%2,%3};"
        : "+f"(d[0]), "+f"(d[1]), "+f"(d[2]), "+f"(d[3])
        : "r"(a0), "r"(a1), "r"(a2), "r"(a3), "r"(b0), "r"(b1));
}
__device__ __forceinline__ uint cvt_f16x2(float hi, float lo) {
    uint r; asm("cvt.rn.f16x2.f32 %0, %1, %2;" : "=r"(r) : "f"(hi), "f"(lo)); return r;
}
__device__ __forceinline__ uint hex2x2(uint x) {
    uint r; asm("ex2.approx.f16x2 %0, %1;" : "=r"(r) : "r"(x)); return r;
}

// ---------------- complex helpers ----------------
__device__ __forceinline__ float2 cmul(float2 a, float2 b) {
    return make_float2(a.x*b.x - a.y*b.y, a.x*b.y + a.y*b.x);
}
__device__ __forceinline__ float2 cmulcj(float2 a, float2 b) {
    return make_float2(a.x*b.x + a.y*b.y, a.x*b.y - a.y*b.x);
}
__device__ __forceinline__ float2 cadd(float2 a, float2 b) {
    return make_float2(a.x + b.x, a.y + b.y);
}

// ---------------- 0) positional-encoding table ----------------
__global__ void k_pe() {
    int idx = blockIdx.x * blockDim.x + threadIdx.x;   // < 32768
    int s = idx >> 5, p = idx & 31;
    float div = __expf(-0.14391156831212787f * (float)(2*p));
    float sn, cs;
    sincosf((float)s * div, &sn, &cs);
    g_pe[s*64 + 2*p]     = sn;
    g_pe[s*64 + 2*p + 1] = cs;
}

// ---------------- 1) embedding ----------------
__global__ void k_embed(const float* __restrict__ x,
                        const float* __restrict__ Wemb,
                        const float* __restrict__ bemb) {
    int idx = blockIdx.x * blockDim.x + threadIdx.x;   // < BS*D
    int c   = idx & (D-1);
    int row = idx >> 6;
    int s   = row & (S-1);
    float acc = bemb[c] + g_pe[s*64 + c];
    const float* xr = x + row * NF;
#pragma unroll
    for (int f = 0; f < NF; f++) acc += xr[f] * Wemb[f*D + c];
    g_h[idx] = acc;
}

// ======== MMA GEMM common fragment loaders ========
__device__ __forceinline__ void load_afrag64(uint (&a)[4][4], const uint* sA, int rbase, int gid, int tig) {
    const uint* r0 = sA + (rbase + gid)*36;
    const uint* r1 = sA + (rbase + gid + 8)*36;
#pragma unroll
    for (int kk = 0; kk < 4; kk++) {
        a[kk][0] = r0[kk*8 + tig];
        a[kk][1] = r1[kk*8 + tig];
        a[kk][2] = r0[kk*8 + 4 + tig];
        a[kk][3] = r1[kk*8 + 4 + tig];
    }
}

// ---------------- 2) QKV projection via mma (64 rows/block) ----------------
__global__ void __launch_bounds__(128) k_qkv_mma(
        const float* __restrict__ Wq, const float* __restrict__ bq,
        const float* __restrict__ Wk, const float* __restrict__ bk,
        const float* __restrict__ Wv, const float* __restrict__ bv, int l) {
    __shared__ uint sA [64*36];
    __shared__ uint sWp[3*32*68];
    int tid = threadIdx.x;
    int row0 = blockIdx.x * 64;
    for (int idx = tid; idx < 2048; idx += 128) {
        int r = idx >> 5, c2 = idx & 31;
        float2 v = *(const float2*)(g_h + (size_t)(row0 + r)*D + c2*2);
        sA[r*36 + c2] = cvt_f16x2(v.y, v.x);
    }
    const float* Ws[3] = { Wq + l*4096, Wk + l*4096, Wv + l*4096 };
    for (int m = 0; m < 3; m++) {
        const float* W = Ws[m];
        for (int idx = tid; idx < 2048; idx += 128) {
            int ip = idx >> 6, n = idx & 63;
            sWp[m*2176 + ip*68 + n] = cvt_f16x2(W[(2*ip+1)*64 + n], W[(2*ip)*64 + n]);
        }
    }
    __syncthreads();

    int warp = tid >> 5, lane = tid & 31;
    int gid = lane >> 2, tig = lane & 3;
    uint a[4][4];
    load_afrag64(a, sA, warp*16, gid, tig);

    const float* bs[3] = { bq + l*D, bk + l*D, bv + l*D };
    float* outs[3] = { g_q, g_k, g_v };
#pragma unroll
    for (int m = 0; m < 3; m++) {
        const uint* Wp = sWp + m*2176;
        const float* bias = bs[m];
        float* out = outs[m];
#pragma unroll
        for (int t = 0; t < 8; t++) {
            float acc[4] = {0,0,0,0};
#pragma unroll
            for (int kk = 0; kk < 4; kk++) {
                uint b0 = Wp[(kk*8 + tig)*68 + t*8 + gid];
                uint b1 = Wp[(kk*8 + 4 + tig)*68 + t*8 + gid];
                mma16n8k16(acc, a[kk][0], a[kk][1], a[kk][2], a[kk][3], b0, b1);
            }
            float2 bv2 = *(const float2*)(bias + t*8 + tig*2);
            int r = row0 + warp*16 + gid;
            *(float2*)(out + (size_t)r*D + t*8 + tig*2) =
                make_float2(acc[0] + bv2.x, acc[1] + bv2.y);
            *(float2*)(out + (size_t)(r + 8)*D + t*8 + tig*2) =
                make_float2(acc[2] + bv2.x, acc[3] + bv2.y);
        }
    }
}

// ---------------- 3) split-K attention via mma (partials to gmem) ----------------
// grid: x = qtile(8) * chunk(2) = 16, y = 128 (bh). 2048 CTAs, 16.6KB smem.
__global__ void __launch_bounds__(128) k_attn_mma() {
    __shared__ __half sK [CK2*8];        // 8 KB
    __shared__ __half sVT[8*VPAD2];      // 8.3 KB
    int tid = threadIdx.x;
    int bh  = blockIdx.y;
    int b   = bh >> 3, hh = bh & 7;
    int qt  = blockIdx.x >> 1;
    int ck  = blockIdx.x & 1;
    int k0  = ck * CK2;
    const float* kbase = g_k + (size_t)(b*S + k0)*D + hh*HD;
    const float* vbase = g_v + (size_t)(b*S + k0)*D + hh*HD;
    for (int i = tid; i < CK2*8; i += 128) {
        int key = i >> 3, d = i & 7;
        sK[i]             = __float2half(kbase[key*D + d]);
        sVT[d*VPAD2 + key] = __float2half(vbase[key*D + d]);
    }
    __syncthreads();

    int warp = tid >> 5, lane = tid & 31;
    int gid  = lane >> 2, tig = lane & 3;
    int q0   = qt * 128 + warp * 32;
    const float pre = 0.35355339059327373f * 1.4426950408889634f;  // scale*log2(e)

    uint qa[2][2];
#pragma unroll
    for (int t2 = 0; t2 < 2; t2++) {
#pragma unroll
        for (int hf = 0; hf < 2; hf++) {
            int qrow = q0 + t2*16 + gid + hf*8;
            float2 qv = *(const float2*)(g_q + (size_t)(b*S + qrow)*D + hh*HD + tig*2);
            qa[t2][hf] = cvt_f16x2(qv.y*pre, qv.x*pre);
        }
    }

    float acc0[4] = {0,0,0,0}, acc1[4] = {0,0,0,0};
    float lac0[4] = {0,0,0,0}, lac1[4] = {0,0,0,0};
    const uint ones2 = 0x3C003C00u;
    const __half* kptr = sK  + gid*8 + tig*2;
    const __half* vptr = sVT + gid*VPAD2 + tig*2;

#pragma unroll 2
    for (int j0 = 0; j0 < CK2; j0 += 8) {
        uint kb = *(const uint*)(kptr + j0*8);
        uint vb = *(const uint*)(vptr + j0);
        {
            float s0, s1, s2, s3;
            mma16n8k8(s0, s1, s2, s3, qa[0][0], qa[0][1], kb, 0.f, 0.f, 0.f, 0.f);
            uint p0 = hex2x2(cvt_f16x2(s1, s0));
            uint p1 = hex2x2(cvt_f16x2(s3, s2));
            mma16n8k8(acc0[0], acc0[1], acc0[2], acc0[3], p0, p1, vb,
                      acc0[0], acc0[1], acc0[2], acc0[3]);
            mma16n8k8(lac0[0], lac0[1], lac0[2], lac0[3], p0, p1, ones2,
                      lac0[0], lac0[1], lac0[2], lac0[3]);
        }
        {
            float s0, s1, s2, s3;
            mma16n8k8(s0, s1, s2, s3, qa[1][0], qa[1][1], kb, 0.f, 0.f, 0.f, 0.f);
            uint p0 = hex2x2(cvt_f16x2(s1, s0));
            uint p1 = hex2x2(cvt_f16x2(s3, s2));
            mma16n8k8(acc1[0], acc1[1], acc1[2], acc1[3], p0, p1, vb,
                      acc1[0], acc1[1], acc1[2], acc1[3]);
            mma16n8k8(lac1[0], lac1[1], lac1[2], lac1[3], p0, p1, ones2,
                      lac1[0], lac1[1], lac1[2], lac1[3]);
        }
    }

    // store unnormalized partials: [ck][bh][q][12] (8 acc, lsum at +8)
    size_t base = ((size_t)ck*128 + bh)*S;
    {
        float* pp = g_part + (base + q0 + gid)*12;
        *(float2*)(pp + tig*2) = make_float2(acc0[0], acc0[1]);
        if (tig == 0) pp[8] = lac0[0];
        pp = g_part + (base + q0 + gid + 8)*12;
        *(float2*)(pp + tig*2) = make_float2(acc0[2], acc0[3]);
        if (tig == 0) pp[8] = lac0[2];
        pp = g_part + (base + q0 + 16 + gid)*12;
        *(float2*)(pp + tig*2) = make_float2(acc1[0], acc1[1]);
        if (tig == 0) pp[8] = lac1[0];
        pp = g_part + (base + q0 + 24 + gid)*12;
        *(float2*)(pp + tig*2) = make_float2(acc1[2], acc1[3]);
        if (tig == 0) pp[8] = lac1[2];
    }
}

// ---------------- 4) combine + oproj + residual + LN1 via mma ----------------
__global__ void __launch_bounds__(128) k_oproj_mma(
        const float* __restrict__ Wo, const float* __restrict__ bo,
        const float* __restrict__ g1, const float* __restrict__ b1, int l) {
    __shared__ uint sA [64*36];
    __shared__ uint sWp[32*68];
    int tid = threadIdx.x;
    int row0 = blockIdx.x * 64;
    // combine attention partials -> normalized attention output (fp16 A)
    for (int idx = tid; idx < 2048; idx += 128) {
        int r = idx >> 5, c2 = idx & 31;
        int grow = row0 + r;
        int q  = grow & (S-1);
        int bb = grow >> 10;
        int hh = c2 >> 2;
        int bh = bb*8 + hh;
        int off = (c2 & 3)*2;
        const float* p0 = g_part + ((size_t)(0*128 + bh)*S + q)*12;
        const float* p1 = g_part + ((size_t)(1*128 + bh)*S + q)*12;
        float inv = 1.0f / (p0[8] + p1[8]);
        float a0 = (p0[off]   + p1[off])   * inv;
        float a1 = (p0[off+1] + p1[off+1]) * inv;
        sA[r*36 + c2] = cvt_f16x2(a1, a0);
    }
    const float* W = Wo + l*4096;
    for (int idx = tid; idx < 2048; idx += 128) {
        int ip = idx >> 6, n = idx & 63;
        sWp[ip*68 + n] = cvt_f16x2(W[(2*ip+1)*64 + n], W[(2*ip)*64 + n]);
    }
    __syncthreads();

    int warp = tid >> 5, lane = tid & 31;
    int gid = lane >> 2, tig = lane & 3;
    uint a[4][4];
    load_afrag64(a, sA, warp*16, gid, tig);

    float acc[8][4];
#pragma unroll
    for (int t = 0; t < 8; t++) {
        acc[t][0]=0; acc[t][1]=0; acc[t][2]=0; acc[t][3]=0;
#pragma unroll
        for (int kk = 0; kk < 4; kk++) {
            uint b0 = sWp[(kk*8 + tig)*68 + t*8 + gid];
            uint b1 = sWp[(kk*8 + 4 + tig)*68 + t*8 + gid];
            mma16n8k16(acc[t], a[kk][0], a[kk][1], a[kk][2], a[kk][3], b0, b1);
        }
    }
    int rA = row0 + warp*16 + gid;
    int rB = rA + 8;
    float vA[16], vB[16];
    float sumA=0, sqA=0, sumB=0, sqB=0;
#pragma unroll
    for (int t = 0; t < 8; t++) {
        float2 bo2 = *(const float2*)(bo + l*D + t*8 + tig*2);
        float2 hA = *(const float2*)(g_h + (size_t)rA*D + t*8 + tig*2);
        float2 hB = *(const float2*)(g_h + (size_t)rB*D + t*8 + tig*2);
        float a0 = acc[t][0] + bo2.x + hA.x;
        float a1 = acc[t][1] + bo2.y + hA.y;
        float b0 = acc[t][2] + bo2.x + hB.x;
        float b1 = acc[t][3] + bo2.y + hB.y;
        vA[t*2]=a0; vA[t*2+1]=a1; vB[t*2]=b0; vB[t*2+1]=b1;
        sumA += a0+a1; sqA += a0*a0+a1*a1;
        sumB += b0+b1; sqB += b0*b0+b1*b1;
    }
#pragma unroll
    for (int o = 1; o < 4; o <<= 1) {
        sumA += __shfl_xor_sync(0xffffffffu, sumA, o);
        sqA  += __shfl_xor_sync(0xffffffffu, sqA,  o);
        sumB += __shfl_xor_sync(0xffffffffu, sumB, o);
        sqB  += __shfl_xor_sync(0xffffffffu, sqB,  o);
    }
    float mA = sumA*(1.f/64.f), vrA = sqA*(1.f/64.f) - mA*mA;
    float mB = sumB*(1.f/64.f), vrB = sqB*(1.f/64.f) - mB*mB;
    float rsA = rsqrtf(vrA + 1e-5f), rsB = rsqrtf(vrB + 1e-5f);
#pragma unroll
    for (int t = 0; t < 8; t++) {
        float2 gg = *(const float2*)(g1 + l*D + t*8 + tig*2);
        float2 bb = *(const float2*)(b1 + l*D + t*8 + tig*2);
        *(float2*)(g_h + (size_t)rA*D + t*8 + tig*2) =
            make_float2((vA[t*2]-mA)*rsA*gg.x + bb.x, (vA[t*2+1]-mA)*rsA*gg.y + bb.y);
        *(float2*)(g_h + (size_t)rB*D + t*8 + tig*2) =
            make_float2((vB[t*2]-mB)*rsB*gg.x + bb.x, (vB[t*2+1]-mB)*rsB*gg.y + bb.y);
    }
}

// ---------------- 5) fused FFN via mma (64 rows/block) ----------------
__global__ void __launch_bounds__(128) k_ffn_mma(
        const float* __restrict__ Wf1, const float* __restrict__ bf1,
        const float* __restrict__ Wf2, const float* __restrict__ bf2,
        const float* __restrict__ g2, const float* __restrict__ b2, int l) {
    __shared__ uint sA  [64*36];
    __shared__ uint sW1p[32*132];
    __shared__ uint sW2p[64*68];
    int tid = threadIdx.x;
    int row0 = blockIdx.x * 64;
    for (int idx = tid; idx < 2048; idx += 128) {
        int r = idx >> 5, c2 = idx & 31;
        float2 v = *(const float2*)(g_h + (size_t)(row0 + r)*D + c2*2);
        sA[r*36 + c2] = cvt_f16x2(v.y, v.x);
    }
    const float* W1 = Wf1 + l*8192;
    const float* W2 = Wf2 + l*8192;
    for (int idx = tid; idx < 4096; idx += 128) {
        int ip = idx >> 7, n = idx & 127;
        sW1p[ip*132 + n] = cvt_f16x2(W1[(2*ip+1)*128 + n], W1[(2*ip)*128 + n]);
    }
    for (int idx = tid; idx < 4096; idx += 128) {
        int ip = idx >> 6, n = idx & 63;
        sW2p[ip*68 + n] = cvt_f16x2(W2[(2*ip+1)*64 + n], W2[(2*ip)*64 + n]);
    }
    __syncthreads();

    int warp = tid >> 5, lane = tid & 31;
    int gid = lane >> 2, tig = lane & 3;
    uint a[4][4];
    load_afrag64(a, sA, warp*16, gid, tig);

    uint hA[16][2];
#pragma unroll
    for (int t = 0; t < 16; t++) {
        float acc[4] = {0,0,0,0};
#pragma unroll
        for (int kk = 0; kk < 4; kk++) {
            uint b0 = sW1p[(kk*8 + tig)*132 + t*8 + gid];
            uint b1 = sW1p[(kk*8 + 4 + tig)*132 + t*8 + gid];
            mma16n8k16(acc, a[kk][0], a[kk][1], a[kk][2], a[kk][3], b0, b1);
        }
        float2 bf = *(const float2*)(bf1 + l*FF + t*8 + tig*2);
        float c0 = fmaxf(acc[0] + bf.x, 0.f);
        float c1 = fmaxf(acc[1] + bf.y, 0.f);
        float c2 = fmaxf(acc[2] + bf.x, 0.f);
        float c3 = fmaxf(acc[3] + bf.y, 0.f);
        hA[t][0] = cvt_f16x2(c1, c0);
        hA[t][1] = cvt_f16x2(c3, c2);
    }

    float acc[8][4];
#pragma unroll
    for (int t = 0; t < 8; t++) {
        acc[t][0]=0; acc[t][1]=0; acc[t][2]=0; acc[t][3]=0;
#pragma unroll
        for (int kk = 0; kk < 8; kk++) {
            uint b0 = sW2p[(kk*8 + tig)*68 + t*8 + gid];
            uint b1 = sW2p[(kk*8 + 4 + tig)*68 + t*8 + gid];
            mma16n8k16(acc[t], hA[2*kk][0], hA[2*kk][1], hA[2*kk+1][0], hA[2*kk+1][1], b0, b1);
        }
    }
    int rA = row0 + warp*16 + gid;
    int rB = rA + 8;
    float vA[16], vB[16];
    float sumA=0, sqA=0, sumB=0, sqB=0;
#pragma unroll
    for (int t = 0; t < 8; t++) {
        float2 bo2 = *(const float2*)(bf2 + l*D + t*8 + tig*2);
        float2 hAr = *(const float2*)(g_h + (size_t)rA*D + t*8 + tig*2);
        float2 hBr = *(const float2*)(g_h + (size_t)rB*D + t*8 + tig*2);
        float a0 = acc[t][0] + bo2.x + hAr.x;
        float a1 = acc[t][1] + bo2.y + hAr.y;
        float b0 = acc[t][2] + bo2.x + hBr.x;
        float b1 = acc[t][3] + bo2.y + hBr.y;
        vA[t*2]=a0; vA[t*2+1]=a1; vB[t*2]=b0; vB[t*2+1]=b1;
        sumA += a0+a1; sqA += a0*a0+a1*a1;
        sumB += b0+b1; sqB += b0*b0+b1*b1;
    }
#pragma unroll
    for (int o = 1; o < 4; o <<= 1) {
        sumA += __shfl_xor_sync(0xffffffffu, sumA, o);
        sqA  += __shfl_xor_sync(0xffffffffu, sqA,  o);
        sumB += __shfl_xor_sync(0xffffffffu, sumB, o);
        sqB  += __shfl_xor_sync(0xffffffffu, sqB,  o);
    }
    float mA = sumA*(1.f/64.f), vrA = sqA*(1.f/64.f) - mA*mA;
    float mB = sumB*(1.f/64.f), vrB = sqB*(1.f/64.f) - mB*mB;
    float rsA = rsqrtf(vrA + 1e-5f), rsB = rsqrtf(vrB + 1e-5f);
#pragma unroll
    for (int t = 0; t < 8; t++) {
        float2 gg = *(const float2*)(g2 + l*D + t*8 + tig*2);
        float2 bb = *(const float2*)(b2 + l*D + t*8 + tig*2);
        *(float2*)(g_h + (size_t)rA*D + t*8 + tig*2) =
            make_float2((vA[t*2]-mA)*rsA*gg.x + bb.x, (vA[t*2+1]-mA)*rsA*gg.y + bb.y);
        *(float2*)(g_h + (size_t)rB*D + t*8 + tig*2) =
            make_float2((vB[t*2]-mB)*rsB*gg.x + bb.x, (vB[t*2+1]-mB)*rsB*gg.y + bb.y);
    }
}

// ---------------- 6) pool + MLP + quantum circuit + <Z> + entropy ----------------
#define BARS128() asm volatile("bar.sync 1, 128;" ::: "memory")

__global__ void k_pool_quantum(const float* __restrict__ Wp1, const float* __restrict__ bp1,
                               const float* __restrict__ Wp2, const float* __restrict__ bp2,
                               const float* __restrict__ qw, float* __restrict__ out) {
    __shared__ float sp2[256];
    __shared__ float sp[64];
    __shared__ float sh[32];
    __shared__ float sang[8];
    __shared__ float2 st[256];
    __shared__ float2 rho[256];
    __shared__ float  sred[256];
    __shared__ float  jc[8], js[8], jpx[8], jpy[8];
    int b = blockIdx.x, tid = threadIdx.x;

    {
        int col = tid & 63, ch = tid >> 6;
        const float* hb = g_h + (size_t)b*S*D + (size_t)ch*256*D;
        float sum = 0.f;
#pragma unroll 8
        for (int s = 0; s < 256; s++) sum += hb[s*D + col];
        sp2[tid] = sum;
    }
    __syncthreads();
    if (tid < 64)
        sp[tid] = (sp2[tid] + sp2[tid+64] + sp2[tid+128] + sp2[tid+192]) * (1.0f/(float)S);
    __syncthreads();
    if (tid < 32) {
        float a = bp1[tid];
#pragma unroll
        for (int i = 0; i < 64; i++) a += sp[i] * Wp1[i*32 + tid];
        sh[tid] = fmaxf(a, 0.f);
    }
    __syncthreads();
    if (tid < 8) {
        float a = bp2[tid];
#pragma unroll
        for (int i = 0; i < 32; i++) a += sh[i] * Wp2[i*8 + tid];
        sang[tid] = tanhf(a) * 3.14159265358979f;
    }

    st[tid] = make_float2(tid == 0 ? 1.f : 0.f, 0.f);
    __syncthreads();

    for (int l = 0; l < QL; l++) {
        for (int w = 0; w < NQ; w++) {
            int mask = 1 << (7 - w);
            float c = cosf(0.5f * sang[w]);
            float s = sinf(0.5f * sang[w]);
            if (!(tid & mask)) {
                float2 v0 = st[tid], v1 = st[tid | mask];
                st[tid]        = make_float2(c*v0.x + s*v1.y,  c*v0.y - s*v1.x);
                st[tid | mask] = make_float2(s*v0.y + c*v1.x, -s*v0.x + c*v1.y);
            }
            __syncthreads();
        }
        for (int w = 0; w < NQ; w++) {
            int mask = 1 << (7 - w);
            float phi = qw[(l*NQ + w)*3 + 0];
            float th  = qw[(l*NQ + w)*3 + 1];
            float om  = qw[(l*NQ + w)*3 + 2];
            float ct = cosf(0.5f*th), stt = sinf(0.5f*th);
            float aa = 0.5f*(phi + om), bb = 0.5f*(phi - om);
            float ca = cosf(aa), sa = sinf(aa), cb = cosf(bb), sb = sinf(bb);
            float2 U00 = make_float2( ct*ca, -ct*sa);
            float2 U01 = make_float2(-stt*cb, -stt*sb);
            float2 U10 = make_float2( stt*cb, -stt*sb);
            float2 U11 = make_float2( ct*ca,  ct*sa);
            if (!(tid & mask)) {
                float2 v0 = st[tid], v1 = st[tid | mask];
                st[tid]        = cadd(cmul(U00, v0), cmul(U01, v1));
                st[tid | mask] = cadd(cmul(U10, v0), cmul(U11, v1));
            }
            __syncthreads();
        }
        for (int w = 0; w < NQ; w++) {
            int mc = 1 << (7 - w);
            int mt = 1 << (7 - ((w + 1) & 7));
            if ((tid & mc) && !(tid & mt)) {
                float2 t0 = st[tid];
                st[tid] = st[tid | mt];
                st[tid | mt] = t0;
            }
            __syncthreads();
        }
    }

    float p = st[tid].x*st[tid].x + st[tid].y*st[tid].y;
    for (int w = 0; w < 3; w++) {
        sred[tid] = (tid & (1 << (7 - w))) ? -p : p;
        __syncthreads();
        for (int off = 128; off > 0; off >>= 1) {
            if (tid < off) sred[tid] += sred[tid + off];
            __syncthreads();
        }
        if (tid == 0) out[b*3 + w] = sred[0];
        __syncthreads();
    }

    {
        int r = tid >> 4, c = tid & 15;
        float2 acc = make_float2(0.f, 0.f);
#pragma unroll
        for (int k = 0; k < 16; k++) {
            float2 mr = st[r*16 + k], mcv = st[c*16 + k];
            acc.x += mr.x*mcv.x + mr.y*mcv.y;
            acc.y += mr.y*mcv.x - mr.x*mcv.y;
        }
        rho[tid] = acc;
    }
    __syncthreads();

    if (tid < 128) {
        int g = tid >> 4, k = tid & 15;
        for (int sweep = 0; sweep < 6; sweep++) {
            for (int rnd = 0; rnd < 15; rnd++) {
                int pa, qa_;
                if (g == 0) { pa = 15; qa_ = rnd; }
                else {
                    pa  = (rnd + g) % 15;
                    qa_ = (rnd + 15 - g) % 15;
                }
                int pp = min(pa, qa_), qq = max(pa, qa_);
                if (k == 0) {
                    float2 apq = rho[pp*16 + qq];
                    float b2v = apq.x*apq.x + apq.y*apq.y;
                    if (b2v > 1e-26f) {
                        float app = rho[pp*16 + pp].x;
                        float aqq = rho[qq*16 + qq].x;
                        float bn  = sqrtf(b2v);
                        float tau = (aqq - app) / (2.f * bn);
                        float rt  = sqrtf(1.f + tau*tau);
                        float t   = (tau >= 0.f) ? 1.f/(tau + rt) : -1.f/(-tau + rt);
                        float cc  = rsqrtf(1.f + t*t);
                        jc[g] = cc; js[g] = t*cc;
                        jpx[g] = apq.x/bn; jpy[g] = apq.y/bn;
                    } else {
                        jc[g] = 1.f; js[g] = 0.f; jpx[g] = 1.f; jpy[g] = 0.f;
                    }
                }
                BARS128();
                float cc = jc[g], ss = js[g];
                float2 ph = make_float2(jpx[g], jpy[g]);
                {
                    float2 rp = rho[pp*16 + k], rq = rho[qq*16 + k];
                    float2 prq  = cmul(ph, rq);
                    float2 cprp = cmulcj(ph, rp);
                    rho[pp*16 + k] = make_float2(cc*rp.x - ss*prq.x,  cc*rp.y - ss*prq.y);
                    rho[qq*16 + k] = make_float2(ss*cprp.x + cc*rq.x, ss*cprp.y + cc*rq.y);
                }
                BARS128();
                {
                    float2 cp = rho[k*16 + pp], cq = rho[k*16 + qq];
                    float2 ccq = cmulcj(ph, cq);
                    float2 pcp = cmul(ph, cp);
                    rho[k*16 + pp] = make_float2(cc*cp.x - ss*ccq.x,  cc*cp.y - ss*ccq.y);
                    rho[k*16 + qq] = make_float2(ss*pcp.x + cc*cq.x, ss*pcp.y + cc*cq.y);
                }
                BARS128();
            }
        }
        if (tid == 0) {
            float ent = 0.f;
#pragma unroll
            for (int kk = 0; kk < 16; kk++) {
                float ev = rho[kk*16 + kk].x;
                ev = fminf(fmaxf(ev, 1e-10f), 1.f);
                ent -= ev * logf(ev);
            }
            out[48 + b] = ent;
        }
    }
}

// ---------------- launch ----------------
extern "C" void kernel_launch(void* const* d_in, const int* in_sizes, int n_in,
                              void* d_out, int out_size) {
    const float* x    = (const float*)d_in[0];
    const float* Wemb = (const float*)d_in[1];
    const float* bemb = (const float*)d_in[2];
    const float* Wq   = (const float*)d_in[3];
    const float* bq   = (const float*)d_in[4];
    const float* Wk   = (const float*)d_in[5];
    const float* bk   = (const float*)d_in[6];
    const float* Wv   = (const float*)d_in[7];
    const float* bv   = (const float*)d_in[8];
    const float* Wo   = (const float*)d_in[9];
    const float* bo   = (const float*)d_in[10];
    const float* ln1g = (const float*)d_in[11];
    const float* ln1b = (const float*)d_in[12];
    const float* ln2g = (const float*)d_in[13];
    const float* ln2b = (const float*)d_in[14];
    const float* Wf1  = (const float*)d_in[15];
    const float* bf1  = (const float*)d_in[16];
    const float* Wf2  = (const float*)d_in[17];
    const float* bf2  = (const float*)d_in[18];
    const float* Wp1  = (const float*)d_in[19];
    const float* bp1  = (const float*)d_in[20];
    const float* Wp2  = (const float*)d_in[21];
    const float* bp2  = (const float*)d_in[22];
    const float* qw   = (const float*)d_in[23];
    float* out = (float*)d_out;

    k_pe<<<128, 256>>>();
    k_embed<<<(BS*D)/256, 256>>>(x, Wemb, bemb);
    for (int l = 0; l < NL; l++) {
        k_qkv_mma<<<256, 128>>>(Wq, bq, Wk, bk, Wv, bv, l);
        dim3 ag(16, B*H);
        k_attn_mma<<<ag, 128>>>();
        k_oproj_mma<<<256, 128>>>(Wo, bo, ln1g, ln1b, l);
        k_ffn_mma<<<256, 128>>>(Wf1, bf1, Wf2, bf2, ln2g, ln2b, l);
    }
    k_pool_quantum<<<B, 256>>>(Wp1, bp1, Wp2, bp2, qw, out);
}

// round 8
// speedup vs baseline: 1.0448x; 1.0448x over previous
#include <cuda_runtime.h>
#include <cuda_fp16.h>
#include <math.h>

#define B   16
#define S   1024
#define NF  5
#define D   64
#define H   8
#define HD  8
#define NL  2
#define FF  128
#define NQ  8
#define QL  3
#define BS  (B*S)
#define CK2  512          // keys per chunk (2 chunks)
#define VPAD2 520         // padded V row (halves): 260 uints, mod 32 = 4

typedef unsigned long long ull;
typedef unsigned int uint;

// ---------------- device scratch ----------------
__device__ float g_h  [BS*D];
__device__ float g_q  [BS*D];
__device__ float g_k  [BS*D];
__device__ float g_v  [BS*D];
__device__ float g_pe [S*D];
__device__ float g_part[(size_t)2*128*S*12];   // 12.6 MB partials

// ---------------- mma / f16 helpers ----------------
__device__ __forceinline__ void mma16n8k8_f16(uint& d0, uint& d1, uint a0, uint a1, uint b0) {
    asm volatile("mma.sync.aligned.m16n8k8.row.col.f16.f16.f16.f16 "
        "{%0,%1}, {%2,%3}, {%4}, {%5,%6};"
        : "=r"(d0), "=r"(d1)
        : "r"(a0), "r"(a1), "r"(b0), "r"(0u), "r"(0u));
}
__device__ __forceinline__ void mma16n8k16(float* d,
                                           uint a0, uint a1, uint a2, uint a3,
                                           uint b0, uint b1) {
    asm volatile("mma.sync.aligned.m16n8k16.row.col.f32.f16.f16.f32 "
        "{%0,%1,%2,%3}, {%4,%5,%6,%7}, {%8,%9}, {%0,%1,%2,%3};"
        : "+f"(d[0]), "+f"(d[1]), "+f"(d[2]), "+f"(d[3])
        : "r"(a0), "r"(a1), "r"(a2), "r"(a3), "r"(b0), "r"(b1));
}
__device__ __forceinline__ uint cvt_f16x2(float hi, float lo) {
    uint r; asm("cvt.rn.f16x2.f32 %0, %1, %2;" : "=r"(r) : "f"(hi), "f"(lo)); return r;
}
__device__ __forceinline__ uint hex2x2(uint x) {
    uint r; asm("ex2.approx.f16x2 %0, %1;" : "=r"(r) : "r"(x)); return r;
}

// ---------------- complex helpers ----------------
__device__ __forceinline__ float2 cmul(float2 a, float2 b) {
    return make_float2(a.x*b.x - a.y*b.y, a.x*b.y + a.y*b.x);
}
__device__ __forceinline__ float2 cmulcj(float2 a, float2 b) {
    return make_float2(a.x*b.x + a.y*b.y, a.x*b.y - a.y*b.x);
}
__device__ __forceinline__ float2 cadd(float2 a, float2 b) {
    return make_float2(a.x + b.x, a.y + b.y);
}

// ---------------- 0) positional-encoding table ----------------
__global__ void k_pe() {
    int idx = blockIdx.x * blockDim.x + threadIdx.x;   // < 32768
    int s = idx >> 5, p = idx & 31;
    float div = __expf(-0.14391156831212787f * (float)(2*p));
    float sn, cs;
    sincosf((float)s * div, &sn, &cs);
    g_pe[s*64 + 2*p]     = sn;
    g_pe[s*64 + 2*p + 1] = cs;
}

// ---------------- 1) embedding ----------------
__global__ void k_embed(const float* __restrict__ x,
                        const float* __restrict__ Wemb,
                        const float* __restrict__ bemb) {
    int idx = blockIdx.x * blockDim.x + threadIdx.x;   // < BS*D
    int c   = idx & (D-1);
    int row = idx >> 6;
    int s   = row & (S-1);
    float acc = bemb[c] + g_pe[s*64 + c];
    const float* xr = x + row * NF;
#pragma unroll
    for (int f = 0; f < NF; f++) acc += xr[f] * Wemb[f*D + c];
    g_h[idx] = acc;
}

// ======== MMA GEMM common fragment loaders ========
__device__ __forceinline__ void load_afrag64(uint (&a)[4][4], const uint* sA, int rbase, int gid, int tig) {
    const uint* r0 = sA + (rbase + gid)*36;
    const uint* r1 = sA + (rbase + gid + 8)*36;
#pragma unroll
    for (int kk = 0; kk < 4; kk++) {
        a[kk][0] = r0[kk*8 + tig];
        a[kk][1] = r1[kk*8 + tig];
        a[kk][2] = r0[kk*8 + 4 + tig];
        a[kk][3] = r1[kk*8 + 4 + tig];
    }
}

// ---------------- 2) QKV projection via mma (64 rows/block, grid.y selects matrix) --------
__global__ void __launch_bounds__(128) k_qkv_mma(
        const float* __restrict__ Wq, const float* __restrict__ bq,
        const float* __restrict__ Wk, const float* __restrict__ bk,
        const float* __restrict__ Wv, const float* __restrict__ bv, int l) {
    __shared__ uint sA [64*36];
    __shared__ uint sWp[32*68];
    int tid = threadIdx.x;
    int row0 = blockIdx.x * 64;
    int m = blockIdx.y;
    const float* W    = (m == 0) ? (Wq + l*4096) : (m == 1) ? (Wk + l*4096) : (Wv + l*4096);
    const float* bias = (m == 0) ? (bq + l*D)    : (m == 1) ? (bk + l*D)    : (bv + l*D);
    float* out        = (m == 0) ? g_q : (m == 1) ? g_k : g_v;

    for (int idx = tid; idx < 2048; idx += 128) {
        int r = idx >> 5, c2 = idx & 31;
        float2 v = *(const float2*)(g_h + (size_t)(row0 + r)*D + c2*2);
        sA[r*36 + c2] = cvt_f16x2(v.y, v.x);
    }
    for (int idx = tid; idx < 2048; idx += 128) {
        int ip = idx >> 6, n = idx & 63;
        sWp[ip*68 + n] = cvt_f16x2(W[(2*ip+1)*64 + n], W[(2*ip)*64 + n]);
    }
    __syncthreads();

    int warp = tid >> 5, lane = tid & 31;
    int gid = lane >> 2, tig = lane & 3;
    uint a[4][4];
    load_afrag64(a, sA, warp*16, gid, tig);

#pragma unroll
    for (int t = 0; t < 8; t++) {
        float acc[4] = {0,0,0,0};
#pragma unroll
        for (int kk = 0; kk < 4; kk++) {
            uint b0 = sWp[(kk*8 + tig)*68 + t*8 + gid];
            uint b1 = sWp[(kk*8 + 4 + tig)*68 + t*8 + gid];
            mma16n8k16(acc, a[kk][0], a[kk][1], a[kk][2], a[kk][3], b0, b1);
        }
        float2 bv2 = *(const float2*)(bias + t*8 + tig*2);
        int r = row0 + warp*16 + gid;
        *(float2*)(out + (size_t)r*D + t*8 + tig*2) =
            make_float2(acc[0] + bv2.x, acc[1] + bv2.y);
        *(float2*)(out + (size_t)(r + 8)*D + t*8 + tig*2) =
            make_float2(acc[2] + bv2.x, acc[3] + bv2.y);
    }
}

// ---------------- 3) split-K attention via mma: f16-accum QK, k16 PV ----------------
// grid: x = qtile(8) * chunk(2) = 16, y = 128 (bh). 2048 CTAs, 16.6KB smem.
__global__ void __launch_bounds__(128) k_attn_mma() {
    __shared__ __half sK [CK2*8];        // 8 KB
    __shared__ __half sVT[8*VPAD2];      // 8.3 KB
    int tid = threadIdx.x;
    int bh  = blockIdx.y;
    int b   = bh >> 3, hh = bh & 7;
    int qt  = blockIdx.x >> 1;
    int ck  = blockIdx.x & 1;
    int k0  = ck * CK2;
    const float* kbase = g_k + (size_t)(b*S + k0)*D + hh*HD;
    const float* vbase = g_v + (size_t)(b*S + k0)*D + hh*HD;
    const float pre = 0.35355339059327373f * 1.4426950408889634f;  // scale*log2(e)
    for (int i = tid; i < CK2*8; i += 128) {
        int key = i >> 3, d = i & 7;
        sK[i]             = __float2half(kbase[key*D + d] * pre);  // pre-scaled K
        sVT[d*VPAD2 + key] = __float2half(vbase[key*D + d]);
    }
    __syncthreads();

    int warp = tid >> 5, lane = tid & 31;
    int gid  = lane >> 2, tig = lane & 3;
    int q0   = qt * 128 + warp * 32;

    uint qa[2][2];
#pragma unroll
    for (int t2 = 0; t2 < 2; t2++) {
#pragma unroll
        for (int hf = 0; hf < 2; hf++) {
            int qrow = q0 + t2*16 + gid + hf*8;
            float2 qv = *(const float2*)(g_q + (size_t)(b*S + qrow)*D + hh*HD + tig*2);
            qa[t2][hf] = cvt_f16x2(qv.y, qv.x);
        }
    }

    float acc0[4] = {0,0,0,0}, acc1[4] = {0,0,0,0};
    float lac0[4] = {0,0,0,0}, lac1[4] = {0,0,0,0};
    const uint ones2 = 0x3C003C00u;
    const __half* kptr = sK  + gid*8 + tig*2;
    const __half* vptr = sVT + gid*VPAD2 + tig*2;

#pragma unroll 2
    for (int j0 = 0; j0 < CK2; j0 += 16) {
        uint kb0 = *(const uint*)(kptr + j0*8);
        uint kb1 = *(const uint*)(kptr + j0*8 + 64);
        uint vb0 = *(const uint*)(vptr + j0);
        uint vb1 = *(const uint*)(vptr + j0 + 8);
        // tile 0 (q rows q0..q0+15)
        {
            uint s01a, s23a, s01b, s23b;
            mma16n8k8_f16(s01a, s23a, qa[0][0], qa[0][1], kb0);
            mma16n8k8_f16(s01b, s23b, qa[0][0], qa[0][1], kb1);
            uint p0 = hex2x2(s01a), p1 = hex2x2(s23a);
            uint p2 = hex2x2(s01b), p3 = hex2x2(s23b);
            mma16n8k16(acc0, p0, p1, p2, p3, vb0, vb1);
            mma16n8k16(lac0, p0, p1, p2, p3, ones2, ones2);
        }
        // tile 1 (q rows q0+16..q0+31)
        {
            uint s01a, s23a, s01b, s23b;
            mma16n8k8_f16(s01a, s23a, qa[1][0], qa[1][1], kb0);
            mma16n8k8_f16(s01b, s23b, qa[1][0], qa[1][1], kb1);
            uint p0 = hex2x2(s01a), p1 = hex2x2(s23a);
            uint p2 = hex2x2(s01b), p3 = hex2x2(s23b);
            mma16n8k16(acc1, p0, p1, p2, p3, vb0, vb1);
            mma16n8k16(lac1, p0, p1, p2, p3, ones2, ones2);
        }
    }

    // store unnormalized partials: [ck][bh][q][12] (8 acc, lsum at +8)
    size_t base = ((size_t)ck*128 + bh)*S;
    {
        float* pp = g_part + (base + q0 + gid)*12;
        *(float2*)(pp + tig*2) = make_float2(acc0[0], acc0[1]);
        if (tig == 0) pp[8] = lac0[0];
        pp = g_part + (base + q0 + gid + 8)*12;
        *(float2*)(pp + tig*2) = make_float2(acc0[2], acc0[3]);
        if (tig == 0) pp[8] = lac0[2];
        pp = g_part + (base + q0 + 16 + gid)*12;
        *(float2*)(pp + tig*2) = make_float2(acc1[0], acc1[1]);
        if (tig == 0) pp[8] = lac1[0];
        pp = g_part + (base + q0 + 24 + gid)*12;
        *(float2*)(pp + tig*2) = make_float2(acc1[2], acc1[3]);
        if (tig == 0) pp[8] = lac1[2];
    }
}

// ---------------- 4) combine + oproj + residual + LN1 via mma ----------------
__global__ void __launch_bounds__(128) k_oproj_mma(
        const float* __restrict__ Wo, const float* __restrict__ bo,
        const float* __restrict__ g1, const float* __restrict__ b1, int l) {
    __shared__ uint sA [64*36];
    __shared__ uint sWp[32*68];
    int tid = threadIdx.x;
    int row0 = blockIdx.x * 64;
    // combine attention partials -> normalized attention output (fp16 A)
    for (int idx = tid; idx < 2048; idx += 128) {
        int r = idx >> 5, c2 = idx & 31;
        int grow = row0 + r;
        int q  = grow & (S-1);
        int bb = grow >> 10;
        int hh = c2 >> 2;
        int bh = bb*8 + hh;
        int off = (c2 & 3)*2;
        const float* p0 = g_part + ((size_t)(0*128 + bh)*S + q)*12;
        const float* p1 = g_part + ((size_t)(1*128 + bh)*S + q)*12;
        float inv = 1.0f / (p0[8] + p1[8]);
        float a0 = (p0[off]   + p1[off])   * inv;
        float a1 = (p0[off+1] + p1[off+1]) * inv;
        sA[r*36 + c2] = cvt_f16x2(a1, a0);
    }
    const float* W = Wo + l*4096;
    for (int idx = tid; idx < 2048; idx += 128) {
        int ip = idx >> 6, n = idx & 63;
        sWp[ip*68 + n] = cvt_f16x2(W[(2*ip+1)*64 + n], W[(2*ip)*64 + n]);
    }
    __syncthreads();

    int warp = tid >> 5, lane = tid & 31;
    int gid = lane >> 2, tig = lane & 3;
    uint a[4][4];
    load_afrag64(a, sA, warp*16, gid, tig);

    float acc[8][4];
#pragma unroll
    for (int t = 0; t < 8; t++) {
        acc[t][0]=0; acc[t][1]=0; acc[t][2]=0; acc[t][3]=0;
#pragma unroll
        for (int kk = 0; kk < 4; kk++) {
            uint b0 = sWp[(kk*8 + tig)*68 + t*8 + gid];
            uint b1 = sWp[(kk*8 + 4 + tig)*68 + t*8 + gid];
            mma16n8k16(acc[t], a[kk][0], a[kk][1], a[kk][2], a[kk][3], b0, b1);
        }
    }
    int rA = row0 + warp*16 + gid;
    int rB = rA + 8;
    float vA[16], vB[16];
    float sumA=0, sqA=0, sumB=0, sqB=0;
#pragma unroll
    for (int t = 0; t < 8; t++) {
        float2 bo2 = *(const float2*)(bo + l*D + t*8 + tig*2);
        float2 hA = *(const float2*)(g_h + (size_t)rA*D + t*8 + tig*2);
        float2 hB = *(const float2*)(g_h + (size_t)rB*D + t*8 + tig*2);
        float a0 = acc[t][0] + bo2.x + hA.x;
        float a1 = acc[t][1] + bo2.y + hA.y;
        float b0 = acc[t][2] + bo2.x + hB.x;
        float b1 = acc[t][3] + bo2.y + hB.y;
        vA[t*2]=a0; vA[t*2+1]=a1; vB[t*2]=b0; vB[t*2+1]=b1;
        sumA += a0+a1; sqA += a0*a0+a1*a1;
        sumB += b0+b1; sqB += b0*b0+b1*b1;
    }
#pragma unroll
    for (int o = 1; o < 4; o <<= 1) {
        sumA += __shfl_xor_sync(0xffffffffu, sumA, o);
        sqA  += __shfl_xor_sync(0xffffffffu, sqA,  o);
        sumB += __shfl_xor_sync(0xffffffffu, sumB, o);
        sqB  += __shfl_xor_sync(0xffffffffu, sqB,  o);
    }
    float mA = sumA*(1.f/64.f), vrA = sqA*(1.f/64.f) - mA*mA;
    float mB = sumB*(1.f/64.f), vrB = sqB*(1.f/64.f) - mB*mB;
    float rsA = rsqrtf(vrA + 1e-5f), rsB = rsqrtf(vrB + 1e-5f);
#pragma unroll
    for (int t = 0; t < 8; t++) {
        float2 gg = *(const float2*)(g1 + l*D + t*8 + tig*2);
        float2 bb = *(const float2*)(b1 + l*D + t*8 + tig*2);
        *(float2*)(g_h + (size_t)rA*D + t*8 + tig*2) =
            make_float2((vA[t*2]-mA)*rsA*gg.x + bb.x, (vA[t*2+1]-mA)*rsA*gg.y + bb.y);
        *(float2*)(g_h + (size_t)rB*D + t*8 + tig*2) =
            make_float2((vB[t*2]-mB)*rsB*gg.x + bb.x, (vB[t*2+1]-mB)*rsB*gg.y + bb.y);
    }
}

// ---------------- 5) fused FFN via mma (64 rows/block) ----------------
__global__ void __launch_bounds__(128) k_ffn_mma(
        const float* __restrict__ Wf1, const float* __restrict__ bf1,
        const float* __restrict__ Wf2, const float* __restrict__ bf2,
        const float* __restrict__ g2, const float* __restrict__ b2, int l) {
    __shared__ uint sA  [64*36];
    __shared__ uint sW1p[32*132];
    __shared__ uint sW2p[64*68];
    int tid = threadIdx.x;
    int row0 = blockIdx.x * 64;
    for (int idx = tid; idx < 2048; idx += 128) {
        int r = idx >> 5, c2 = idx & 31;
        float2 v = *(const float2*)(g_h + (size_t)(row0 + r)*D + c2*2);
        sA[r*36 + c2] = cvt_f16x2(v.y, v.x);
    }
    const float* W1 = Wf1 + l*8192;
    const float* W2 = Wf2 + l*8192;
    for (int idx = tid; idx < 4096; idx += 128) {
        int ip = idx >> 7, n = idx & 127;
        sW1p[ip*132 + n] = cvt_f16x2(W1[(2*ip+1)*128 + n], W1[(2*ip)*128 + n]);
    }
    for (int idx = tid; idx < 4096; idx += 128) {
        int ip = idx >> 6, n = idx & 63;
        sW2p[ip*68 + n] = cvt_f16x2(W2[(2*ip+1)*64 + n], W2[(2*ip)*64 + n]);
    }
    __syncthreads();

    int warp = tid >> 5, lane = tid & 31;
    int gid = lane >> 2, tig = lane & 3;
    uint a[4][4];
    load_afrag64(a, sA, warp*16, gid, tig);

    uint hA[16][2];
#pragma unroll
    for (int t = 0; t < 16; t++) {
        float acc[4] = {0,0,0,0};
#pragma unroll
        for (int kk = 0; kk < 4; kk++) {
            uint b0 = sW1p[(kk*8 + tig)*132 + t*8 + gid];
            uint b1 = sW1p[(kk*8 + 4 + tig)*132 + t*8 + gid];
            mma16n8k16(acc, a[kk][0], a[kk][1], a[kk][2], a[kk][3], b0, b1);
        }
        float2 bf = *(const float2*)(bf1 + l*FF + t*8 + tig*2);
        float c0 = fmaxf(acc[0] + bf.x, 0.f);
        float c1 = fmaxf(acc[1] + bf.y, 0.f);
        float c2 = fmaxf(acc[2] + bf.x, 0.f);
        float c3 = fmaxf(acc[3] + bf.y, 0.f);
        hA[t][0] = cvt_f16x2(c1, c0);
        hA[t][1] = cvt_f16x2(c3, c2);
    }

    float acc[8][4];
#pragma unroll
    for (int t = 0; t < 8; t++) {
        acc[t][0]=0; acc[t][1]=0; acc[t][2]=0; acc[t][3]=0;
#pragma unroll
        for (int kk = 0; kk < 8; kk++) {
            uint b0 = sW2p[(kk*8 + tig)*68 + t*8 + gid];
            uint b1 = sW2p[(kk*8 + 4 + tig)*68 + t*8 + gid];
            mma16n8k16(acc[t], hA[2*kk][0], hA[2*kk][1], hA[2*kk+1][0], hA[2*kk+1][1], b0, b1);
        }
    }
    int rA = row0 + warp*16 + gid;
    int rB = rA + 8;
    float vA[16], vB[16];
    float sumA=0, sqA=0, sumB=0, sqB=0;
#pragma unroll
    for (int t = 0; t < 8; t++) {
        float2 bo2 = *(const float2*)(bf2 + l*D + t*8 + tig*2);
        float2 hAr = *(const float2*)(g_h + (size_t)rA*D + t*8 + tig*2);
        float2 hBr = *(const float2*)(g_h + (size_t)rB*D + t*8 + tig*2);
        float a0 = acc[t][0] + bo2.x + hAr.x;
        float a1 = acc[t][1] + bo2.y + hAr.y;
        float b0 = acc[t][2] + bo2.x + hBr.x;
        float b1 = acc[t][3] + bo2.y + hBr.y;
        vA[t*2]=a0; vA[t*2+1]=a1; vB[t*2]=b0; vB[t*2+1]=b1;
        sumA += a0+a1; sqA += a0*a0+a1*a1;
        sumB += b0+b1; sqB += b0*b0+b1*b1;
    }
#pragma unroll
    for (int o = 1; o < 4; o <<= 1) {
        sumA += __shfl_xor_sync(0xffffffffu, sumA, o);
        sqA  += __shfl_xor_sync(0xffffffffu, sqA,  o);
        sumB += __shfl_xor_sync(0xffffffffu, sumB, o);
        sqB  += __shfl_xor_sync(0xffffffffu, sqB,  o);
    }
    float mA = sumA*(1.f/64.f), vrA = sqA*(1.f/64.f) - mA*mA;
    float mB = sumB*(1.f/64.f), vrB = sqB*(1.f/64.f) - mB*mB;
    float rsA = rsqrtf(vrA + 1e-5f), rsB = rsqrtf(vrB + 1e-5f);
#pragma unroll
    for (int t = 0; t < 8; t++) {
        float2 gg = *(const float2*)(g2 + l*D + t*8 + tig*2);
        float2 bb = *(const float2*)(b2 + l*D + t*8 + tig*2);
        *(float2*)(g_h + (size_t)rA*D + t*8 + tig*2) =
            make_float2((vA[t*2]-mA)*rsA*gg.x + bb.x, (vA[t*2+1]-mA)*rsA*gg.y + bb.y);
        *(float2*)(g_h + (size_t)rB*D + t*8 + tig*2) =
            make_float2((vB[t*2]-mB)*rsB*gg.x + bb.x, (vB[t*2+1]-mB)*rsB*gg.y + bb.y);
    }
}

// ---------------- 6) pool + MLP + quantum circuit + <Z> + entropy ----------------
#define BARS128() asm volatile("bar.sync 1, 128;" ::: "memory")

__global__ void k_pool_quantum(const float* __restrict__ Wp1, const float* __restrict__ bp1,
                               const float* __restrict__ Wp2, const float* __restrict__ bp2,
                               const float* __restrict__ qw, float* __restrict__ out) {
    __shared__ float sp2[256];
    __shared__ float sp[64];
    __shared__ float sh[32];
    __shared__ float sang[8];
    __shared__ float2 st[256];
    __shared__ float2 rho[256];
    __shared__ float  sred[256];
    __shared__ float  jc[8], js[8], jpx[8], jpy[8];
    int b = blockIdx.x, tid = threadIdx.x;

    {
        int col = tid & 63, ch = tid >> 6;
        const float* hb = g_h + (size_t)b*S*D + (size_t)ch*256*D;
        float sum = 0.f;
#pragma unroll 8
        for (int s = 0; s < 256; s++) sum += hb[s*D + col];
        sp2[tid] = sum;
    }
    __syncthreads();
    if (tid < 64)
        sp[tid] = (sp2[tid] + sp2[tid+64] + sp2[tid+128] + sp2[tid+192]) * (1.0f/(float)S);
    __syncthreads();
    if (tid < 32) {
        float a = bp1[tid];
#pragma unroll
        for (int i = 0; i < 64; i++) a += sp[i] * Wp1[i*32 + tid];
        sh[tid] = fmaxf(a, 0.f);
    }
    __syncthreads();
    if (tid < 8) {
        float a = bp2[tid];
#pragma unroll
        for (int i = 0; i < 32; i++) a += sh[i] * Wp2[i*8 + tid];
        sang[tid] = tanhf(a) * 3.14159265358979f;
    }

    st[tid] = make_float2(tid == 0 ? 1.f : 0.f, 0.f);
    __syncthreads();

    for (int l = 0; l < QL; l++) {
        for (int w = 0; w < NQ; w++) {
            int mask = 1 << (7 - w);
            float c = cosf(0.5f * sang[w]);
            float s = sinf(0.5f * sang[w]);
            if (!(tid & mask)) {
                float2 v0 = st[tid], v1 = st[tid | mask];
                st[tid]        = make_float2(c*v0.x + s*v1.y,  c*v0.y - s*v1.x);
                st[tid | mask] = make_float2(s*v0.y + c*v1.x, -s*v0.x + c*v1.y);
            }
            __syncthreads();
        }
        for (int w = 0; w < NQ; w++) {
            int mask = 1 << (7 - w);
            float phi = qw[(l*NQ + w)*3 + 0];
            float th  = qw[(l*NQ + w)*3 + 1];
            float om  = qw[(l*NQ + w)*3 + 2];
            float ct = cosf(0.5f*th), stt = sinf(0.5f*th);
            float aa = 0.5f*(phi + om), bb = 0.5f*(phi - om);
            float ca = cosf(aa), sa = sinf(aa), cb = cosf(bb), sb = sinf(bb);
            float2 U00 = make_float2( ct*ca, -ct*sa);
            float2 U01 = make_float2(-stt*cb, -stt*sb);
            float2 U10 = make_float2( stt*cb, -stt*sb);
            float2 U11 = make_float2( ct*ca,  ct*sa);
            if (!(tid & mask)) {
                float2 v0 = st[tid], v1 = st[tid | mask];
                st[tid]        = cadd(cmul(U00, v0), cmul(U01, v1));
                st[tid | mask] = cadd(cmul(U10, v0), cmul(U11, v1));
            }
            __syncthreads();
        }
        for (int w = 0; w < NQ; w++) {
            int mc = 1 << (7 - w);
            int mt = 1 << (7 - ((w + 1) & 7));
            if ((tid & mc) && !(tid & mt)) {
                float2 t0 = st[tid];
                st[tid] = st[tid | mt];
                st[tid | mt] = t0;
            }
            __syncthreads();
        }
    }

    float p = st[tid].x*st[tid].x + st[tid].y*st[tid].y;
    for (int w = 0; w < 3; w++) {
        sred[tid] = (tid & (1 << (7 - w))) ? -p : p;
        __syncthreads();
        for (int off = 128; off > 0; off >>= 1) {
            if (tid < off) sred[tid] += sred[tid + off];
            __syncthreads();
        }
        if (tid == 0) out[b*3 + w] = sred[0];
        __syncthreads();
    }

    {
        int r = tid >> 4, c = tid & 15;
        float2 acc = make_float2(0.f, 0.f);
#pragma unroll
        for (int k = 0; k < 16; k++) {
            float2 mr = st[r*16 + k], mcv = st[c*16 + k];
            acc.x += mr.x*mcv.x + mr.y*mcv.y;
            acc.y += mr.y*mcv.x - mr.x*mcv.y;
        }
        rho[tid] = acc;
    }
    __syncthreads();

    if (tid < 128) {
        int g = tid >> 4, k = tid & 15;
        for (int sweep = 0; sweep < 6; sweep++) {
            for (int rnd = 0; rnd < 15; rnd++) {
                int pa, qa_;
                if (g == 0) { pa = 15; qa_ = rnd; }
                else {
                    pa  = (rnd + g) % 15;
                    qa_ = (rnd + 15 - g) % 15;
                }
                int pp = min(pa, qa_), qq = max(pa, qa_);
                if (k == 0) {
                    float2 apq = rho[pp*16 + qq];
                    float b2v = apq.x*apq.x + apq.y*apq.y;
                    if (b2v > 1e-26f) {
                        float app = rho[pp*16 + pp].x;
                        float aqq = rho[qq*16 + qq].x;
                        float bn  = sqrtf(b2v);
                        float tau = (aqq - app) / (2.f * bn);
                        float rt  = sqrtf(1.f + tau*tau);
                        float t   = (tau >= 0.f) ? 1.f/(tau + rt) : -1.f/(-tau + rt);
                        float cc  = rsqrtf(1.f + t*t);
                        jc[g] = cc; js[g] = t*cc;
                        jpx[g] = apq.x/bn; jpy[g] = apq.y/bn;
                    } else {
                        jc[g] = 1.f; js[g] = 0.f; jpx[g] = 1.f; jpy[g] = 0.f;
                    }
                }
                BARS128();
                float cc = jc[g], ss = js[g];
                float2 ph = make_float2(jpx[g], jpy[g]);
                {
                    float2 rp = rho[pp*16 + k], rq = rho[qq*16 + k];
                    float2 prq  = cmul(ph, rq);
                    float2 cprp = cmulcj(ph, rp);
                    rho[pp*16 + k] = make_float2(cc*rp.x - ss*prq.x,  cc*rp.y - ss*prq.y);
                    rho[qq*16 + k] = make_float2(ss*cprp.x + cc*rq.x, ss*cprp.y + cc*rq.y);
                }
                BARS128();
                {
                    float2 cp = rho[k*16 + pp], cq = rho[k*16 + qq];
                    float2 ccq = cmulcj(ph, cq);
                    float2 pcp = cmul(ph, cp);
                    rho[k*16 + pp] = make_float2(cc*cp.x - ss*ccq.x,  cc*cp.y - ss*ccq.y);
                    rho[k*16 + qq] = make_float2(ss*pcp.x + cc*cq.x, ss*pcp.y + cc*cq.y);
                }
                BARS128();
            }
        }
        if (tid == 0) {
            float ent = 0.f;
#pragma unroll
            for (int kk = 0; kk < 16; kk++) {
                float ev = rho[kk*16 + kk].x;
                ev = fminf(fmaxf(ev, 1e-10f), 1.f);
                ent -= ev * logf(ev);
            }
            out[48 + b] = ent;
        }
    }
}

// ---------------- launch ----------------
extern "C" void kernel_launch(void* const* d_in, const int* in_sizes, int n_in,
                              void* d_out, int out_size) {
    const float* x    = (const float*)d_in[0];
    const float* Wemb = (const float*)d_in[1];
    const float* bemb = (const float*)d_in[2];
    const float* Wq   = (const float*)d_in[3];
    const float* bq   = (const float*)d_in[4];
    const float* Wk   = (const float*)d_in[5];
    const float* bk   = (const float*)d_in[6];
    const float* Wv   = (const float*)d_in[7];
    const float* bv   = (const float*)d_in[8];
    const float* Wo   = (const float*)d_in[9];
    const float* bo   = (const float*)d_in[10];
    const float* ln1g = (const float*)d_in[11];
    const float* ln1b = (const float*)d_in[12];
    const float* ln2g = (const float*)d_in[13];
    const float* ln2b = (const float*)d_in[14];
    const float* Wf1  = (const float*)d_in[15];
    const float* bf1  = (const float*)d_in[16];
    const float* Wf2  = (const float*)d_in[17];
    const float* bf2  = (const float*)d_in[18];
    const float* Wp1  = (const float*)d_in[19];
    const float* bp1  = (const float*)d_in[20];
    const float* Wp2  = (const float*)d_in[21];
    const float* bp2  = (const float*)d_in[22];
    const float* qw   = (const float*)d_in[23];
    float* out = (float*)d_out;

    k_pe<<<128, 256>>>();
    k_embed<<<(BS*D)/256, 256>>>(x, Wemb, bemb);
    for (int l = 0; l < NL; l++) {
        dim3 qg(256, 3);
        k_qkv_mma<<<qg, 128>>>(Wq, bq, Wk, bk, Wv, bv, l);
        dim3 ag(16, B*H);
        k_attn_mma<<<ag, 128>>>();
        k_oproj_mma<<<256, 128>>>(Wo, bo, ln1g, ln1b, l);
        k_ffn_mma<<<256, 128>>>(Wf1, bf1, Wf2, bf2, ln2g, ln2b, l);
    }
    k_pool_quantum<<<B, 256>>>(Wp1, bp1, Wp2, bp2, qw, out);
}

// round 9
// speedup vs baseline: 1.1254x; 1.0772x over previous
#include <cuda_runtime.h>
#include <cuda_fp16.h>
#include <math.h>

#define B   16
#define S   1024
#define NF  5
#define D   64
#define H   8
#define HD  8
#define NL  2
#define FF  128
#define NQ  8
#define QL  3
#define BS  (B*S)
#define CK2  512          // keys per chunk (2 chunks)
#define VPAD2 520         // padded V row (halves)

typedef unsigned long long ull;
typedef unsigned int uint;

// ---------------- device scratch ----------------
__device__ float g_h  [BS*D];
__device__ float g_q  [BS*D];
__device__ float g_k  [BS*D];
__device__ float g_v  [BS*D];
__device__ float g_pe [S*D];
__device__ float g_part[(size_t)2*128*S*12];   // 12.6 MB partials

// ---------------- mma / f16 helpers ----------------
__device__ __forceinline__ void mma16n8k8_f16(uint& d0, uint& d1, uint a0, uint a1, uint b0) {
    asm volatile("mma.sync.aligned.m16n8k8.row.col.f16.f16.f16.f16 "
        "{%0,%1}, {%2,%3}, {%4}, {%5,%6};"
        : "=r"(d0), "=r"(d1)
        : "r"(a0), "r"(a1), "r"(b0), "r"(0u), "r"(0u));
}
__device__ __forceinline__ void mma16n8k16(float* d,
                                           uint a0, uint a1, uint a2, uint a3,
                                           uint b0, uint b1) {
    asm volatile("mma.sync.aligned.m16n8k16.row.col.f32.f16.f16.f32 "
        "{%0,%1,%2,%3}, {%4,%5,%6,%7}, {%8,%9}, {%0,%1,%2,%3};"
        : "+f"(d[0]), "+f"(d[1]), "+f"(d[2]), "+f"(d[3])
        : "r"(a0), "r"(a1), "r"(a2), "r"(a3), "r"(b0), "r"(b1));
}
__device__ __forceinline__ uint cvt_f16x2(float hi, float lo) {
    uint r; asm("cvt.rn.f16x2.f32 %0, %1, %2;" : "=r"(r) : "f"(hi), "f"(lo)); return r;
}
__device__ __forceinline__ uint hex2x2(uint x) {
    uint r; asm("ex2.approx.f16x2 %0, %1;" : "=r"(r) : "r"(x)); return r;
}

// ---------------- complex helpers ----------------
__device__ __forceinline__ float2 cmul(float2 a, float2 b) {
    return make_float2(a.x*b.x - a.y*b.y, a.x*b.y + a.y*b.x);
}
__device__ __forceinline__ float2 cmulcj(float2 a, float2 b) {
    return make_float2(a.x*b.x + a.y*b.y, a.x*b.y - a.y*b.x);
}
__device__ __forceinline__ float2 cadd(float2 a, float2 b) {
    return make_float2(a.x + b.x, a.y + b.y);
}

// ---------------- 0) positional-encoding table ----------------
__global__ void k_pe() {
    int idx = blockIdx.x * blockDim.x + threadIdx.x;   // < 32768
    int s = idx >> 5, p = idx & 31;
    float div = __expf(-0.14391156831212787f * (float)(2*p));
    float sn, cs;
    sincosf((float)s * div, &sn, &cs);
    g_pe[s*64 + 2*p]     = sn;
    g_pe[s*64 + 2*p + 1] = cs;
}

// ======== MMA GEMM common fragment loaders ========
__device__ __forceinline__ void load_afrag64(uint (&a)[4][4], const uint* sA, int rbase, int gid, int tig) {
    const uint* r0 = sA + (rbase + gid)*36;
    const uint* r1 = sA + (rbase + gid + 8)*36;
#pragma unroll
    for (int kk = 0; kk < 4; kk++) {
        a[kk][0] = r0[kk*8 + tig];
        a[kk][1] = r1[kk*8 + tig];
        a[kk][2] = r0[kk*8 + 4 + tig];
        a[kk][3] = r1[kk*8 + 4 + tig];
    }
}

// ---------------- 1) QKV projection via mma (64 rows/block, grid.y = matrix) ----------------
// l==0: computes the embedding inline (x @ Wemb + bemb + pe); m==0 writes g_h.
__global__ void __launch_bounds__(128) k_qkv_mma(
        const float* __restrict__ Wq, const float* __restrict__ bq,
        const float* __restrict__ Wk, const float* __restrict__ bk,
        const float* __restrict__ Wv, const float* __restrict__ bv,
        const float* __restrict__ x,  const float* __restrict__ Wemb,
        const float* __restrict__ bemb, int l) {
    __shared__ uint  sA [64*36];
    __shared__ uint  sWp[32*68];
    __shared__ float sX [64*NF];
    int tid = threadIdx.x;
    int row0 = blockIdx.x * 64;
    int m = blockIdx.y;
    const float* W    = (m == 0) ? (Wq + l*4096) : (m == 1) ? (Wk + l*4096) : (Wv + l*4096);
    const float* bias = (m == 0) ? (bq + l*D)    : (m == 1) ? (bk + l*D)    : (bv + l*D);
    float* out        = (m == 0) ? g_q : (m == 1) ? g_k : g_v;

    if (l == 0) {
        for (int idx = tid; idx < 64*NF; idx += 128)
            sX[idx] = x[(size_t)(row0 + idx/NF)*NF + idx%NF];
        __syncthreads();
        for (int idx = tid; idx < 2048; idx += 128) {
            int r = idx >> 5, c2 = idx & 31;
            int row = row0 + r;
            int s = row & (S-1);
            int c = c2*2;
            float v0 = bemb[c]   + g_pe[s*64 + c];
            float v1 = bemb[c+1] + g_pe[s*64 + c + 1];
            const float* xr = sX + r*NF;
#pragma unroll
            for (int f = 0; f < NF; f++) {
                v0 += xr[f] * Wemb[f*D + c];
                v1 += xr[f] * Wemb[f*D + c + 1];
            }
            sA[r*36 + c2] = cvt_f16x2(v1, v0);
            if (m == 0) *(float2*)(g_h + (size_t)row*D + c) = make_float2(v0, v1);
        }
    } else {
        for (int idx = tid; idx < 2048; idx += 128) {
            int r = idx >> 5, c2 = idx & 31;
            float2 v = *(const float2*)(g_h + (size_t)(row0 + r)*D + c2*2);
            sA[r*36 + c2] = cvt_f16x2(v.y, v.x);
        }
    }
    for (int idx = tid; idx < 2048; idx += 128) {
        int ip = idx >> 6, n = idx & 63;
        sWp[ip*68 + n] = cvt_f16x2(W[(2*ip+1)*64 + n], W[(2*ip)*64 + n]);
    }
    __syncthreads();

    int warp = tid >> 5, lane = tid & 31;
    int gid = lane >> 2, tig = lane & 3;
    uint a[4][4];
    load_afrag64(a, sA, warp*16, gid, tig);

#pragma unroll
    for (int t = 0; t < 8; t++) {
        float acc[4] = {0,0,0,0};
#pragma unroll
        for (int kk = 0; kk < 4; kk++) {
            uint b0 = sWp[(kk*8 + tig)*68 + t*8 + gid];
            uint b1 = sWp[(kk*8 + 4 + tig)*68 + t*8 + gid];
            mma16n8k16(acc, a[kk][0], a[kk][1], a[kk][2], a[kk][3], b0, b1);
        }
        float2 bv2 = *(const float2*)(bias + t*8 + tig*2);
        int r = row0 + warp*16 + gid;
        *(float2*)(out + (size_t)r*D + t*8 + tig*2) =
            make_float2(acc[0] + bv2.x, acc[1] + bv2.y);
        *(float2*)(out + (size_t)(r + 8)*D + t*8 + tig*2) =
            make_float2(acc[2] + bv2.x, acc[3] + bv2.y);
    }
}

// ---------------- 2) split-K attention via mma: f16-accum QK, k16 PV ----------------
__global__ void __launch_bounds__(128) k_attn_mma() {
    __shared__ __half sK [CK2*8];
    __shared__ __half sVT[8*VPAD2];
    int tid = threadIdx.x;
    int bh  = blockIdx.y;
    int b   = bh >> 3, hh = bh & 7;
    int qt  = blockIdx.x >> 1;
    int ck  = blockIdx.x & 1;
    int k0  = ck * CK2;
    const float* kbase = g_k + (size_t)(b*S + k0)*D + hh*HD;
    const float* vbase = g_v + (size_t)(b*S + k0)*D + hh*HD;
    const float pre = 0.35355339059327373f * 1.4426950408889634f;  // scale*log2(e)
    for (int i = tid; i < CK2*8; i += 128) {
        int key = i >> 3, d = i & 7;
        sK[i]             = __float2half(kbase[key*D + d] * pre);
        sVT[d*VPAD2 + key] = __float2half(vbase[key*D + d]);
    }
    __syncthreads();

    int warp = tid >> 5, lane = tid & 31;
    int gid  = lane >> 2, tig = lane & 3;
    int q0   = qt * 128 + warp * 32;

    uint qa[2][2];
#pragma unroll
    for (int t2 = 0; t2 < 2; t2++) {
#pragma unroll
        for (int hf = 0; hf < 2; hf++) {
            int qrow = q0 + t2*16 + gid + hf*8;
            float2 qv = *(const float2*)(g_q + (size_t)(b*S + qrow)*D + hh*HD + tig*2);
            qa[t2][hf] = cvt_f16x2(qv.y, qv.x);
        }
    }

    float acc0[4] = {0,0,0,0}, acc1[4] = {0,0,0,0};
    float lac0[4] = {0,0,0,0}, lac1[4] = {0,0,0,0};
    const uint ones2 = 0x3C003C00u;
    const __half* kptr = sK  + gid*8 + tig*2;
    const __half* vptr = sVT + gid*VPAD2 + tig*2;

#pragma unroll 2
    for (int j0 = 0; j0 < CK2; j0 += 16) {
        uint kb0 = *(const uint*)(kptr + j0*8);
        uint kb1 = *(const uint*)(kptr + j0*8 + 64);
        uint vb0 = *(const uint*)(vptr + j0);
        uint vb1 = *(const uint*)(vptr + j0 + 8);
        {
            uint s01a, s23a, s01b, s23b;
            mma16n8k8_f16(s01a, s23a, qa[0][0], qa[0][1], kb0);
            mma16n8k8_f16(s01b, s23b, qa[0][0], qa[0][1], kb1);
            uint p0 = hex2x2(s01a), p1 = hex2x2(s23a);
            uint p2 = hex2x2(s01b), p3 = hex2x2(s23b);
            mma16n8k16(acc0, p0, p1, p2, p3, vb0, vb1);
            mma16n8k16(lac0, p0, p1, p2, p3, ones2, ones2);
        }
        {
            uint s01a, s23a, s01b, s23b;
            mma16n8k8_f16(s01a, s23a, qa[1][0], qa[1][1], kb0);
            mma16n8k8_f16(s01b, s23b, qa[1][0], qa[1][1], kb1);
            uint p0 = hex2x2(s01a), p1 = hex2x2(s23a);
            uint p2 = hex2x2(s01b), p3 = hex2x2(s23b);
            mma16n8k16(acc1, p0, p1, p2, p3, vb0, vb1);
            mma16n8k16(lac1, p0, p1, p2, p3, ones2, ones2);
        }
    }

    size_t base = ((size_t)ck*128 + bh)*S;
    {
        float* pp = g_part + (base + q0 + gid)*12;
        *(float2*)(pp + tig*2) = make_float2(acc0[0], acc0[1]);
        if (tig == 0) pp[8] = lac0[0];
        pp = g_part + (base + q0 + gid + 8)*12;
        *(float2*)(pp + tig*2) = make_float2(acc0[2], acc0[3]);
        if (tig == 0) pp[8] = lac0[2];
        pp = g_part + (base + q0 + 16 + gid)*12;
        *(float2*)(pp + tig*2) = make_float2(acc1[0], acc1[1]);
        if (tig == 0) pp[8] = lac1[0];
        pp = g_part + (base + q0 + 24 + gid)*12;
        *(float2*)(pp + tig*2) = make_float2(acc1[2], acc1[3]);
        if (tig == 0) pp[8] = lac1[2];
    }
}

// ---------------- 3) FUSED: combine + oproj + LN1 + FFN1 + ReLU + FFN2 + LN2 ----------------
// dynamic smem layout (uints): sA[0,2304) sWo[2304,4480) sW1[4480,8704) sW2[8704,13056)
__global__ void __launch_bounds__(128) k_block_mma(
        const float* __restrict__ Wo, const float* __restrict__ bo,
        const float* __restrict__ g1, const float* __restrict__ b1,
        const float* __restrict__ Wf1, const float* __restrict__ bf1,
        const float* __restrict__ Wf2, const float* __restrict__ bf2,
        const float* __restrict__ g2, const float* __restrict__ b2, int l) {
    extern __shared__ uint smem[];
    uint* sA  = smem;
    uint* sWo = smem + 2304;
    uint* sW1 = smem + 4480;
    uint* sW2 = smem + 8704;
    int tid = threadIdx.x;
    int row0 = blockIdx.x * 64;

    // combine attention partials -> normalized attention output (fp16 A)
    for (int idx = tid; idx < 2048; idx += 128) {
        int r = idx >> 5, c2 = idx & 31;
        int grow = row0 + r;
        int q  = grow & (S-1);
        int bb = grow >> 10;
        int hh = c2 >> 2;
        int bh = bb*8 + hh;
        int off = (c2 & 3)*2;
        const float* p0 = g_part + ((size_t)(0*128 + bh)*S + q)*12;
        const float* p1 = g_part + ((size_t)(1*128 + bh)*S + q)*12;
        float inv = 1.0f / (p0[8] + p1[8]);
        float a0 = (p0[off]   + p1[off])   * inv;
        float a1 = (p0[off+1] + p1[off+1]) * inv;
        sA[r*36 + c2] = cvt_f16x2(a1, a0);
    }
    {
        const float* W = Wo + l*4096;
        for (int idx = tid; idx < 2048; idx += 128) {
            int ip = idx >> 6, n = idx & 63;
            sWo[ip*68 + n] = cvt_f16x2(W[(2*ip+1)*64 + n], W[(2*ip)*64 + n]);
        }
        const float* W1 = Wf1 + l*8192;
        for (int idx = tid; idx < 4096; idx += 128) {
            int ip = idx >> 7, n = idx & 127;
            sW1[ip*132 + n] = cvt_f16x2(W1[(2*ip+1)*128 + n], W1[(2*ip)*128 + n]);
        }
        const float* W2 = Wf2 + l*8192;
        for (int idx = tid; idx < 4096; idx += 128) {
            int ip = idx >> 6, n = idx & 63;
            sW2[ip*68 + n] = cvt_f16x2(W2[(2*ip+1)*64 + n], W2[(2*ip)*64 + n]);
        }
    }
    __syncthreads();

    int warp = tid >> 5, lane = tid & 31;
    int gid = lane >> 2, tig = lane & 3;
    int rA = row0 + warp*16 + gid;
    int rB = rA + 8;

    // ---- oproj ----
    uint a[4][4];
    load_afrag64(a, sA, warp*16, gid, tig);
    float acc[8][4];
#pragma unroll
    for (int t = 0; t < 8; t++) {
        acc[t][0]=0; acc[t][1]=0; acc[t][2]=0; acc[t][3]=0;
#pragma unroll
        for (int kk = 0; kk < 4; kk++) {
            uint b0 = sWo[(kk*8 + tig)*68 + t*8 + gid];
            uint b1 = sWo[(kk*8 + 4 + tig)*68 + t*8 + gid];
            mma16n8k16(acc[t], a[kk][0], a[kk][1], a[kk][2], a[kk][3], b0, b1);
        }
    }
    // bias + residual + LN1 (kept in registers)
    float vA[16], vB[16];
    {
        float sumA=0, sqA=0, sumB=0, sqB=0;
#pragma unroll
        for (int t = 0; t < 8; t++) {
            float2 bo2 = *(const float2*)(bo + l*D + t*8 + tig*2);
            float2 hA = *(const float2*)(g_h + (size_t)rA*D + t*8 + tig*2);
            float2 hB = *(const float2*)(g_h + (size_t)rB*D + t*8 + tig*2);
            float a0 = acc[t][0] + bo2.x + hA.x;
            float a1 = acc[t][1] + bo2.y + hA.y;
            float b0 = acc[t][2] + bo2.x + hB.x;
            float b1 = acc[t][3] + bo2.y + hB.y;
            vA[t*2]=a0; vA[t*2+1]=a1; vB[t*2]=b0; vB[t*2+1]=b1;
            sumA += a0+a1; sqA += a0*a0+a1*a1;
            sumB += b0+b1; sqB += b0*b0+b1*b1;
        }
#pragma unroll
        for (int o = 1; o < 4; o <<= 1) {
            sumA += __shfl_xor_sync(0xffffffffu, sumA, o);
            sqA  += __shfl_xor_sync(0xffffffffu, sqA,  o);
            sumB += __shfl_xor_sync(0xffffffffu, sumB, o);
            sqB  += __shfl_xor_sync(0xffffffffu, sqB,  o);
        }
        float mA = sumA*(1.f/64.f), vrA = sqA*(1.f/64.f) - mA*mA;
        float mB = sumB*(1.f/64.f), vrB = sqB*(1.f/64.f) - mB*mB;
        float rsA = rsqrtf(vrA + 1e-5f), rsB = rsqrtf(vrB + 1e-5f);
#pragma unroll
        for (int t = 0; t < 8; t++) {
            float2 gg = *(const float2*)(g1 + l*D + t*8 + tig*2);
            float2 bb = *(const float2*)(b1 + l*D + t*8 + tig*2);
            vA[t*2]   = (vA[t*2]  -mA)*rsA*gg.x + bb.x;
            vA[t*2+1] = (vA[t*2+1]-mA)*rsA*gg.y + bb.y;
            vB[t*2]   = (vB[t*2]  -mB)*rsB*gg.x + bb.x;
            vB[t*2+1] = (vB[t*2+1]-mB)*rsB*gg.y + bb.y;
        }
    }
    __syncthreads();   // all afrags consumed; safe to overwrite sA
    // write LN1'd h into sA as fp16
#pragma unroll
    for (int t = 0; t < 8; t++) {
        sA[(warp*16 + gid)*36     + t*4 + tig] = cvt_f16x2(vA[t*2+1], vA[t*2]);
        sA[(warp*16 + gid + 8)*36 + t*4 + tig] = cvt_f16x2(vB[t*2+1], vB[t*2]);
    }
    __syncthreads();

    // ---- FFN phase 1 ----
    uint a2[4][4];
    load_afrag64(a2, sA, warp*16, gid, tig);
    uint hA[16][2];
#pragma unroll
    for (int t = 0; t < 16; t++) {
        float facc[4] = {0,0,0,0};
#pragma unroll
        for (int kk = 0; kk < 4; kk++) {
            uint b0 = sW1[(kk*8 + tig)*132 + t*8 + gid];
            uint b1 = sW1[(kk*8 + 4 + tig)*132 + t*8 + gid];
            mma16n8k16(facc, a2[kk][0], a2[kk][1], a2[kk][2], a2[kk][3], b0, b1);
        }
        float2 bf = *(const float2*)(bf1 + l*FF + t*8 + tig*2);
        float c0 = fmaxf(facc[0] + bf.x, 0.f);
        float c1 = fmaxf(facc[1] + bf.y, 0.f);
        float c2 = fmaxf(facc[2] + bf.x, 0.f);
        float c3 = fmaxf(facc[3] + bf.y, 0.f);
        hA[t][0] = cvt_f16x2(c1, c0);
        hA[t][1] = cvt_f16x2(c3, c2);
    }

    // ---- FFN phase 2 ----
#pragma unroll
    for (int t = 0; t < 8; t++) {
        acc[t][0]=0; acc[t][1]=0; acc[t][2]=0; acc[t][3]=0;
#pragma unroll
        for (int kk = 0; kk < 8; kk++) {
            uint b0 = sW2[(kk*8 + tig)*68 + t*8 + gid];
            uint b1 = sW2[(kk*8 + 4 + tig)*68 + t*8 + gid];
            mma16n8k16(acc[t], hA[2*kk][0], hA[2*kk][1], hA[2*kk+1][0], hA[2*kk+1][1], b0, b1);
        }
    }
    // bias + residual (LN1 output in regs) + LN2 -> g_h
    {
        float sumA=0, sqA=0, sumB=0, sqB=0;
        float wA[16], wB[16];
#pragma unroll
        for (int t = 0; t < 8; t++) {
            float2 bo2 = *(const float2*)(bf2 + l*D + t*8 + tig*2);
            float a0 = acc[t][0] + bo2.x + vA[t*2];
            float a1 = acc[t][1] + bo2.y + vA[t*2+1];
            float b0 = acc[t][2] + bo2.x + vB[t*2];
            float b1 = acc[t][3] + bo2.y + vB[t*2+1];
            wA[t*2]=a0; wA[t*2+1]=a1; wB[t*2]=b0; wB[t*2+1]=b1;
            sumA += a0+a1; sqA += a0*a0+a1*a1;
            sumB += b0+b1; sqB += b0*b0+b1*b1;
        }
#pragma unroll
        for (int o = 1; o < 4; o <<= 1) {
            sumA += __shfl_xor_sync(0xffffffffu, sumA, o);
            sqA  += __shfl_xor_sync(0xffffffffu, sqA,  o);
            sumB += __shfl_xor_sync(0xffffffffu, sumB, o);
            sqB  += __shfl_xor_sync(0xffffffffu, sqB,  o);
        }
        float mA = sumA*(1.f/64.f), vrA = sqA*(1.f/64.f) - mA*mA;
        float mB = sumB*(1.f/64.f), vrB = sqB*(1.f/64.f) - mB*mB;
        float rsA = rsqrtf(vrA + 1e-5f), rsB = rsqrtf(vrB + 1e-5f);
#pragma unroll
        for (int t = 0; t < 8; t++) {
            float2 gg = *(const float2*)(g2 + l*D + t*8 + tig*2);
            float2 bb = *(const float2*)(b2 + l*D + t*8 + tig*2);
            *(float2*)(g_h + (size_t)rA*D + t*8 + tig*2) =
                make_float2((wA[t*2]-mA)*rsA*gg.x + bb.x, (wA[t*2+1]-mA)*rsA*gg.y + bb.y);
            *(float2*)(g_h + (size_t)rB*D + t*8 + tig*2) =
                make_float2((wB[t*2]-mB)*rsB*gg.x + bb.x, (wB[t*2+1]-mB)*rsB*gg.y + bb.y);
        }
    }
}

// ---------------- 4) pool + MLP + quantum circuit + <Z> + entropy ----------------
#define BARS128() asm volatile("bar.sync 1, 128;" ::: "memory")

__global__ void k_pool_quantum(const float* __restrict__ Wp1, const float* __restrict__ bp1,
                               const float* __restrict__ Wp2, const float* __restrict__ bp2,
                               const float* __restrict__ qw, float* __restrict__ out) {
    __shared__ float sp2[256];
    __shared__ float sp[64];
    __shared__ float sh[32];
    __shared__ float sang[8];
    __shared__ float2 st[256];
    __shared__ float2 rho[256];
    __shared__ float  sred[256];
    __shared__ float  jc[8], js[8], jpx[8], jpy[8];
    int b = blockIdx.x, tid = threadIdx.x;

    {
        int col = tid & 63, ch = tid >> 6;
        const float* hb = g_h + (size_t)b*S*D + (size_t)ch*256*D;
        float sum = 0.f;
#pragma unroll 8
        for (int s = 0; s < 256; s++) sum += hb[s*D + col];
        sp2[tid] = sum;
    }
    __syncthreads();
    if (tid < 64)
        sp[tid] = (sp2[tid] + sp2[tid+64] + sp2[tid+128] + sp2[tid+192]) * (1.0f/(float)S);
    __syncthreads();
    if (tid < 32) {
        float a = bp1[tid];
#pragma unroll
        for (int i = 0; i < 64; i++) a += sp[i] * Wp1[i*32 + tid];
        sh[tid] = fmaxf(a, 0.f);
    }
    __syncthreads();
    if (tid < 8) {
        float a = bp2[tid];
#pragma unroll
        for (int i = 0; i < 32; i++) a += sh[i] * Wp2[i*8 + tid];
        sang[tid] = tanhf(a) * 3.14159265358979f;
    }

    st[tid] = make_float2(tid == 0 ? 1.f : 0.f, 0.f);
    __syncthreads();

    for (int l = 0; l < QL; l++) {
        for (int w = 0; w < NQ; w++) {
            int mask = 1 << (7 - w);
            float c = cosf(0.5f * sang[w]);
            float s = sinf(0.5f * sang[w]);
            if (!(tid & mask)) {
                float2 v0 = st[tid], v1 = st[tid | mask];
                st[tid]        = make_float2(c*v0.x + s*v1.y,  c*v0.y - s*v1.x);
                st[tid | mask] = make_float2(s*v0.y + c*v1.x, -s*v0.x + c*v1.y);
            }
            __syncthreads();
        }
        for (int w = 0; w < NQ; w++) {
            int mask = 1 << (7 - w);
            float phi = qw[(l*NQ + w)*3 + 0];
            float th  = qw[(l*NQ + w)*3 + 1];
            float om  = qw[(l*NQ + w)*3 + 2];
            float ct = cosf(0.5f*th), stt = sinf(0.5f*th);
            float aa = 0.5f*(phi + om), bb = 0.5f*(phi - om);
            float ca = cosf(aa), sa = sinf(aa), cb = cosf(bb), sb = sinf(bb);
            float2 U00 = make_float2( ct*ca, -ct*sa);
            float2 U01 = make_float2(-stt*cb, -stt*sb);
            float2 U10 = make_float2( stt*cb, -stt*sb);
            float2 U11 = make_float2( ct*ca,  ct*sa);
            if (!(tid & mask)) {
                float2 v0 = st[tid], v1 = st[tid | mask];
                st[tid]        = cadd(cmul(U00, v0), cmul(U01, v1));
                st[tid | mask] = cadd(cmul(U10, v0), cmul(U11, v1));
            }
            __syncthreads();
        }
        for (int w = 0; w < NQ; w++) {
            int mc = 1 << (7 - w);
            int mt = 1 << (7 - ((w + 1) & 7));
            if ((tid & mc) && !(tid & mt)) {
                float2 t0 = st[tid];
                st[tid] = st[tid | mt];
                st[tid | mt] = t0;
            }
            __syncthreads();
        }
    }

    float p = st[tid].x*st[tid].x + st[tid].y*st[tid].y;
    for (int w = 0; w < 3; w++) {
        sred[tid] = (tid & (1 << (7 - w))) ? -p : p;
        __syncthreads();
        for (int off = 128; off > 0; off >>= 1) {
            if (tid < off) sred[tid] += sred[tid + off];
            __syncthreads();
        }
        if (tid == 0) out[b*3 + w] = sred[0];
        __syncthreads();
    }

    {
        int r = tid >> 4, c = tid & 15;
        float2 acc = make_float2(0.f, 0.f);
#pragma unroll
        for (int k = 0; k < 16; k++) {
            float2 mr = st[r*16 + k], mcv = st[c*16 + k];
            acc.x += mr.x*mcv.x + mr.y*mcv.y;
            acc.y += mr.y*mcv.x - mr.x*mcv.y;
        }
        rho[tid] = acc;
    }
    __syncthreads();

    if (tid < 128) {
        int g = tid >> 4, k = tid & 15;
        for (int sweep = 0; sweep < 6; sweep++) {
            for (int rnd = 0; rnd < 15; rnd++) {
                int pa, qa_;
                if (g == 0) { pa = 15; qa_ = rnd; }
                else {
                    pa  = (rnd + g) % 15;
                    qa_ = (rnd + 15 - g) % 15;
                }
                int pp = min(pa, qa_), qq = max(pa, qa_);
                if (k == 0) {
                    float2 apq = rho[pp*16 + qq];
                    float b2v = apq.x*apq.x + apq.y*apq.y;
                    if (b2v > 1e-26f) {
                        float app = rho[pp*16 + pp].x;
                        float aqq = rho[qq*16 + qq].x;
                        float bn  = sqrtf(b2v);
                        float tau = (aqq - app) / (2.f * bn);
                        float rt  = sqrtf(1.f + tau*tau);
                        float t   = (tau >= 0.f) ? 1.f/(tau + rt) : -1.f/(-tau + rt);
                        float cc  = rsqrtf(1.f + t*t);
                        jc[g] = cc; js[g] = t*cc;
                        jpx[g] = apq.x/bn; jpy[g] = apq.y/bn;
                    } else {
                        jc[g] = 1.f; js[g] = 0.f; jpx[g] = 1.f; jpy[g] = 0.f;
                    }
                }
                BARS128();
                float cc = jc[g], ss = js[g];
                float2 ph = make_float2(jpx[g], jpy[g]);
                {
                    float2 rp = rho[pp*16 + k], rq = rho[qq*16 + k];
                    float2 prq  = cmul(ph, rq);
                    float2 cprp = cmulcj(ph, rp);
                    rho[pp*16 + k] = make_float2(cc*rp.x - ss*prq.x,  cc*rp.y - ss*prq.y);
                    rho[qq*16 + k] = make_float2(ss*cprp.x + cc*rq.x, ss*cprp.y + cc*rq.y);
                }
                BARS128();
                {
                    float2 cp = rho[k*16 + pp], cq = rho[k*16 + qq];
                    float2 ccq = cmulcj(ph, cq);
                    float2 pcp = cmul(ph, cp);
                    rho[k*16 + pp] = make_float2(cc*cp.x - ss*ccq.x,  cc*cp.y - ss*ccq.y);
                    rho[k*16 + qq] = make_float2(ss*pcp.x + cc*cq.x, ss*pcp.y + cc*cq.y);
                }
                BARS128();
            }
        }
        if (tid == 0) {
            float ent = 0.f;
#pragma unroll
            for (int kk = 0; kk < 16; kk++) {
                float ev = rho[kk*16 + kk].x;
                ev = fminf(fmaxf(ev, 1e-10f), 1.f);
                ent -= ev * logf(ev);
            }
            out[48 + b] = ent;
        }
    }
}

// ---------------- launch ----------------
extern "C" void kernel_launch(void* const* d_in, const int* in_sizes, int n_in,
                              void* d_out, int out_size) {
    const float* x    = (const float*)d_in[0];
    const float* Wemb = (const float*)d_in[1];
    const float* bemb = (const float*)d_in[2];
    const float* Wq   = (const float*)d_in[3];
    const float* bq   = (const float*)d_in[4];
    const float* Wk   = (const float*)d_in[5];
    const float* bk   = (const float*)d_in[6];
    const float* Wv   = (const float*)d_in[7];
    const float* bv   = (const float*)d_in[8];
    const float* Wo   = (const float*)d_in[9];
    const float* bo   = (const float*)d_in[10];
    const float* ln1g = (const float*)d_in[11];
    const float* ln1b = (const float*)d_in[12];
    const float* ln2g = (const float*)d_in[13];
    const float* ln2b = (const float*)d_in[14];
    const float* Wf1  = (const float*)d_in[15];
    const float* bf1  = (const float*)d_in[16];
    const float* Wf2  = (const float*)d_in[17];
    const float* bf2  = (const float*)d_in[18];
    const float* Wp1  = (const float*)d_in[19];
    const float* bp1  = (const float*)d_in[20];
    const float* Wp2  = (const float*)d_in[21];
    const float* bp2  = (const float*)d_in[22];
    const float* qw   = (const float*)d_in[23];
    float* out = (float*)d_out;

    cudaFuncSetAttribute(k_block_mma, cudaFuncAttributeMaxDynamicSharedMemorySize, 53248);

    k_pe<<<128, 256>>>();
    for (int l = 0; l < NL; l++) {
        dim3 qg(256, 3);
        k_qkv_mma<<<qg, 128>>>(Wq, bq, Wk, bk, Wv, bv, x, Wemb, bemb, l);
        dim3 ag(16, B*H);
        k_attn_mma<<<ag, 128>>>();
        k_block_mma<<<256, 128, 53248>>>(Wo, bo, ln1g, ln1b, Wf1, bf1, Wf2, bf2, ln2g, ln2b, l);
    }
    k_pool_quantum<<<B, 256>>>(Wp1, bp1, Wp2, bp2, qw, out);
}

// round 10
// speedup vs baseline: 1.1469x; 1.0191x over previous
#include <cuda_runtime.h>
#include <cuda_fp16.h>
#include <math.h>

#define B   16
#define S   1024
#define NF  5
#define D   64
#define H   8
#define HD  8
#define NL  2
#define FF  128
#define NQ  8
#define QL  3
#define BS  (B*S)
#define CK2  512
#define VPAD2 520

typedef unsigned long long ull;
typedef unsigned int uint;

// ---------------- device scratch ----------------
__device__ float g_h  [BS*D];
__device__ float g_q  [BS*D];
__device__ float g_k  [BS*D];
__device__ float g_v  [BS*D];
__device__ float g_pe [S*D];
__device__ float g_part[(size_t)2*128*S*12];   // 12.6 MB partials
// prepacked half2 weights (B-fragment layout)
__device__ uint g_pWo[NL*32*68];    // stride 68
__device__ uint g_pW1[NL*32*132];   // stride 132
__device__ uint g_pW2[NL*64*68];    // stride 68

// ---------------- mma / f16 helpers ----------------
__device__ __forceinline__ void mma16n8k8_f16(uint& d0, uint& d1, uint a0, uint a1, uint b0) {
    asm volatile("mma.sync.aligned.m16n8k8.row.col.f16.f16.f16.f16 "
        "{%0,%1}, {%2,%3}, {%4}, {%5,%6};"
        : "=r"(d0), "=r"(d1)
        : "r"(a0), "r"(a1), "r"(b0), "r"(0u), "r"(0u));
}
__device__ __forceinline__ void mma16n8k16(float* d,
                                           uint a0, uint a1, uint a2, uint a3,
                                           uint b0, uint b1) {
    asm volatile("mma.sync.aligned.m16n8k16.row.col.f32.f16.f16.f32 "
        "{%0,%1,%2,%3}, {%4,%5,%6,%7}, {%8,%9}, {%0,%1,%2,%3};"
        : "+f"(d[0]), "+f"(d[1]), "+f"(d[2]), "+f"(d[3])
        : "r"(a0), "r"(a1), "r"(a2), "r"(a3), "r"(b0), "r"(b1));
}
__device__ __forceinline__ uint cvt_f16x2(float hi, float lo) {
    uint r; asm("cvt.rn.f16x2.f32 %0, %1, %2;" : "=r"(r) : "f"(hi), "f"(lo)); return r;
}
__device__ __forceinline__ uint hex2x2(uint x) {
    uint r; asm("ex2.approx.f16x2 %0, %1;" : "=r"(r) : "r"(x)); return r;
}

// ---------------- complex helpers ----------------
__device__ __forceinline__ float2 cmul(float2 a, float2 b) {
    return make_float2(a.x*b.x - a.y*b.y, a.x*b.y + a.y*b.x);
}
__device__ __forceinline__ float2 cmulcj(float2 a, float2 b) {
    return make_float2(a.x*b.x + a.y*b.y, a.x*b.y - a.y*b.x);
}
__device__ __forceinline__ float2 cadd(float2 a, float2 b) {
    return make_float2(a.x + b.x, a.y + b.y);
}

// ---------------- 0a) positional-encoding table ----------------
__global__ void k_pe() {
    int idx = blockIdx.x * blockDim.x + threadIdx.x;   // < 32768
    int s = idx >> 5, p = idx & 31;
    float div = __expf(-0.14391156831212787f * (float)(2*p));
    float sn, cs;
    sincosf((float)s * div, &sn, &cs);
    g_pe[s*64 + 2*p]     = sn;
    g_pe[s*64 + 2*p + 1] = cs;
}

// ---------------- 0b) weight prepack (both layers) ----------------
__global__ void k_pack(const float* __restrict__ Wo,
                       const float* __restrict__ Wf1,
                       const float* __restrict__ Wf2) {
    int idx = blockIdx.x * blockDim.x + threadIdx.x;   // < NL*10240
    int l = idx / 10240;
    int r = idx % 10240;
    if (r < 2048) {                        // Wo: 32 ip x 64 n
        int ip = r >> 6, n = r & 63;
        const float* W = Wo + l*4096;
        g_pWo[l*2176 + ip*68 + n] = cvt_f16x2(W[(2*ip+1)*64 + n], W[(2*ip)*64 + n]);
    } else if (r < 6144) {                 // W1: 32 ip x 128 n
        int q = r - 2048;
        int ip = q >> 7, n = q & 127;
        const float* W = Wf1 + l*8192;
        g_pW1[l*4224 + ip*132 + n] = cvt_f16x2(W[(2*ip+1)*128 + n], W[(2*ip)*128 + n]);
    } else {                               // W2: 64 ip x 64 n
        int q = r - 6144;
        int ip = q >> 6, n = q & 63;
        const float* W = Wf2 + l*8192;
        g_pW2[l*4352 + ip*68 + n] = cvt_f16x2(W[(2*ip+1)*64 + n], W[(2*ip)*64 + n]);
    }
}

// ======== MMA GEMM common fragment loaders ========
__device__ __forceinline__ void load_afrag64(uint (&a)[4][4], const uint* sA, int rbase, int gid, int tig) {
    const uint* r0 = sA + (rbase + gid)*36;
    const uint* r1 = sA + (rbase + gid + 8)*36;
#pragma unroll
    for (int kk = 0; kk < 4; kk++) {
        a[kk][0] = r0[kk*8 + tig];
        a[kk][1] = r1[kk*8 + tig];
        a[kk][2] = r0[kk*8 + 4 + tig];
        a[kk][3] = r1[kk*8 + 4 + tig];
    }
}

// ---------------- 1) QKV projection via mma (64 rows/block, grid.y = matrix) ----------------
__global__ void __launch_bounds__(128) k_qkv_mma(
        const float* __restrict__ Wq, const float* __restrict__ bq,
        const float* __restrict__ Wk, const float* __restrict__ bk,
        const float* __restrict__ Wv, const float* __restrict__ bv,
        const float* __restrict__ x,  const float* __restrict__ Wemb,
        const float* __restrict__ bemb, int l) {
    __shared__ uint  sA [64*36];
    __shared__ uint  sWp[32*68];
    __shared__ float sX [64*NF];
    int tid = threadIdx.x;
    int row0 = blockIdx.x * 64;
    int m = blockIdx.y;
    const float* W    = (m == 0) ? (Wq + l*4096) : (m == 1) ? (Wk + l*4096) : (Wv + l*4096);
    const float* bias = (m == 0) ? (bq + l*D)    : (m == 1) ? (bk + l*D)    : (bv + l*D);
    float* out        = (m == 0) ? g_q : (m == 1) ? g_k : g_v;

    if (l == 0) {
        for (int idx = tid; idx < 64*NF; idx += 128)
            sX[idx] = x[(size_t)(row0 + idx/NF)*NF + idx%NF];
        __syncthreads();
        for (int idx = tid; idx < 2048; idx += 128) {
            int r = idx >> 5, c2 = idx & 31;
            int row = row0 + r;
            int s = row & (S-1);
            int c = c2*2;
            float v0 = bemb[c]   + g_pe[s*64 + c];
            float v1 = bemb[c+1] + g_pe[s*64 + c + 1];
            const float* xr = sX + r*NF;
#pragma unroll
            for (int f = 0; f < NF; f++) {
                v0 += xr[f] * Wemb[f*D + c];
                v1 += xr[f] * Wemb[f*D + c + 1];
            }
            sA[r*36 + c2] = cvt_f16x2(v1, v0);
            if (m == 0) *(float2*)(g_h + (size_t)row*D + c) = make_float2(v0, v1);
        }
    } else {
        for (int idx = tid; idx < 2048; idx += 128) {
            int r = idx >> 5, c2 = idx & 31;
            float2 v = *(const float2*)(g_h + (size_t)(row0 + r)*D + c2*2);
            sA[r*36 + c2] = cvt_f16x2(v.y, v.x);
        }
    }
    for (int idx = tid; idx < 2048; idx += 128) {
        int ip = idx >> 6, n = idx & 63;
        sWp[ip*68 + n] = cvt_f16x2(W[(2*ip+1)*64 + n], W[(2*ip)*64 + n]);
    }
    __syncthreads();

    int warp = tid >> 5, lane = tid & 31;
    int gid = lane >> 2, tig = lane & 3;
    uint a[4][4];
    load_afrag64(a, sA, warp*16, gid, tig);

#pragma unroll
    for (int t = 0; t < 8; t++) {
        float acc[4] = {0,0,0,0};
#pragma unroll
        for (int kk = 0; kk < 4; kk++) {
            uint b0 = sWp[(kk*8 + tig)*68 + t*8 + gid];
            uint b1 = sWp[(kk*8 + 4 + tig)*68 + t*8 + gid];
            mma16n8k16(acc, a[kk][0], a[kk][1], a[kk][2], a[kk][3], b0, b1);
        }
        float2 bv2 = *(const float2*)(bias + t*8 + tig*2);
        int r = row0 + warp*16 + gid;
        *(float2*)(out + (size_t)r*D + t*8 + tig*2) =
            make_float2(acc[0] + bv2.x, acc[1] + bv2.y);
        *(float2*)(out + (size_t)(r + 8)*D + t*8 + tig*2) =
            make_float2(acc[2] + bv2.x, acc[3] + bv2.y);
    }
}

// ---------------- 2) split-K attention via mma: f16-accum QK, k16 PV ----------------
__global__ void __launch_bounds__(128) k_attn_mma() {
    __shared__ __half sK [CK2*8];
    __shared__ __half sVT[8*VPAD2];
    int tid = threadIdx.x;
    int bh  = blockIdx.y;
    int b   = bh >> 3, hh = bh & 7;
    int qt  = blockIdx.x >> 1;
    int ck  = blockIdx.x & 1;
    int k0  = ck * CK2;
    const float* kbase = g_k + (size_t)(b*S + k0)*D + hh*HD;
    const float* vbase = g_v + (size_t)(b*S + k0)*D + hh*HD;
    const float pre = 0.35355339059327373f * 1.4426950408889634f;
    for (int i = tid; i < CK2*8; i += 128) {
        int key = i >> 3, d = i & 7;
        sK[i]             = __float2half(kbase[key*D + d] * pre);
        sVT[d*VPAD2 + key] = __float2half(vbase[key*D + d]);
    }
    __syncthreads();

    int warp = tid >> 5, lane = tid & 31;
    int gid  = lane >> 2, tig = lane & 3;
    int q0   = qt * 128 + warp * 32;

    uint qa[2][2];
#pragma unroll
    for (int t2 = 0; t2 < 2; t2++) {
#pragma unroll
        for (int hf = 0; hf < 2; hf++) {
            int qrow = q0 + t2*16 + gid + hf*8;
            float2 qv = *(const float2*)(g_q + (size_t)(b*S + qrow)*D + hh*HD + tig*2);
            qa[t2][hf] = cvt_f16x2(qv.y, qv.x);
        }
    }

    float acc0[4] = {0,0,0,0}, acc1[4] = {0,0,0,0};
    float lac0[4] = {0,0,0,0}, lac1[4] = {0,0,0,0};
    const uint ones2 = 0x3C003C00u;
    const __half* kptr = sK  + gid*8 + tig*2;
    const __half* vptr = sVT + gid*VPAD2 + tig*2;

#pragma unroll 2
    for (int j0 = 0; j0 < CK2; j0 += 16) {
        uint kb0 = *(const uint*)(kptr + j0*8);
        uint kb1 = *(const uint*)(kptr + j0*8 + 64);
        uint vb0 = *(const uint*)(vptr + j0);
        uint vb1 = *(const uint*)(vptr + j0 + 8);
        {
            uint s01a, s23a, s01b, s23b;
            mma16n8k8_f16(s01a, s23a, qa[0][0], qa[0][1], kb0);
            mma16n8k8_f16(s01b, s23b, qa[0][0], qa[0][1], kb1);
            uint p0 = hex2x2(s01a), p1 = hex2x2(s23a);
            uint p2 = hex2x2(s01b), p3 = hex2x2(s23b);
            mma16n8k16(acc0, p0, p1, p2, p3, vb0, vb1);
            mma16n8k16(lac0, p0, p1, p2, p3, ones2, ones2);
        }
        {
            uint s01a, s23a, s01b, s23b;
            mma16n8k8_f16(s01a, s23a, qa[1][0], qa[1][1], kb0);
            mma16n8k8_f16(s01b, s23b, qa[1][0], qa[1][1], kb1);
            uint p0 = hex2x2(s01a), p1 = hex2x2(s23a);
            uint p2 = hex2x2(s01b), p3 = hex2x2(s23b);
            mma16n8k16(acc1, p0, p1, p2, p3, vb0, vb1);
            mma16n8k16(lac1, p0, p1, p2, p3, ones2, ones2);
        }
    }

    size_t base = ((size_t)ck*128 + bh)*S;
    {
        float* pp = g_part + (base + q0 + gid)*12;
        *(float2*)(pp + tig*2) = make_float2(acc0[0], acc0[1]);
        if (tig == 0) pp[8] = lac0[0];
        pp = g_part + (base + q0 + gid + 8)*12;
        *(float2*)(pp + tig*2) = make_float2(acc0[2], acc0[3]);
        if (tig == 0) pp[8] = lac0[2];
        pp = g_part + (base + q0 + 16 + gid)*12;
        *(float2*)(pp + tig*2) = make_float2(acc1[0], acc1[1]);
        if (tig == 0) pp[8] = lac1[0];
        pp = g_part + (base + q0 + 24 + gid)*12;
        *(float2*)(pp + tig*2) = make_float2(acc1[2], acc1[3]);
        if (tig == 0) pp[8] = lac1[2];
    }
}

// ---------------- 3) FUSED block: combine + oproj + LN1 + FFN + LN2 ----------------
// 32 rows/CTA, 64 threads (2 warps), weights direct from prepacked gmem (L2-hot)
__global__ void __launch_bounds__(64) k_block_mma(
        const float* __restrict__ bo,
        const float* __restrict__ g1, const float* __restrict__ b1,
        const float* __restrict__ bf1, const float* __restrict__ bf2,
        const float* __restrict__ g2, const float* __restrict__ b2, int l) {
    __shared__ uint sA[32*36];
    int tid = threadIdx.x;
    int row0 = blockIdx.x * 32;
    const uint* pWo = g_pWo + l*2176;
    const uint* pW1 = g_pW1 + l*4224;
    const uint* pW2 = g_pW2 + l*4352;

    // combine attention partials -> normalized attention output (fp16 A)
    for (int idx = tid; idx < 1024; idx += 64) {
        int r = idx >> 5, c2 = idx & 31;
        int grow = row0 + r;
        int q  = grow & (S-1);
        int bb = grow >> 10;
        int hh = c2 >> 2;
        int bh = bb*8 + hh;
        int off = (c2 & 3)*2;
        const float* p0 = g_part + ((size_t)(0*128 + bh)*S + q)*12;
        const float* p1 = g_part + ((size_t)(1*128 + bh)*S + q)*12;
        float inv = 1.0f / (p0[8] + p1[8]);
        float a0 = (p0[off]   + p1[off])   * inv;
        float a1 = (p0[off+1] + p1[off+1]) * inv;
        sA[r*36 + c2] = cvt_f16x2(a1, a0);
    }
    __syncthreads();

    int warp = tid >> 5, lane = tid & 31;
    int gid = lane >> 2, tig = lane & 3;
    int rA = row0 + warp*16 + gid;
    int rB = rA + 8;

    // ---- oproj ----
    uint a[4][4];
    load_afrag64(a, sA, warp*16, gid, tig);
    float acc[8][4];
#pragma unroll
    for (int t = 0; t < 8; t++) {
        acc[t][0]=0; acc[t][1]=0; acc[t][2]=0; acc[t][3]=0;
#pragma unroll
        for (int kk = 0; kk < 4; kk++) {
            uint b0 = pWo[(kk*8 + tig)*68 + t*8 + gid];
            uint b1 = pWo[(kk*8 + 4 + tig)*68 + t*8 + gid];
            mma16n8k16(acc[t], a[kk][0], a[kk][1], a[kk][2], a[kk][3], b0, b1);
        }
    }
    // bias + residual + LN1 (in registers)
    float vA[16], vB[16];
    {
        float sumA=0, sqA=0, sumB=0, sqB=0;
#pragma unroll
        for (int t = 0; t < 8; t++) {
            float2 bo2 = *(const float2*)(bo + l*D + t*8 + tig*2);
            float2 hA = *(const float2*)(g_h + (size_t)rA*D + t*8 + tig*2);
            float2 hB = *(const float2*)(g_h + (size_t)rB*D + t*8 + tig*2);
            float a0 = acc[t][0] + bo2.x + hA.x;
            float a1 = acc[t][1] + bo2.y + hA.y;
            float b0 = acc[t][2] + bo2.x + hB.x;
            float b1 = acc[t][3] + bo2.y + hB.y;
            vA[t*2]=a0; vA[t*2+1]=a1; vB[t*2]=b0; vB[t*2+1]=b1;
            sumA += a0+a1; sqA += a0*a0+a1*a1;
            sumB += b0+b1; sqB += b0*b0+b1*b1;
        }
#pragma unroll
        for (int o = 1; o < 4; o <<= 1) {
            sumA += __shfl_xor_sync(0xffffffffu, sumA, o);
            sqA  += __shfl_xor_sync(0xffffffffu, sqA,  o);
            sumB += __shfl_xor_sync(0xffffffffu, sumB, o);
            sqB  += __shfl_xor_sync(0xffffffffu, sqB,  o);
        }
        float mA = sumA*(1.f/64.f), vrA = sqA*(1.f/64.f) - mA*mA;
        float mB = sumB*(1.f/64.f), vrB = sqB*(1.f/64.f) - mB*mB;
        float rsA = rsqrtf(vrA + 1e-5f), rsB = rsqrtf(vrB + 1e-5f);
#pragma unroll
        for (int t = 0; t < 8; t++) {
            float2 gg = *(const float2*)(g1 + l*D + t*8 + tig*2);
            float2 bb = *(const float2*)(b1 + l*D + t*8 + tig*2);
            vA[t*2]   = (vA[t*2]  -mA)*rsA*gg.x + bb.x;
            vA[t*2+1] = (vA[t*2+1]-mA)*rsA*gg.y + bb.y;
            vB[t*2]   = (vB[t*2]  -mB)*rsB*gg.x + bb.x;
            vB[t*2+1] = (vB[t*2+1]-mB)*rsB*gg.y + bb.y;
        }
    }
    __syncthreads();   // afrags consumed; safe to overwrite sA
#pragma unroll
    for (int t = 0; t < 8; t++) {
        sA[(warp*16 + gid)*36     + t*4 + tig] = cvt_f16x2(vA[t*2+1], vA[t*2]);
        sA[(warp*16 + gid + 8)*36 + t*4 + tig] = cvt_f16x2(vB[t*2+1], vB[t*2]);
    }
    __syncthreads();

    // ---- FFN phase 1 ----
    uint a2[4][4];
    load_afrag64(a2, sA, warp*16, gid, tig);
    uint hA[16][2];
#pragma unroll
    for (int t = 0; t < 16; t++) {
        float facc[4] = {0,0,0,0};
#pragma unroll
        for (int kk = 0; kk < 4; kk++) {
            uint b0 = pW1[(kk*8 + tig)*132 + t*8 + gid];
            uint b1 = pW1[(kk*8 + 4 + tig)*132 + t*8 + gid];
            mma16n8k16(facc, a2[kk][0], a2[kk][1], a2[kk][2], a2[kk][3], b0, b1);
        }
        float2 bf = *(const float2*)(bf1 + l*FF + t*8 + tig*2);
        float c0 = fmaxf(facc[0] + bf.x, 0.f);
        float c1 = fmaxf(facc[1] + bf.y, 0.f);
        float c2 = fmaxf(facc[2] + bf.x, 0.f);
        float c3 = fmaxf(facc[3] + bf.y, 0.f);
        hA[t][0] = cvt_f16x2(c1, c0);
        hA[t][1] = cvt_f16x2(c3, c2);
    }

    // ---- FFN phase 2 ----
#pragma unroll
    for (int t = 0; t < 8; t++) {
        acc[t][0]=0; acc[t][1]=0; acc[t][2]=0; acc[t][3]=0;
#pragma unroll
        for (int kk = 0; kk < 8; kk++) {
            uint b0 = pW2[(kk*8 + tig)*68 + t*8 + gid];
            uint b1 = pW2[(kk*8 + 4 + tig)*68 + t*8 + gid];
            mma16n8k16(acc[t], hA[2*kk][0], hA[2*kk][1], hA[2*kk+1][0], hA[2*kk+1][1], b0, b1);
        }
    }
    // bias + residual + LN2 -> g_h
    {
        float sumA=0, sqA=0, sumB=0, sqB=0;
        float wA[16], wB[16];
#pragma unroll
        for (int t = 0; t < 8; t++) {
            float2 bo2 = *(const float2*)(bf2 + l*D + t*8 + tig*2);
            float a0 = acc[t][0] + bo2.x + vA[t*2];
            float a1 = acc[t][1] + bo2.y + vA[t*2+1];
            float b0 = acc[t][2] + bo2.x + vB[t*2];
            float b1 = acc[t][3] + bo2.y + vB[t*2+1];
            wA[t*2]=a0; wA[t*2+1]=a1; wB[t*2]=b0; wB[t*2+1]=b1;
            sumA += a0+a1; sqA += a0*a0+a1*a1;
            sumB += b0+b1; sqB += b0*b0+b1*b1;
        }
#pragma unroll
        for (int o = 1; o < 4; o <<= 1) {
            sumA += __shfl_xor_sync(0xffffffffu, sumA, o);
            sqA  += __shfl_xor_sync(0xffffffffu, sqA,  o);
            sumB += __shfl_xor_sync(0xffffffffu, sumB, o);
            sqB  += __shfl_xor_sync(0xffffffffu, sqB,  o);
        }
        float mA = sumA*(1.f/64.f), vrA = sqA*(1.f/64.f) - mA*mA;
        float mB = sumB*(1.f/64.f), vrB = sqB*(1.f/64.f) - mB*mB;
        float rsA = rsqrtf(vrA + 1e-5f), rsB = rsqrtf(vrB + 1e-5f);
#pragma unroll
        for (int t = 0; t < 8; t++) {
            float2 gg = *(const float2*)(g2 + l*D + t*8 + tig*2);
            float2 bb = *(const float2*)(b2 + l*D + t*8 + tig*2);
            *(float2*)(g_h + (size_t)rA*D + t*8 + tig*2) =
                make_float2((wA[t*2]-mA)*rsA*gg.x + bb.x, (wA[t*2+1]-mA)*rsA*gg.y + bb.y);
            *(float2*)(g_h + (size_t)rB*D + t*8 + tig*2) =
                make_float2((wB[t*2]-mB)*rsB*gg.x + bb.x, (wB[t*2+1]-mB)*rsB*gg.y + bb.y);
        }
    }
}

// ---------------- 4) pool + MLP + quantum circuit + <Z> + entropy ----------------
#define BARS128() asm volatile("bar.sync 1, 128;" ::: "memory")

__global__ void k_pool_quantum(const float* __restrict__ Wp1, const float* __restrict__ bp1,
                               const float* __restrict__ Wp2, const float* __restrict__ bp2,
                               const float* __restrict__ qw, float* __restrict__ out) {
    __shared__ float sp2[256];
    __shared__ float sp[64];
    __shared__ float sh[32];
    __shared__ float sang[8];
    __shared__ float2 st[256];
    __shared__ float2 rho[256];
    __shared__ float  sred[256];
    __shared__ float  jc[8], js[8], jpx[8], jpy[8];
    int b = blockIdx.x, tid = threadIdx.x;

    {
        int col = tid & 63, ch = tid >> 6;
        const float* hb = g_h + (size_t)b*S*D + (size_t)ch*256*D;
        float sum = 0.f;
#pragma unroll 8
        for (int s = 0; s < 256; s++) sum += hb[s*D + col];
        sp2[tid] = sum;
    }
    __syncthreads();
    if (tid < 64)
        sp[tid] = (sp2[tid] + sp2[tid+64] + sp2[tid+128] + sp2[tid+192]) * (1.0f/(float)S);
    __syncthreads();
    if (tid < 32) {
        float a = bp1[tid];
#pragma unroll
        for (int i = 0; i < 64; i++) a += sp[i] * Wp1[i*32 + tid];
        sh[tid] = fmaxf(a, 0.f);
    }
    __syncthreads();
    if (tid < 8) {
        float a = bp2[tid];
#pragma unroll
        for (int i = 0; i < 32; i++) a += sh[i] * Wp2[i*8 + tid];
        sang[tid] = tanhf(a) * 3.14159265358979f;
    }

    st[tid] = make_float2(tid == 0 ? 1.f : 0.f, 0.f);
    __syncthreads();

    for (int l = 0; l < QL; l++) {
        for (int w = 0; w < NQ; w++) {
            int mask = 1 << (7 - w);
            float c = cosf(0.5f * sang[w]);
            float s = sinf(0.5f * sang[w]);
            if (!(tid & mask)) {
                float2 v0 = st[tid], v1 = st[tid | mask];
                st[tid]        = make_float2(c*v0.x + s*v1.y,  c*v0.y - s*v1.x);
                st[tid | mask] = make_float2(s*v0.y + c*v1.x, -s*v0.x + c*v1.y);
            }
            __syncthreads();
        }
        for (int w = 0; w < NQ; w++) {
            int mask = 1 << (7 - w);
            float phi = qw[(l*NQ + w)*3 + 0];
            float th  = qw[(l*NQ + w)*3 + 1];
            float om  = qw[(l*NQ + w)*3 + 2];
            float ct = cosf(0.5f*th), stt = sinf(0.5f*th);
            float aa = 0.5f*(phi + om), bb = 0.5f*(phi - om);
            float ca = cosf(aa), sa = sinf(aa), cb = cosf(bb), sb = sinf(bb);
            float2 U00 = make_float2( ct*ca, -ct*sa);
            float2 U01 = make_float2(-stt*cb, -stt*sb);
            float2 U10 = make_float2( stt*cb, -stt*sb);
            float2 U11 = make_float2( ct*ca,  ct*sa);
            if (!(tid & mask)) {
                float2 v0 = st[tid], v1 = st[tid | mask];
                st[tid]        = cadd(cmul(U00, v0), cmul(U01, v1));
                st[tid | mask] = cadd(cmul(U10, v0), cmul(U11, v1));
            }
            __syncthreads();
        }
        for (int w = 0; w < NQ; w++) {
            int mc = 1 << (7 - w);
            int mt = 1 << (7 - ((w + 1) & 7));
            if ((tid & mc) && !(tid & mt)) {
                float2 t0 = st[tid];
                st[tid] = st[tid | mt];
                st[tid | mt] = t0;
            }
            __syncthreads();
        }
    }

    float p = st[tid].x*st[tid].x + st[tid].y*st[tid].y;
    for (int w = 0; w < 3; w++) {
        sred[tid] = (tid & (1 << (7 - w))) ? -p : p;
        __syncthreads();
        for (int off = 128; off > 0; off >>= 1) {
            if (tid < off) sred[tid] += sred[tid + off];
            __syncthreads();
        }
        if (tid == 0) out[b*3 + w] = sred[0];
        __syncthreads();
    }

    {
        int r = tid >> 4, c = tid & 15;
        float2 acc = make_float2(0.f, 0.f);
#pragma unroll
        for (int k = 0; k < 16; k++) {
            float2 mr = st[r*16 + k], mcv = st[c*16 + k];
            acc.x += mr.x*mcv.x + mr.y*mcv.y;
            acc.y += mr.y*mcv.x - mr.x*mcv.y;
        }
        rho[tid] = acc;
    }
    __syncthreads();

    if (tid < 128) {
        int g = tid >> 4, k = tid & 15;
        for (int sweep = 0; sweep < 6; sweep++) {
            for (int rnd = 0; rnd < 15; rnd++) {
                int pa, qa_;
                if (g == 0) { pa = 15; qa_ = rnd; }
                else {
                    pa  = (rnd + g) % 15;
                    qa_ = (rnd + 15 - g) % 15;
                }
                int pp = min(pa, qa_), qq = max(pa, qa_);
                if (k == 0) {
                    float2 apq = rho[pp*16 + qq];
                    float b2v = apq.x*apq.x + apq.y*apq.y;
                    if (b2v > 1e-26f) {
                        float app = rho[pp*16 + pp].x;
                        float aqq = rho[qq*16 + qq].x;
                        float bn  = sqrtf(b2v);
                        float tau = (aqq - app) / (2.f * bn);
                        float rt  = sqrtf(1.f + tau*tau);
                        float t   = (tau >= 0.f) ? 1.f/(tau + rt) : -1.f/(-tau + rt);
                        float cc  = rsqrtf(1.f + t*t);
                        jc[g] = cc; js[g] = t*cc;
                        jpx[g] = apq.x/bn; jpy[g] = apq.y/bn;
                    } else {
                        jc[g] = 1.f; js[g] = 0.f; jpx[g] = 1.f; jpy[g] = 0.f;
                    }
                }
                BARS128();
                float cc = jc[g], ss = js[g];
                float2 ph = make_float2(jpx[g], jpy[g]);
                {
                    float2 rp = rho[pp*16 + k], rq = rho[qq*16 + k];
                    float2 prq  = cmul(ph, rq);
                    float2 cprp = cmulcj(ph, rp);
                    rho[pp*16 + k] = make_float2(cc*rp.x - ss*prq.x,  cc*rp.y - ss*prq.y);
                    rho[qq*16 + k] = make_float2(ss*cprp.x + cc*rq.x, ss*cprp.y + cc*rq.y);
                }
                BARS128();
                {
                    float2 cp = rho[k*16 + pp], cq = rho[k*16 + qq];
                    float2 ccq = cmulcj(ph, cq);
                    float2 pcp = cmul(ph, cp);
                    rho[k*16 + pp] = make_float2(cc*cp.x - ss*ccq.x,  cc*cp.y - ss*ccq.y);
                    rho[k*16 + qq] = make_float2(ss*pcp.x + cc*cq.x, ss*pcp.y + cc*cq.y);
                }
                BARS128();
            }
        }
        if (tid == 0) {
            float ent = 0.f;
#pragma unroll
            for (int kk = 0; kk < 16; kk++) {
                float ev = rho[kk*16 + kk].x;
                ev = fminf(fmaxf(ev, 1e-10f), 1.f);
                ent -= ev * logf(ev);
            }
            out[48 + b] = ent;
        }
    }
}

// ---------------- launch ----------------
extern "C" void kernel_launch(void* const* d_in, const int* in_sizes, int n_in,
                              void* d_out, int out_size) {
    const float* x    = (const float*)d_in[0];
    const float* Wemb = (const float*)d_in[1];
    const float* bemb = (const float*)d_in[2];
    const float* Wq   = (const float*)d_in[3];
    const float* bq   = (const float*)d_in[4];
    const float* Wk   = (const float*)d_in[5];
    const float* bk   = (const float*)d_in[6];
    const float* Wv   = (const float*)d_in[7];
    const float* bv   = (const float*)d_in[8];
    const float* Wo   = (const float*)d_in[9];
    const float* bo   = (const float*)d_in[10];
    const float* ln1g = (const float*)d_in[11];
    const float* ln1b = (const float*)d_in[12];
    const float* ln2g = (const float*)d_in[13];
    const float* ln2b = (const float*)d_in[14];
    const float* Wf1  = (const float*)d_in[15];
    const float* bf1  = (const float*)d_in[16];
    const float* Wf2  = (const float*)d_in[17];
    const float* bf2  = (const float*)d_in[18];
    const float* Wp1  = (const float*)d_in[19];
    const float* bp1  = (const float*)d_in[20];
    const float* Wp2  = (const float*)d_in[21];
    const float* bp2  = (const float*)d_in[22];
    const float* qw   = (const float*)d_in[23];
    float* out = (float*)d_out;

    k_pe<<<128, 256>>>();
    k_pack<<<(NL*10240 + 127)/128, 128>>>(Wo, Wf1, Wf2);
    for (int l = 0; l < NL; l++) {
        dim3 qg(256, 3);
        k_qkv_mma<<<qg, 128>>>(Wq, bq, Wk, bk, Wv, bv, x, Wemb, bemb, l);
        dim3 ag(16, B*H);
        k_attn_mma<<<ag, 128>>>();
        k_block_mma<<<512, 64>>>(bo, ln1g, ln1b, bf1, bf2, ln2g, ln2b, l);
    }
    k_pool_quantum<<<B, 256>>>(Wp1, bp1, Wp2, bp2, qw, out);
}

// round 11
// speedup vs baseline: 1.1811x; 1.0298x over previous
#include <cuda_runtime.h>
#include <cuda_fp16.h>
#include <math.h>

#define B   16
#define S   1024
#define NF  5
#define D   64
#define H   8
#define HD  8
#define NL  2
#define FF  128
#define NQ  8
#define QL  3
#define BS  (B*S)
#define CK2  512
#define VPAD2 520

typedef unsigned long long ull;
typedef unsigned int uint;

// ---------------- device scratch ----------------
__device__ float g_h  [BS*D];
__device__ float g_q  [BS*D];
__device__ float g_k  [BS*D];
__device__ float g_v  [BS*D];
__device__ float g_pe [S*D];
__device__ float g_part[(size_t)2*128*S*12];   // 12.6 MB partials
// prepacked half2 weights (B-fragment layout)
__device__ uint g_pWo[NL*32*68];
__device__ uint g_pW1[NL*32*132];
__device__ uint g_pW2[NL*64*68];

// ---------------- mma / f16 helpers ----------------
__device__ __forceinline__ void mma16n8k8_f16(uint& d0, uint& d1, uint a0, uint a1, uint b0) {
    asm volatile("mma.sync.aligned.m16n8k8.row.col.f16.f16.f16.f16 "
        "{%0,%1}, {%2,%3}, {%4}, {%5,%6};"
        : "=r"(d0), "=r"(d1)
        : "r"(a0), "r"(a1), "r"(b0), "r"(0u), "r"(0u));
}
__device__ __forceinline__ void mma16n8k16(float* d,
                                           uint a0, uint a1, uint a2, uint a3,
                                           uint b0, uint b1) {
    asm volatile("mma.sync.aligned.m16n8k16.row.col.f32.f16.f16.f32 "
        "{%0,%1,%2,%3}, {%4,%5,%6,%7}, {%8,%9}, {%0,%1,%2,%3};"
        : "+f"(d[0]), "+f"(d[1]), "+f"(d[2]), "+f"(d[3])
        : "r"(a0), "r"(a1), "r"(a2), "r"(a3), "r"(b0), "r"(b1));
}
__device__ __forceinline__ uint cvt_f16x2(float hi, float lo) {
    uint r; asm("cvt.rn.f16x2.f32 %0, %1, %2;" : "=r"(r) : "f"(hi), "f"(lo)); return r;
}
__device__ __forceinline__ uint hex2x2(uint x) {
    uint r; asm("ex2.approx.f16x2 %0, %1;" : "=r"(r) : "r"(x)); return r;
}

// ---------------- complex helpers ----------------
__device__ __forceinline__ float2 cmul(float2 a, float2 b) {
    return make_float2(a.x*b.x - a.y*b.y, a.x*b.y + a.y*b.x);
}
__device__ __forceinline__ float2 cmulcj(float2 a, float2 b) {
    return make_float2(a.x*b.x + a.y*b.y, a.x*b.y - a.y*b.x);
}
__device__ __forceinline__ float2 cadd(float2 a, float2 b) {
    return make_float2(a.x + b.x, a.y + b.y);
}

// ---------------- 0a) positional-encoding table ----------------
__global__ void k_pe() {
    int idx = blockIdx.x * blockDim.x + threadIdx.x;
    int s = idx >> 5, p = idx & 31;
    float div = __expf(-0.14391156831212787f * (float)(2*p));
    float sn, cs;
    sincosf((float)s * div, &sn, &cs);
    g_pe[s*64 + 2*p]     = sn;
    g_pe[s*64 + 2*p + 1] = cs;
}

// ---------------- 0b) weight prepack ----------------
__global__ void k_pack(const float* __restrict__ Wo,
                       const float* __restrict__ Wf1,
                       const float* __restrict__ Wf2) {
    int idx = blockIdx.x * blockDim.x + threadIdx.x;
    int l = idx / 10240;
    int r = idx % 10240;
    if (r < 2048) {
        int ip = r >> 6, n = r & 63;
        const float* W = Wo + l*4096;
        g_pWo[l*2176 + ip*68 + n] = cvt_f16x2(W[(2*ip+1)*64 + n], W[(2*ip)*64 + n]);
    } else if (r < 6144) {
        int q = r - 2048;
        int ip = q >> 7, n = q & 127;
        const float* W = Wf1 + l*8192;
        g_pW1[l*4224 + ip*132 + n] = cvt_f16x2(W[(2*ip+1)*128 + n], W[(2*ip)*128 + n]);
    } else {
        int q = r - 6144;
        int ip = q >> 6, n = q & 63;
        const float* W = Wf2 + l*8192;
        g_pW2[l*4352 + ip*68 + n] = cvt_f16x2(W[(2*ip+1)*64 + n], W[(2*ip)*64 + n]);
    }
}

// ======== MMA GEMM common fragment loaders ========
__device__ __forceinline__ void load_afrag64(uint (&a)[4][4], const uint* sA, int rbase, int gid, int tig) {
    const uint* r0 = sA + (rbase + gid)*36;
    const uint* r1 = sA + (rbase + gid + 8)*36;
#pragma unroll
    for (int kk = 0; kk < 4; kk++) {
        a[kk][0] = r0[kk*8 + tig];
        a[kk][1] = r1[kk*8 + tig];
        a[kk][2] = r0[kk*8 + 4 + tig];
        a[kk][3] = r1[kk*8 + 4 + tig];
    }
}

// ---------------- 1) QKV projection via mma ----------------
__global__ void __launch_bounds__(128) k_qkv_mma(
        const float* __restrict__ Wq, const float* __restrict__ bq,
        const float* __restrict__ Wk, const float* __restrict__ bk,
        const float* __restrict__ Wv, const float* __restrict__ bv,
        const float* __restrict__ x,  const float* __restrict__ Wemb,
        const float* __restrict__ bemb, int l) {
    __shared__ uint  sA [64*36];
    __shared__ uint  sWp[32*68];
    __shared__ float sX [64*NF];
    int tid = threadIdx.x;
    int row0 = blockIdx.x * 64;
    int m = blockIdx.y;
    const float* W    = (m == 0) ? (Wq + l*4096) : (m == 1) ? (Wk + l*4096) : (Wv + l*4096);
    const float* bias = (m == 0) ? (bq + l*D)    : (m == 1) ? (bk + l*D)    : (bv + l*D);
    float* out        = (m == 0) ? g_q : (m == 1) ? g_k : g_v;

    if (l == 0) {
        for (int idx = tid; idx < 64*NF; idx += 128)
            sX[idx] = x[(size_t)(row0 + idx/NF)*NF + idx%NF];
        __syncthreads();
        for (int idx = tid; idx < 2048; idx += 128) {
            int r = idx >> 5, c2 = idx & 31;
            int row = row0 + r;
            int s = row & (S-1);
            int c = c2*2;
            float v0 = bemb[c]   + g_pe[s*64 + c];
            float v1 = bemb[c+1] + g_pe[s*64 + c + 1];
            const float* xr = sX + r*NF;
#pragma unroll
            for (int f = 0; f < NF; f++) {
                v0 += xr[f] * Wemb[f*D + c];
                v1 += xr[f] * Wemb[f*D + c + 1];
            }
            sA[r*36 + c2] = cvt_f16x2(v1, v0);
            if (m == 0) *(float2*)(g_h + (size_t)row*D + c) = make_float2(v0, v1);
        }
    } else {
        for (int idx = tid; idx < 2048; idx += 128) {
            int r = idx >> 5, c2 = idx & 31;
            float2 v = *(const float2*)(g_h + (size_t)(row0 + r)*D + c2*2);
            sA[r*36 + c2] = cvt_f16x2(v.y, v.x);
        }
    }
    for (int idx = tid; idx < 2048; idx += 128) {
        int ip = idx >> 6, n = idx & 63;
        sWp[ip*68 + n] = cvt_f16x2(W[(2*ip+1)*64 + n], W[(2*ip)*64 + n]);
    }
    __syncthreads();

    int warp = tid >> 5, lane = tid & 31;
    int gid = lane >> 2, tig = lane & 3;
    uint a[4][4];
    load_afrag64(a, sA, warp*16, gid, tig);

#pragma unroll
    for (int t = 0; t < 8; t++) {
        float acc[4] = {0,0,0,0};
#pragma unroll
        for (int kk = 0; kk < 4; kk++) {
            uint b0 = sWp[(kk*8 + tig)*68 + t*8 + gid];
            uint b1 = sWp[(kk*8 + 4 + tig)*68 + t*8 + gid];
            mma16n8k16(acc, a[kk][0], a[kk][1], a[kk][2], a[kk][3], b0, b1);
        }
        float2 bv2 = *(const float2*)(bias + t*8 + tig*2);
        int r = row0 + warp*16 + gid;
        *(float2*)(out + (size_t)r*D + t*8 + tig*2) =
            make_float2(acc[0] + bv2.x, acc[1] + bv2.y);
        *(float2*)(out + (size_t)(r + 8)*D + t*8 + tig*2) =
            make_float2(acc[2] + bv2.x, acc[3] + bv2.y);
    }
}

// ---------------- 2) split-K attention: split accumulator chains (E/O) ----------------
__global__ void __launch_bounds__(128) k_attn_mma() {
    __shared__ __half sK [CK2*8];
    __shared__ __half sVT[8*VPAD2];
    int tid = threadIdx.x;
    int bh  = blockIdx.y;
    int b   = bh >> 3, hh = bh & 7;
    int qt  = blockIdx.x >> 1;
    int ck  = blockIdx.x & 1;
    int k0  = ck * CK2;
    const float* kbase = g_k + (size_t)(b*S + k0)*D + hh*HD;
    const float* vbase = g_v + (size_t)(b*S + k0)*D + hh*HD;
    const float pre = 0.35355339059327373f * 1.4426950408889634f;
    for (int i = tid; i < CK2*8; i += 128) {
        int key = i >> 3, d = i & 7;
        sK[i]             = __float2half(kbase[key*D + d] * pre);
        sVT[d*VPAD2 + key] = __float2half(vbase[key*D + d]);
    }
    __syncthreads();

    int warp = tid >> 5, lane = tid & 31;
    int gid  = lane >> 2, tig = lane & 3;
    int q0   = qt * 128 + warp * 32;

    uint qa[2][2];
#pragma unroll
    for (int t2 = 0; t2 < 2; t2++) {
#pragma unroll
        for (int hf = 0; hf < 2; hf++) {
            int qrow = q0 + t2*16 + gid + hf*8;
            float2 qv = *(const float2*)(g_q + (size_t)(b*S + qrow)*D + hh*HD + tig*2);
            qa[t2][hf] = cvt_f16x2(qv.y, qv.x);
        }
    }

    // E/O split accumulator chains (8 independent chains)
    float acc0E[4] = {0,0,0,0}, acc0O[4] = {0,0,0,0};
    float acc1E[4] = {0,0,0,0}, acc1O[4] = {0,0,0,0};
    float lac0E[4] = {0,0,0,0}, lac0O[4] = {0,0,0,0};
    float lac1E[4] = {0,0,0,0}, lac1O[4] = {0,0,0,0};
    const uint ones2 = 0x3C003C00u;
    const __half* kptr = sK  + gid*8 + tig*2;
    const __half* vptr = sVT + gid*VPAD2 + tig*2;

    for (int j0 = 0; j0 < CK2; j0 += 32) {
        uint kb0 = *(const uint*)(kptr + j0*8);
        uint kb1 = *(const uint*)(kptr + j0*8 + 64);
        uint kb2 = *(const uint*)(kptr + j0*8 + 128);
        uint kb3 = *(const uint*)(kptr + j0*8 + 192);
        uint vb0 = *(const uint*)(vptr + j0);
        uint vb1 = *(const uint*)(vptr + j0 + 8);
        uint vb2 = *(const uint*)(vptr + j0 + 16);
        uint vb3 = *(const uint*)(vptr + j0 + 24);
        // tile0, even half (keys j0..j0+15)
        {
            uint s01a, s23a, s01b, s23b;
            mma16n8k8_f16(s01a, s23a, qa[0][0], qa[0][1], kb0);
            mma16n8k8_f16(s01b, s23b, qa[0][0], qa[0][1], kb1);
            uint p0 = hex2x2(s01a), p1 = hex2x2(s23a);
            uint p2 = hex2x2(s01b), p3 = hex2x2(s23b);
            mma16n8k16(acc0E, p0, p1, p2, p3, vb0, vb1);
            mma16n8k16(lac0E, p0, p1, p2, p3, ones2, ones2);
        }
        // tile1, even half
        {
            uint s01a, s23a, s01b, s23b;
            mma16n8k8_f16(s01a, s23a, qa[1][0], qa[1][1], kb0);
            mma16n8k8_f16(s01b, s23b, qa[1][0], qa[1][1], kb1);
            uint p0 = hex2x2(s01a), p1 = hex2x2(s23a);
            uint p2 = hex2x2(s01b), p3 = hex2x2(s23b);
            mma16n8k16(acc1E, p0, p1, p2, p3, vb0, vb1);
            mma16n8k16(lac1E, p0, p1, p2, p3, ones2, ones2);
        }
        // tile0, odd half (keys j0+16..j0+31)
        {
            uint s01a, s23a, s01b, s23b;
            mma16n8k8_f16(s01a, s23a, qa[0][0], qa[0][1], kb2);
            mma16n8k8_f16(s01b, s23b, qa[0][0], qa[0][1], kb3);
            uint p0 = hex2x2(s01a), p1 = hex2x2(s23a);
            uint p2 = hex2x2(s01b), p3 = hex2x2(s23b);
            mma16n8k16(acc0O, p0, p1, p2, p3, vb2, vb3);
            mma16n8k16(lac0O, p0, p1, p2, p3, ones2, ones2);
        }
        // tile1, odd half
        {
            uint s01a, s23a, s01b, s23b;
            mma16n8k8_f16(s01a, s23a, qa[1][0], qa[1][1], kb2);
            mma16n8k8_f16(s01b, s23b, qa[1][0], qa[1][1], kb3);
            uint p0 = hex2x2(s01a), p1 = hex2x2(s23a);
            uint p2 = hex2x2(s01b), p3 = hex2x2(s23b);
            mma16n8k16(acc1O, p0, p1, p2, p3, vb2, vb3);
            mma16n8k16(lac1O, p0, p1, p2, p3, ones2, ones2);
        }
    }

    // merge E/O chains
    float acc0[4], acc1[4], lac0[4], lac1[4];
#pragma unroll
    for (int i = 0; i < 4; i++) {
        acc0[i] = acc0E[i] + acc0O[i];
        acc1[i] = acc1E[i] + acc1O[i];
        lac0[i] = lac0E[i] + lac0O[i];
        lac1[i] = lac1E[i] + lac1O[i];
    }

    size_t base = ((size_t)ck*128 + bh)*S;
    {
        float* pp = g_part + (base + q0 + gid)*12;
        *(float2*)(pp + tig*2) = make_float2(acc0[0], acc0[1]);
        if (tig == 0) pp[8] = lac0[0];
        pp = g_part + (base + q0 + gid + 8)*12;
        *(float2*)(pp + tig*2) = make_float2(acc0[2], acc0[3]);
        if (tig == 0) pp[8] = lac0[2];
        pp = g_part + (base + q0 + 16 + gid)*12;
        *(float2*)(pp + tig*2) = make_float2(acc1[0], acc1[1]);
        if (tig == 0) pp[8] = lac1[0];
        pp = g_part + (base + q0 + 24 + gid)*12;
        *(float2*)(pp + tig*2) = make_float2(acc1[2], acc1[3]);
        if (tig == 0) pp[8] = lac1[2];
    }
}

// ---------------- 3) FUSED block: combine + oproj + LN1 + FFN + LN2 ----------------
__global__ void __launch_bounds__(64) k_block_mma(
        const float* __restrict__ bo,
        const float* __restrict__ g1, const float* __restrict__ b1,
        const float* __restrict__ bf1, const float* __restrict__ bf2,
        const float* __restrict__ g2, const float* __restrict__ b2, int l) {
    __shared__ uint sA[32*36];
    int tid = threadIdx.x;
    int row0 = blockIdx.x * 32;
    const uint* pWo = g_pWo + l*2176;
    const uint* pW1 = g_pW1 + l*4224;
    const uint* pW2 = g_pW2 + l*4352;

    for (int idx = tid; idx < 1024; idx += 64) {
        int r = idx >> 5, c2 = idx & 31;
        int grow = row0 + r;
        int q  = grow & (S-1);
        int bb = grow >> 10;
        int hh = c2 >> 2;
        int bh = bb*8 + hh;
        int off = (c2 & 3)*2;
        const float* p0 = g_part + ((size_t)(0*128 + bh)*S + q)*12;
        const float* p1 = g_part + ((size_t)(1*128 + bh)*S + q)*12;
        float inv = 1.0f / (p0[8] + p1[8]);
        float a0 = (p0[off]   + p1[off])   * inv;
        float a1 = (p0[off+1] + p1[off+1]) * inv;
        sA[r*36 + c2] = cvt_f16x2(a1, a0);
    }
    __syncthreads();

    int warp = tid >> 5, lane = tid & 31;
    int gid = lane >> 2, tig = lane & 3;
    int rA = row0 + warp*16 + gid;
    int rB = rA + 8;

    uint a[4][4];
    load_afrag64(a, sA, warp*16, gid, tig);
    float acc[8][4];
#pragma unroll
    for (int t = 0; t < 8; t++) {
        acc[t][0]=0; acc[t][1]=0; acc[t][2]=0; acc[t][3]=0;
#pragma unroll
        for (int kk = 0; kk < 4; kk++) {
            uint b0 = pWo[(kk*8 + tig)*68 + t*8 + gid];
            uint b1 = pWo[(kk*8 + 4 + tig)*68 + t*8 + gid];
            mma16n8k16(acc[t], a[kk][0], a[kk][1], a[kk][2], a[kk][3], b0, b1);
        }
    }
    float vA[16], vB[16];
    {
        float sumA=0, sqA=0, sumB=0, sqB=0;
#pragma unroll
        for (int t = 0; t < 8; t++) {
            float2 bo2 = *(const float2*)(bo + l*D + t*8 + tig*2);
            float2 hA = *(const float2*)(g_h + (size_t)rA*D + t*8 + tig*2);
            float2 hB = *(const float2*)(g_h + (size_t)rB*D + t*8 + tig*2);
            float a0 = acc[t][0] + bo2.x + hA.x;
            float a1 = acc[t][1] + bo2.y + hA.y;
            float b0 = acc[t][2] + bo2.x + hB.x;
            float b1 = acc[t][3] + bo2.y + hB.y;
            vA[t*2]=a0; vA[t*2+1]=a1; vB[t*2]=b0; vB[t*2+1]=b1;
            sumA += a0+a1; sqA += a0*a0+a1*a1;
            sumB += b0+b1; sqB += b0*b0+b1*b1;
        }
#pragma unroll
        for (int o = 1; o < 4; o <<= 1) {
            sumA += __shfl_xor_sync(0xffffffffu, sumA, o);
            sqA  += __shfl_xor_sync(0xffffffffu, sqA,  o);
            sumB += __shfl_xor_sync(0xffffffffu, sumB, o);
            sqB  += __shfl_xor_sync(0xffffffffu, sqB,  o);
        }
        float mA = sumA*(1.f/64.f), vrA = sqA*(1.f/64.f) - mA*mA;
        float mB = sumB*(1.f/64.f), vrB = sqB*(1.f/64.f) - mB*mB;
        float rsA = rsqrtf(vrA + 1e-5f), rsB = rsqrtf(vrB + 1e-5f);
#pragma unroll
        for (int t = 0; t < 8; t++) {
            float2 gg = *(const float2*)(g1 + l*D + t*8 + tig*2);
            float2 bb = *(const float2*)(b1 + l*D + t*8 + tig*2);
            vA[t*2]   = (vA[t*2]  -mA)*rsA*gg.x + bb.x;
            vA[t*2+1] = (vA[t*2+1]-mA)*rsA*gg.y + bb.y;
            vB[t*2]   = (vB[t*2]  -mB)*rsB*gg.x + bb.x;
            vB[t*2+1] = (vB[t*2+1]-mB)*rsB*gg.y + bb.y;
        }
    }
    __syncthreads();
#pragma unroll
    for (int t = 0; t < 8; t++) {
        sA[(warp*16 + gid)*36     + t*4 + tig] = cvt_f16x2(vA[t*2+1], vA[t*2]);
        sA[(warp*16 + gid + 8)*36 + t*4 + tig] = cvt_f16x2(vB[t*2+1], vB[t*2]);
    }
    __syncthreads();

    uint a2[4][4];
    load_afrag64(a2, sA, warp*16, gid, tig);
    uint hA[16][2];
#pragma unroll
    for (int t = 0; t < 16; t++) {
        float facc[4] = {0,0,0,0};
#pragma unroll
        for (int kk = 0; kk < 4; kk++) {
            uint b0 = pW1[(kk*8 + tig)*132 + t*8 + gid];
            uint b1 = pW1[(kk*8 + 4 + tig)*132 + t*8 + gid];
            mma16n8k16(facc, a2[kk][0], a2[kk][1], a2[kk][2], a2[kk][3], b0, b1);
        }
        float2 bf = *(const float2*)(bf1 + l*FF + t*8 + tig*2);
        float c0 = fmaxf(facc[0] + bf.x, 0.f);
        float c1 = fmaxf(facc[1] + bf.y, 0.f);
        float c2 = fmaxf(facc[2] + bf.x, 0.f);
        float c3 = fmaxf(facc[3] + bf.y, 0.f);
        hA[t][0] = cvt_f16x2(c1, c0);
        hA[t][1] = cvt_f16x2(c3, c2);
    }

#pragma unroll
    for (int t = 0; t < 8; t++) {
        acc[t][0]=0; acc[t][1]=0; acc[t][2]=0; acc[t][3]=0;
#pragma unroll
        for (int kk = 0; kk < 8; kk++) {
            uint b0 = pW2[(kk*8 + tig)*68 + t*8 + gid];
            uint b1 = pW2[(kk*8 + 4 + tig)*68 + t*8 + gid];
            mma16n8k16(acc[t], hA[2*kk][0], hA[2*kk][1], hA[2*kk+1][0], hA[2*kk+1][1], b0, b1);
        }
    }
    {
        float sumA=0, sqA=0, sumB=0, sqB=0;
        float wA[16], wB[16];
#pragma unroll
        for (int t = 0; t < 8; t++) {
            float2 bo2 = *(const float2*)(bf2 + l*D + t*8 + tig*2);
            float a0 = acc[t][0] + bo2.x + vA[t*2];
            float a1 = acc[t][1] + bo2.y + vA[t*2+1];
            float b0 = acc[t][2] + bo2.x + vB[t*2];
            float b1 = acc[t][3] + bo2.y + vB[t*2+1];
            wA[t*2]=a0; wA[t*2+1]=a1; wB[t*2]=b0; wB[t*2+1]=b1;
            sumA += a0+a1; sqA += a0*a0+a1*a1;
            sumB += b0+b1; sqB += b0*b0+b1*b1;
        }
#pragma unroll
        for (int o = 1; o < 4; o <<= 1) {
            sumA += __shfl_xor_sync(0xffffffffu, sumA, o);
            sqA  += __shfl_xor_sync(0xffffffffu, sqA,  o);
            sumB += __shfl_xor_sync(0xffffffffu, sumB, o);
            sqB  += __shfl_xor_sync(0xffffffffu, sqB,  o);
        }
        float mA = sumA*(1.f/64.f), vrA = sqA*(1.f/64.f) - mA*mA;
        float mB = sumB*(1.f/64.f), vrB = sqB*(1.f/64.f) - mB*mB;
        float rsA = rsqrtf(vrA + 1e-5f), rsB = rsqrtf(vrB + 1e-5f);
#pragma unroll
        for (int t = 0; t < 8; t++) {
            float2 gg = *(const float2*)(g2 + l*D + t*8 + tig*2);
            float2 bb = *(const float2*)(b2 + l*D + t*8 + tig*2);
            *(float2*)(g_h + (size_t)rA*D + t*8 + tig*2) =
                make_float2((wA[t*2]-mA)*rsA*gg.x + bb.x, (wA[t*2+1]-mA)*rsA*gg.y + bb.y);
            *(float2*)(g_h + (size_t)rB*D + t*8 + tig*2) =
                make_float2((wB[t*2]-mB)*rsB*gg.x + bb.x, (wB[t*2+1]-mB)*rsB*gg.y + bb.y);
        }
    }
}

// ---------------- 4) pool + MLP + quantum circuit + <Z> + entropy ----------------
#define BARS128() asm volatile("bar.sync 1, 128;" ::: "memory")

__global__ void k_pool_quantum(const float* __restrict__ Wp1, const float* __restrict__ bp1,
                               const float* __restrict__ Wp2, const float* __restrict__ bp2,
                               const float* __restrict__ qw, float* __restrict__ out) {
    __shared__ float sp2[256];
    __shared__ float sp[64];
    __shared__ float sh[32];
    __shared__ float sang[8];
    __shared__ float2 st[256];
    __shared__ float2 rho[256];
    __shared__ float  sred[256];
    __shared__ float  jc[8], js[8], jpx[8], jpy[8];
    int b = blockIdx.x, tid = threadIdx.x;

    {
        int col = tid & 63, ch = tid >> 6;
        const float* hb = g_h + (size_t)b*S*D + (size_t)ch*256*D;
        float sum = 0.f;
#pragma unroll 8
        for (int s = 0; s < 256; s++) sum += hb[s*D + col];
        sp2[tid] = sum;
    }
    __syncthreads();
    if (tid < 64)
        sp[tid] = (sp2[tid] + sp2[tid+64] + sp2[tid+128] + sp2[tid+192]) * (1.0f/(float)S);
    __syncthreads();
    if (tid < 32) {
        float a = bp1[tid];
#pragma unroll
        for (int i = 0; i < 64; i++) a += sp[i] * Wp1[i*32 + tid];
        sh[tid] = fmaxf(a, 0.f);
    }
    __syncthreads();
    if (tid < 8) {
        float a = bp2[tid];
#pragma unroll
        for (int i = 0; i < 32; i++) a += sh[i] * Wp2[i*8 + tid];
        sang[tid] = tanhf(a) * 3.14159265358979f;
    }

    st[tid] = make_float2(tid == 0 ? 1.f : 0.f, 0.f);
    __syncthreads();

    for (int l = 0; l < QL; l++) {
        for (int w = 0; w < NQ; w++) {
            int mask = 1 << (7 - w);
            float c = cosf(0.5f * sang[w]);
            float s = sinf(0.5f * sang[w]);
            if (!(tid & mask)) {
                float2 v0 = st[tid], v1 = st[tid | mask];
                st[tid]        = make_float2(c*v0.x + s*v1.y,  c*v0.y - s*v1.x);
                st[tid | mask] = make_float2(s*v0.y + c*v1.x, -s*v0.x + c*v1.y);
            }
            __syncthreads();
        }
        for (int w = 0; w < NQ; w++) {
            int mask = 1 << (7 - w);
            float phi = qw[(l*NQ + w)*3 + 0];
            float th  = qw[(l*NQ + w)*3 + 1];
            float om  = qw[(l*NQ + w)*3 + 2];
            float ct = cosf(0.5f*th), stt = sinf(0.5f*th);
            float aa = 0.5f*(phi + om), bb = 0.5f*(phi - om);
            float ca = cosf(aa), sa = sinf(aa), cb = cosf(bb), sb = sinf(bb);
            float2 U00 = make_float2( ct*ca, -ct*sa);
            float2 U01 = make_float2(-stt*cb, -stt*sb);
            float2 U10 = make_float2( stt*cb, -stt*sb);
            float2 U11 = make_float2( ct*ca,  ct*sa);
            if (!(tid & mask)) {
                float2 v0 = st[tid], v1 = st[tid | mask];
                st[tid]        = cadd(cmul(U00, v0), cmul(U01, v1));
                st[tid | mask] = cadd(cmul(U10, v0), cmul(U11, v1));
            }
            __syncthreads();
        }
        for (int w = 0; w < NQ; w++) {
            int mc = 1 << (7 - w);
            int mt = 1 << (7 - ((w + 1) & 7));
            if ((tid & mc) && !(tid & mt)) {
                float2 t0 = st[tid];
                st[tid] = st[tid | mt];
                st[tid | mt] = t0;
            }
            __syncthreads();
        }
    }

    float p = st[tid].x*st[tid].x + st[tid].y*st[tid].y;
    for (int w = 0; w < 3; w++) {
        sred[tid] = (tid & (1 << (7 - w))) ? -p : p;
        __syncthreads();
        for (int off = 128; off > 0; off >>= 1) {
            if (tid < off) sred[tid] += sred[tid + off];
            __syncthreads();
        }
        if (tid == 0) out[b*3 + w] = sred[0];
        __syncthreads();
    }

    {
        int r = tid >> 4, c = tid & 15;
        float2 acc = make_float2(0.f, 0.f);
#pragma unroll
        for (int k = 0; k < 16; k++) {
            float2 mr = st[r*16 + k], mcv = st[c*16 + k];
            acc.x += mr.x*mcv.x + mr.y*mcv.y;
            acc.y += mr.y*mcv.x - mr.x*mcv.y;
        }
        rho[tid] = acc;
    }
    __syncthreads();

    if (tid < 128) {
        int g = tid >> 4, k = tid & 15;
        for (int sweep = 0; sweep < 6; sweep++) {
            for (int rnd = 0; rnd < 15; rnd++) {
                int pa, qa_;
                if (g == 0) { pa = 15; qa_ = rnd; }
                else {
                    pa  = (rnd + g) % 15;
                    qa_ = (rnd + 15 - g) % 15;
                }
                int pp = min(pa, qa_), qq = max(pa, qa_);
                if (k == 0) {
                    float2 apq = rho[pp*16 + qq];
                    float b2v = apq.x*apq.x + apq.y*apq.y;
                    if (b2v > 1e-26f) {
                        float app = rho[pp*16 + pp].x;
                        float aqq = rho[qq*16 + qq].x;
                        float bn  = sqrtf(b2v);
                        float tau = (aqq - app) / (2.f * bn);
                        float rt  = sqrtf(1.f + tau*tau);
                        float t   = (tau >= 0.f) ? 1.f/(tau + rt) : -1.f/(-tau + rt);
                        float cc  = rsqrtf(1.f + t*t);
                        jc[g] = cc; js[g] = t*cc;
                        jpx[g] = apq.x/bn; jpy[g] = apq.y/bn;
                    } else {
                        jc[g] = 1.f; js[g] = 0.f; jpx[g] = 1.f; jpy[g] = 0.f;
                    }
                }
                BARS128();
                float cc = jc[g], ss = js[g];
                float2 ph = make_float2(jpx[g], jpy[g]);
                {
                    float2 rp = rho[pp*16 + k], rq = rho[qq*16 + k];
                    float2 prq  = cmul(ph, rq);
                    float2 cprp = cmulcj(ph, rp);
                    rho[pp*16 + k] = make_float2(cc*rp.x - ss*prq.x,  cc*rp.y - ss*prq.y);
                    rho[qq*16 + k] = make_float2(ss*cprp.x + cc*rq.x, ss*cprp.y + cc*rq.y);
                }
                BARS128();
                {
                    float2 cp = rho[k*16 + pp], cq = rho[k*16 + qq];
                    float2 ccq = cmulcj(ph, cq);
                    float2 pcp = cmul(ph, cp);
                    rho[k*16 + pp] = make_float2(cc*cp.x - ss*ccq.x,  cc*cp.y - ss*ccq.y);
                    rho[k*16 + qq] = make_float2(ss*pcp.x + cc*cq.x, ss*pcp.y + cc*cq.y);
                }
                BARS128();
            }
        }
        if (tid == 0) {
            float ent = 0.f;
#pragma unroll
            for (int kk = 0; kk < 16; kk++) {
                float ev = rho[kk*16 + kk].x;
                ev = fminf(fmaxf(ev, 1e-10f), 1.f);
                ent -= ev * logf(ev);
            }
            out[48 + b] = ent;
        }
    }
}

// ---------------- launch ----------------
extern "C" void kernel_launch(void* const* d_in, const int* in_sizes, int n_in,
                              void* d_out, int out_size) {
    const float* x    = (const float*)d_in[0];
    const float* Wemb = (const float*)d_in[1];
    const float* bemb = (const float*)d_in[2];
    const float* Wq   = (const float*)d_in[3];
    const float* bq   = (const float*)d_in[4];
    const float* Wk   = (const float*)d_in[5];
    const float* bk   = (const float*)d_in[6];
    const float* Wv   = (const float*)d_in[7];
    const float* bv   = (const float*)d_in[8];
    const float* Wo   = (const float*)d_in[9];
    const float* bo   = (const float*)d_in[10];
    const float* ln1g = (const float*)d_in[11];
    const float* ln1b = (const float*)d_in[12];
    const float* ln2g = (const float*)d_in[13];
    const float* ln2b = (const float*)d_in[14];
    const float* Wf1  = (const float*)d_in[15];
    const float* bf1  = (const float*)d_in[16];
    const float* Wf2  = (const float*)d_in[17];
    const float* bf2  = (const float*)d_in[18];
    const float* Wp1  = (const float*)d_in[19];
    const float* bp1  = (const float*)d_in[20];
    const float* Wp2  = (const float*)d_in[21];
    const float* bp2  = (const float*)d_in[22];
    const float* qw   = (const float*)d_in[23];
    float* out = (float*)d_out;

    k_pe<<<128, 256>>>();
    k_pack<<<(NL*10240 + 127)/128, 128>>>(Wo, Wf1, Wf2);
    for (int l = 0; l < NL; l++) {
        dim3 qg(256, 3);
        k_qkv_mma<<<qg, 128>>>(Wq, bq, Wk, bk, Wv, bv, x, Wemb, bemb, l);
        dim3 ag(16, B*H);
        k_attn_mma<<<ag, 128>>>();
        k_block_mma<<<512, 64>>>(bo, ln1g, ln1b, bf1, bf2, ln2g, ln2b, l);
    }
    k_pool_quantum<<<B, 256>>>(Wp1, bp1, Wp2, bp2, qw, out);
}

// round 12
// speedup vs baseline: 1.2068x; 1.0217x over previous
#include <cuda_runtime.h>
#include <cuda_fp16.h>
#include <math.h>

#define B   16
#define S   1024
#define NF  5
#define D   64
#define H   8
#define HD  8
#define NL  2
#define FF  128
#define NQ  8
#define QL  3
#define BS  (B*S)
#define CK2  512
#define VPAD2 520

typedef unsigned long long ull;
typedef unsigned int uint;

// ---------------- device scratch ----------------
__device__ float g_h  [BS*D];
__device__ float g_q  [BS*D];
__device__ float g_k  [BS*D];
__device__ float g_v  [BS*D];
__device__ float g_pe [S*D];
__device__ float g_part[(size_t)2*128*S*12];   // 12.6 MB partials
__device__ float g_poolp[B*4*D];               // pool partials
// prepacked half2 weights (B-fragment layout)
__device__ uint g_pWq[NL*32*68];
__device__ uint g_pWk[NL*32*68];
__device__ uint g_pWv[NL*32*68];
__device__ uint g_pWo[NL*32*68];
__device__ uint g_pW1[NL*32*132];
__device__ uint g_pW2[NL*64*68];

// ---------------- mma / f16 helpers ----------------
__device__ __forceinline__ void mma16n8k8_f16(uint& d0, uint& d1, uint a0, uint a1, uint b0) {
    asm volatile("mma.sync.aligned.m16n8k8.row.col.f16.f16.f16.f16 "
        "{%0,%1}, {%2,%3}, {%4}, {%5,%6};"
        : "=r"(d0), "=r"(d1)
        : "r"(a0), "r"(a1), "r"(b0), "r"(0u), "r"(0u));
}
__device__ __forceinline__ void mma16n8k16(float* d,
                                           uint a0, uint a1, uint a2, uint a3,
                                           uint b0, uint b1) {
    asm volatile("mma.sync.aligned.m16n8k16.row.col.f32.f16.f16.f32 "
        "{%0,%1,%2,%3}, {%4,%5,%6,%7}, {%8,%9}, {%0,%1,%2,%3};"
        : "+f"(d[0]), "+f"(d[1]), "+f"(d[2]), "+f"(d[3])
        : "r"(a0), "r"(a1), "r"(a2), "r"(a3), "r"(b0), "r"(b1));
}
__device__ __forceinline__ uint cvt_f16x2(float hi, float lo) {
    uint r; asm("cvt.rn.f16x2.f32 %0, %1, %2;" : "=r"(r) : "f"(hi), "f"(lo)); return r;
}
__device__ __forceinline__ uint hex2x2(uint x) {
    uint r; asm("ex2.approx.f16x2 %0, %1;" : "=r"(r) : "r"(x)); return r;
}

// ---------------- complex helpers ----------------
__device__ __forceinline__ float2 cmul(float2 a, float2 b) {
    return make_float2(a.x*b.x - a.y*b.y, a.x*b.y + a.y*b.x);
}
__device__ __forceinline__ float2 cmulcj(float2 a, float2 b) {
    return make_float2(a.x*b.x + a.y*b.y, a.x*b.y - a.y*b.x);
}
__device__ __forceinline__ float2 cadd(float2 a, float2 b) {
    return make_float2(a.x + b.x, a.y + b.y);
}

// ---------------- 0) init: pe table (blocks 0..127) + weight prepack (blocks 128..255) ----
__global__ void k_init(const float* __restrict__ Wq, const float* __restrict__ Wk,
                       const float* __restrict__ Wv, const float* __restrict__ Wo,
                       const float* __restrict__ Wf1, const float* __restrict__ Wf2) {
    int bidx = blockIdx.x;
    int tid = threadIdx.x;
    if (bidx < 128) {
        int idx = bidx * 256 + tid;            // < 32768
        int s = idx >> 5, p = idx & 31;
        float div = __expf(-0.14391156831212787f * (float)(2*p));
        float sn, cs;
        sincosf((float)s * div, &sn, &cs);
        g_pe[s*64 + 2*p]     = sn;
        g_pe[s*64 + 2*p + 1] = cs;
    } else {
        int idx = (bidx - 128) * 256 + tid;    // < NL*16384
        int l = idx / 16384;
        int r = idx % 16384;
        if (r < 8192) {                        // Wq/Wk/Wv/Wo: 4 x (32 ip x 64 n)
            int m = r >> 11;
            int q = r & 2047;
            int ip = q >> 6, n = q & 63;
            const float* W = (m == 0) ? (Wq + l*4096) : (m == 1) ? (Wk + l*4096)
                           : (m == 2) ? (Wv + l*4096) : (Wo + l*4096);
            uint* dst = (m == 0) ? g_pWq : (m == 1) ? g_pWk : (m == 2) ? g_pWv : g_pWo;
            dst[l*2176 + ip*68 + n] = cvt_f16x2(W[(2*ip+1)*64 + n], W[(2*ip)*64 + n]);
        } else if (r < 12288) {                // W1: 32 ip x 128 n
            int q = r - 8192;
            int ip = q >> 7, n = q & 127;
            const float* W = Wf1 + l*8192;
            g_pW1[l*4224 + ip*132 + n] = cvt_f16x2(W[(2*ip+1)*128 + n], W[(2*ip)*128 + n]);
        } else {                               // W2: 64 ip x 64 n
            int q = r - 12288;
            int ip = q >> 6, n = q & 63;
            const float* W = Wf2 + l*8192;
            g_pW2[l*4352 + ip*68 + n] = cvt_f16x2(W[(2*ip+1)*64 + n], W[(2*ip)*64 + n]);
        }
    }
}

// ======== MMA GEMM common fragment loaders ========
__device__ __forceinline__ void load_afrag64(uint (&a)[4][4], const uint* sA, int rbase, int gid, int tig) {
    const uint* r0 = sA + (rbase + gid)*36;
    const uint* r1 = sA + (rbase + gid + 8)*36;
#pragma unroll
    for (int kk = 0; kk < 4; kk++) {
        a[kk][0] = r0[kk*8 + tig];
        a[kk][1] = r1[kk*8 + tig];
        a[kk][2] = r0[kk*8 + 4 + tig];
        a[kk][3] = r1[kk*8 + 4 + tig];
    }
}

// ---------------- 1) QKV projection: 32 rows/CTA, 64 thr, prepacked weights ----------------
// grid (512, 3): y selects Q/K/V. l==0 computes embedding inline; m==0 writes g_h.
__global__ void __launch_bounds__(64) k_qkv_mma(
        const float* __restrict__ bq, const float* __restrict__ bk,
        const float* __restrict__ bv,
        const float* __restrict__ x,  const float* __restrict__ Wemb,
        const float* __restrict__ bemb, int l) {
    __shared__ uint  sA [32*36];
    __shared__ float sX [32*NF];
    int tid = threadIdx.x;
    int row0 = blockIdx.x * 32;
    int m = blockIdx.y;
    const uint* pW    = ((m == 0) ? g_pWq : (m == 1) ? g_pWk : g_pWv) + l*2176;
    const float* bias = ((m == 0) ? bq : (m == 1) ? bk : bv) + l*D;
    float* out        = (m == 0) ? g_q : (m == 1) ? g_k : g_v;

    if (l == 0) {
        for (int idx = tid; idx < 32*NF; idx += 64)
            sX[idx] = x[(size_t)(row0 + idx/NF)*NF + idx%NF];
        __syncthreads();
        for (int idx = tid; idx < 1024; idx += 64) {
            int r = idx >> 5, c2 = idx & 31;
            int row = row0 + r;
            int s = row & (S-1);
            int c = c2*2;
            float v0 = bemb[c]   + g_pe[s*64 + c];
            float v1 = bemb[c+1] + g_pe[s*64 + c + 1];
            const float* xr = sX + r*NF;
#pragma unroll
            for (int f = 0; f < NF; f++) {
                v0 += xr[f] * Wemb[f*D + c];
                v1 += xr[f] * Wemb[f*D + c + 1];
            }
            sA[r*36 + c2] = cvt_f16x2(v1, v0);
            if (m == 0) *(float2*)(g_h + (size_t)row*D + c) = make_float2(v0, v1);
        }
    } else {
        for (int idx = tid; idx < 1024; idx += 64) {
            int r = idx >> 5, c2 = idx & 31;
            float2 v = *(const float2*)(g_h + (size_t)(row0 + r)*D + c2*2);
            sA[r*36 + c2] = cvt_f16x2(v.y, v.x);
        }
    }
    __syncthreads();

    int warp = tid >> 5, lane = tid & 31;
    int gid = lane >> 2, tig = lane & 3;
    uint a[4][4];
    load_afrag64(a, sA, warp*16, gid, tig);

#pragma unroll
    for (int t = 0; t < 8; t++) {
        float acc[4] = {0,0,0,0};
#pragma unroll
        for (int kk = 0; kk < 4; kk++) {
            uint b0 = pW[(kk*8 + tig)*68 + t*8 + gid];
            uint b1 = pW[(kk*8 + 4 + tig)*68 + t*8 + gid];
            mma16n8k16(acc, a[kk][0], a[kk][1], a[kk][2], a[kk][3], b0, b1);
        }
        float2 bv2 = *(const float2*)(bias + t*8 + tig*2);
        int r = row0 + warp*16 + gid;
        *(float2*)(out + (size_t)r*D + t*8 + tig*2) =
            make_float2(acc[0] + bv2.x, acc[1] + bv2.y);
        *(float2*)(out + (size_t)(r + 8)*D + t*8 + tig*2) =
            make_float2(acc[2] + bv2.x, acc[3] + bv2.y);
    }
}

// ---------------- 2) split-K attention: split accumulator chains (E/O) ----------------
__global__ void __launch_bounds__(128) k_attn_mma() {
    __shared__ __half sK [CK2*8];
    __shared__ __half sVT[8*VPAD2];
    int tid = threadIdx.x;
    int bh  = blockIdx.y;
    int b   = bh >> 3, hh = bh & 7;
    int qt  = blockIdx.x >> 1;
    int ck  = blockIdx.x & 1;
    int k0  = ck * CK2;
    const float* kbase = g_k + (size_t)(b*S + k0)*D + hh*HD;
    const float* vbase = g_v + (size_t)(b*S + k0)*D + hh*HD;
    const float pre = 0.35355339059327373f * 1.4426950408889634f;
    for (int i = tid; i < CK2*8; i += 128) {
        int key = i >> 3, d = i & 7;
        sK[i]             = __float2half(kbase[key*D + d] * pre);
        sVT[d*VPAD2 + key] = __float2half(vbase[key*D + d]);
    }
    __syncthreads();

    int warp = tid >> 5, lane = tid & 31;
    int gid  = lane >> 2, tig = lane & 3;
    int q0   = qt * 128 + warp * 32;

    uint qa[2][2];
#pragma unroll
    for (int t2 = 0; t2 < 2; t2++) {
#pragma unroll
        for (int hf = 0; hf < 2; hf++) {
            int qrow = q0 + t2*16 + gid + hf*8;
            float2 qv = *(const float2*)(g_q + (size_t)(b*S + qrow)*D + hh*HD + tig*2);
            qa[t2][hf] = cvt_f16x2(qv.y, qv.x);
        }
    }

    float acc0E[4] = {0,0,0,0}, acc0O[4] = {0,0,0,0};
    float acc1E[4] = {0,0,0,0}, acc1O[4] = {0,0,0,0};
    float lac0E[4] = {0,0,0,0}, lac0O[4] = {0,0,0,0};
    float lac1E[4] = {0,0,0,0}, lac1O[4] = {0,0,0,0};
    const uint ones2 = 0x3C003C00u;
    const __half* kptr = sK  + gid*8 + tig*2;
    const __half* vptr = sVT + gid*VPAD2 + tig*2;

    for (int j0 = 0; j0 < CK2; j0 += 32) {
        uint kb0 = *(const uint*)(kptr + j0*8);
        uint kb1 = *(const uint*)(kptr + j0*8 + 64);
        uint kb2 = *(const uint*)(kptr + j0*8 + 128);
        uint kb3 = *(const uint*)(kptr + j0*8 + 192);
        uint vb0 = *(const uint*)(vptr + j0);
        uint vb1 = *(const uint*)(vptr + j0 + 8);
        uint vb2 = *(const uint*)(vptr + j0 + 16);
        uint vb3 = *(const uint*)(vptr + j0 + 24);
        {
            uint s01a, s23a, s01b, s23b;
            mma16n8k8_f16(s01a, s23a, qa[0][0], qa[0][1], kb0);
            mma16n8k8_f16(s01b, s23b, qa[0][0], qa[0][1], kb1);
            uint p0 = hex2x2(s01a), p1 = hex2x2(s23a);
            uint p2 = hex2x2(s01b), p3 = hex2x2(s23b);
            mma16n8k16(acc0E, p0, p1, p2, p3, vb0, vb1);
            mma16n8k16(lac0E, p0, p1, p2, p3, ones2, ones2);
        }
        {
            uint s01a, s23a, s01b, s23b;
            mma16n8k8_f16(s01a, s23a, qa[1][0], qa[1][1], kb0);
            mma16n8k8_f16(s01b, s23b, qa[1][0], qa[1][1], kb1);
            uint p0 = hex2x2(s01a), p1 = hex2x2(s23a);
            uint p2 = hex2x2(s01b), p3 = hex2x2(s23b);
            mma16n8k16(acc1E, p0, p1, p2, p3, vb0, vb1);
            mma16n8k16(lac1E, p0, p1, p2, p3, ones2, ones2);
        }
        {
            uint s01a, s23a, s01b, s23b;
            mma16n8k8_f16(s01a, s23a, qa[0][0], qa[0][1], kb2);
            mma16n8k8_f16(s01b, s23b, qa[0][0], qa[0][1], kb3);
            uint p0 = hex2x2(s01a), p1 = hex2x2(s23a);
            uint p2 = hex2x2(s01b), p3 = hex2x2(s23b);
            mma16n8k16(acc0O, p0, p1, p2, p3, vb2, vb3);
            mma16n8k16(lac0O, p0, p1, p2, p3, ones2, ones2);
        }
        {
            uint s01a, s23a, s01b, s23b;
            mma16n8k8_f16(s01a, s23a, qa[1][0], qa[1][1], kb2);
            mma16n8k8_f16(s01b, s23b, qa[1][0], qa[1][1], kb3);
            uint p0 = hex2x2(s01a), p1 = hex2x2(s23a);
            uint p2 = hex2x2(s01b), p3 = hex2x2(s23b);
            mma16n8k16(acc1O, p0, p1, p2, p3, vb2, vb3);
            mma16n8k16(lac1O, p0, p1, p2, p3, ones2, ones2);
        }
    }

    float acc0[4], acc1[4], lac0[4], lac1[4];
#pragma unroll
    for (int i = 0; i < 4; i++) {
        acc0[i] = acc0E[i] + acc0O[i];
        acc1[i] = acc1E[i] + acc1O[i];
        lac0[i] = lac0E[i] + lac0O[i];
        lac1[i] = lac1E[i] + lac1O[i];
    }

    size_t base = ((size_t)ck*128 + bh)*S;
    {
        float* pp = g_part + (base + q0 + gid)*12;
        *(float2*)(pp + tig*2) = make_float2(acc0[0], acc0[1]);
        if (tig == 0) pp[8] = lac0[0];
        pp = g_part + (base + q0 + gid + 8)*12;
        *(float2*)(pp + tig*2) = make_float2(acc0[2], acc0[3]);
        if (tig == 0) pp[8] = lac0[2];
        pp = g_part + (base + q0 + 16 + gid)*12;
        *(float2*)(pp + tig*2) = make_float2(acc1[0], acc1[1]);
        if (tig == 0) pp[8] = lac1[0];
        pp = g_part + (base + q0 + 24 + gid)*12;
        *(float2*)(pp + tig*2) = make_float2(acc1[2], acc1[3]);
        if (tig == 0) pp[8] = lac1[2];
    }
}

// ---------------- 3) FUSED block: combine + oproj + LN1 + FFN + LN2 ----------------
__global__ void __launch_bounds__(64) k_block_mma(
        const float* __restrict__ bo,
        const float* __restrict__ g1, const float* __restrict__ b1,
        const float* __restrict__ bf1, const float* __restrict__ bf2,
        const float* __restrict__ g2, const float* __restrict__ b2, int l) {
    __shared__ uint sA[32*36];
    int tid = threadIdx.x;
    int row0 = blockIdx.x * 32;
    const uint* pWo = g_pWo + l*2176;
    const uint* pW1 = g_pW1 + l*4224;
    const uint* pW2 = g_pW2 + l*4352;

    for (int idx = tid; idx < 1024; idx += 64) {
        int r = idx >> 5, c2 = idx & 31;
        int grow = row0 + r;
        int q  = grow & (S-1);
        int bb = grow >> 10;
        int hh = c2 >> 2;
        int bh = bb*8 + hh;
        int off = (c2 & 3)*2;
        const float* p0 = g_part + ((size_t)(0*128 + bh)*S + q)*12;
        const float* p1 = g_part + ((size_t)(1*128 + bh)*S + q)*12;
        float inv = 1.0f / (p0[8] + p1[8]);
        float a0 = (p0[off]   + p1[off])   * inv;
        float a1 = (p0[off+1] + p1[off+1]) * inv;
        sA[r*36 + c2] = cvt_f16x2(a1, a0);
    }
    __syncthreads();

    int warp = tid >> 5, lane = tid & 31;
    int gid = lane >> 2, tig = lane & 3;
    int rA = row0 + warp*16 + gid;
    int rB = rA + 8;

    uint a[4][4];
    load_afrag64(a, sA, warp*16, gid, tig);
    float acc[8][4];
#pragma unroll
    for (int t = 0; t < 8; t++) {
        acc[t][0]=0; acc[t][1]=0; acc[t][2]=0; acc[t][3]=0;
#pragma unroll
        for (int kk = 0; kk < 4; kk++) {
            uint b0 = pWo[(kk*8 + tig)*68 + t*8 + gid];
            uint b1 = pWo[(kk*8 + 4 + tig)*68 + t*8 + gid];
            mma16n8k16(acc[t], a[kk][0], a[kk][1], a[kk][2], a[kk][3], b0, b1);
        }
    }
    float vA[16], vB[16];
    {
        float sumA=0, sqA=0, sumB=0, sqB=0;
#pragma unroll
        for (int t = 0; t < 8; t++) {
            float2 bo2 = *(const float2*)(bo + l*D + t*8 + tig*2);
            float2 hA = *(const float2*)(g_h + (size_t)rA*D + t*8 + tig*2);
            float2 hB = *(const float2*)(g_h + (size_t)rB*D + t*8 + tig*2);
            float a0 = acc[t][0] + bo2.x + hA.x;
            float a1 = acc[t][1] + bo2.y + hA.y;
            float b0 = acc[t][2] + bo2.x + hB.x;
            float b1 = acc[t][3] + bo2.y + hB.y;
            vA[t*2]=a0; vA[t*2+1]=a1; vB[t*2]=b0; vB[t*2+1]=b1;
            sumA += a0+a1; sqA += a0*a0+a1*a1;
            sumB += b0+b1; sqB += b0*b0+b1*b1;
        }
#pragma unroll
        for (int o = 1; o < 4; o <<= 1) {
            sumA += __shfl_xor_sync(0xffffffffu, sumA, o);
            sqA  += __shfl_xor_sync(0xffffffffu, sqA,  o);
            sumB += __shfl_xor_sync(0xffffffffu, sumB, o);
            sqB  += __shfl_xor_sync(0xffffffffu, sqB,  o);
        }
        float mA = sumA*(1.f/64.f), vrA = sqA*(1.f/64.f) - mA*mA;
        float mB = sumB*(1.f/64.f), vrB = sqB*(1.f/64.f) - mB*mB;
        float rsA = rsqrtf(vrA + 1e-5f), rsB = rsqrtf(vrB + 1e-5f);
#pragma unroll
        for (int t = 0; t < 8; t++) {
            float2 gg = *(const float2*)(g1 + l*D + t*8 + tig*2);
            float2 bb = *(const float2*)(b1 + l*D + t*8 + tig*2);
            vA[t*2]   = (vA[t*2]  -mA)*rsA*gg.x + bb.x;
            vA[t*2+1] = (vA[t*2+1]-mA)*rsA*gg.y + bb.y;
            vB[t*2]   = (vB[t*2]  -mB)*rsB*gg.x + bb.x;
            vB[t*2+1] = (vB[t*2+1]-mB)*rsB*gg.y + bb.y;
        }
    }
    __syncthreads();
#pragma unroll
    for (int t = 0; t < 8; t++) {
        sA[(warp*16 + gid)*36     + t*4 + tig] = cvt_f16x2(vA[t*2+1], vA[t*2]);
        sA[(warp*16 + gid + 8)*36 + t*4 + tig] = cvt_f16x2(vB[t*2+1], vB[t*2]);
    }
    __syncthreads();

    uint a2[4][4];
    load_afrag64(a2, sA, warp*16, gid, tig);
    uint hA[16][2];
#pragma unroll
    for (int t = 0; t < 16; t++) {
        float facc[4] = {0,0,0,0};
#pragma unroll
        for (int kk = 0; kk < 4; kk++) {
            uint b0 = pW1[(kk*8 + tig)*132 + t*8 + gid];
            uint b1 = pW1[(kk*8 + 4 + tig)*132 + t*8 + gid];
            mma16n8k16(facc, a2[kk][0], a2[kk][1], a2[kk][2], a2[kk][3], b0, b1);
        }
        float2 bf = *(const float2*)(bf1 + l*FF + t*8 + tig*2);
        float c0 = fmaxf(facc[0] + bf.x, 0.f);
        float c1 = fmaxf(facc[1] + bf.y, 0.f);
        float c2 = fmaxf(facc[2] + bf.x, 0.f);
        float c3 = fmaxf(facc[3] + bf.y, 0.f);
        hA[t][0] = cvt_f16x2(c1, c0);
        hA[t][1] = cvt_f16x2(c3, c2);
    }

#pragma unroll
    for (int t = 0; t < 8; t++) {
        acc[t][0]=0; acc[t][1]=0; acc[t][2]=0; acc[t][3]=0;
#pragma unroll
        for (int kk = 0; kk < 8; kk++) {
            uint b0 = pW2[(kk*8 + tig)*68 + t*8 + gid];
            uint b1 = pW2[(kk*8 + 4 + tig)*68 + t*8 + gid];
            mma16n8k16(acc[t], hA[2*kk][0], hA[2*kk][1], hA[2*kk+1][0], hA[2*kk+1][1], b0, b1);
        }
    }
    {
        float sumA=0, sqA=0, sumB=0, sqB=0;
        float wA[16], wB[16];
#pragma unroll
        for (int t = 0; t < 8; t++) {
            float2 bo2 = *(const float2*)(bf2 + l*D + t*8 + tig*2);
            float a0 = acc[t][0] + bo2.x + vA[t*2];
            float a1 = acc[t][1] + bo2.y + vA[t*2+1];
            float b0 = acc[t][2] + bo2.x + vB[t*2];
            float b1 = acc[t][3] + bo2.y + vB[t*2+1];
            wA[t*2]=a0; wA[t*2+1]=a1; wB[t*2]=b0; wB[t*2+1]=b1;
            sumA += a0+a1; sqA += a0*a0+a1*a1;
            sumB += b0+b1; sqB += b0*b0+b1*b1;
        }
#pragma unroll
        for (int o = 1; o < 4; o <<= 1) {
            sumA += __shfl_xor_sync(0xffffffffu, sumA, o);
            sqA  += __shfl_xor_sync(0xffffffffu, sqA,  o);
            sumB += __shfl_xor_sync(0xffffffffu, sumB, o);
            sqB  += __shfl_xor_sync(0xffffffffu, sqB,  o);
        }
        float mA = sumA*(1.f/64.f), vrA = sqA*(1.f/64.f) - mA*mA;
        float mB = sumB*(1.f/64.f), vrB = sqB*(1.f/64.f) - mB*mB;
        float rsA = rsqrtf(vrA + 1e-5f), rsB = rsqrtf(vrB + 1e-5f);
#pragma unroll
        for (int t = 0; t < 8; t++) {
            float2 gg = *(const float2*)(g2 + l*D + t*8 + tig*2);
            float2 bb = *(const float2*)(b2 + l*D + t*8 + tig*2);
            *(float2*)(g_h + (size_t)rA*D + t*8 + tig*2) =
                make_float2((wA[t*2]-mA)*rsA*gg.x + bb.x, (wA[t*2+1]-mA)*rsA*gg.y + bb.y);
            *(float2*)(g_h + (size_t)rB*D + t*8 + tig*2) =
                make_float2((wB[t*2]-mB)*rsB*gg.x + bb.x, (wB[t*2+1]-mB)*rsB*gg.y + bb.y);
        }
    }
}

// ---------------- 4a) pool partials: grid (B,4), 256 thr ----------------
__global__ void k_pool(void) {
    __shared__ float sp2[256];
    int b = blockIdx.x, sc = blockIdx.y, tid = threadIdx.x;
    int col = tid & 63, ch = tid >> 6;
    const float* hb = g_h + (size_t)b*S*D + ((size_t)sc*256 + ch*64)*D;
    float sum = 0.f;
#pragma unroll 8
    for (int s = 0; s < 64; s++) sum += hb[s*D + col];
    sp2[tid] = sum;
    __syncthreads();
    if (tid < 64)
        g_poolp[(b*4 + sc)*D + tid] = sp2[tid] + sp2[tid+64] + sp2[tid+128] + sp2[tid+192];
}

// ---------------- 4b) MLP head + quantum circuit + <Z> + entropy ----------------
#define BARS128() asm volatile("bar.sync 1, 128;" ::: "memory")

__global__ void k_quantum(const float* __restrict__ Wp1, const float* __restrict__ bp1,
                          const float* __restrict__ Wp2, const float* __restrict__ bp2,
                          const float* __restrict__ qw, float* __restrict__ out) {
    __shared__ float sp[64];
    __shared__ float sh[32];
    __shared__ float sang[8];
    __shared__ float2 st[256];
    __shared__ float2 rho[256];
    __shared__ float  sred[256];
    __shared__ float  jc[8], js[8], jpx[8], jpy[8];
    int b = blockIdx.x, tid = threadIdx.x;

    if (tid < 64) {
        const float* pp = g_poolp + b*4*D;
        sp[tid] = (pp[tid] + pp[D+tid] + pp[2*D+tid] + pp[3*D+tid]) * (1.0f/(float)S);
    }
    __syncthreads();
    if (tid < 32) {
        float a = bp1[tid];
#pragma unroll
        for (int i = 0; i < 64; i++) a += sp[i] * Wp1[i*32 + tid];
        sh[tid] = fmaxf(a, 0.f);
    }
    __syncthreads();
    if (tid < 8) {
        float a = bp2[tid];
#pragma unroll
        for (int i = 0; i < 32; i++) a += sh[i] * Wp2[i*8 + tid];
        sang[tid] = tanhf(a) * 3.14159265358979f;
    }

    st[tid] = make_float2(tid == 0 ? 1.f : 0.f, 0.f);
    __syncthreads();

    for (int l = 0; l < QL; l++) {
        for (int w = 0; w < NQ; w++) {
            int mask = 1 << (7 - w);
            float c = cosf(0.5f * sang[w]);
            float s = sinf(0.5f * sang[w]);
            if (!(tid & mask)) {
                float2 v0 = st[tid], v1 = st[tid | mask];
                st[tid]        = make_float2(c*v0.x + s*v1.y,  c*v0.y - s*v1.x);
                st[tid | mask] = make_float2(s*v0.y + c*v1.x, -s*v0.x + c*v1.y);
            }
            __syncthreads();
        }
        for (int w = 0; w < NQ; w++) {
            int mask = 1 << (7 - w);
            float phi = qw[(l*NQ + w)*3 + 0];
            float th  = qw[(l*NQ + w)*3 + 1];
            float om  = qw[(l*NQ + w)*3 + 2];
            float ct = cosf(0.5f*th), stt = sinf(0.5f*th);
            float aa = 0.5f*(phi + om), bb = 0.5f*(phi - om);
            float ca = cosf(aa), sa = sinf(aa), cb = cosf(bb), sb = sinf(bb);
            float2 U00 = make_float2( ct*ca, -ct*sa);
            float2 U01 = make_float2(-stt*cb, -stt*sb);
            float2 U10 = make_float2( stt*cb, -stt*sb);
            float2 U11 = make_float2( ct*ca,  ct*sa);
            if (!(tid & mask)) {
                float2 v0 = st[tid], v1 = st[tid | mask];
                st[tid]        = cadd(cmul(U00, v0), cmul(U01, v1));
                st[tid | mask] = cadd(cmul(U10, v0), cmul(U11, v1));
            }
            __syncthreads();
        }
        for (int w = 0; w < NQ; w++) {
            int mc = 1 << (7 - w);
            int mt = 1 << (7 - ((w + 1) & 7));
            if ((tid & mc) && !(tid & mt)) {
                float2 t0 = st[tid];
                st[tid] = st[tid | mt];
                st[tid | mt] = t0;
            }
            __syncthreads();
        }
    }

    float p = st[tid].x*st[tid].x + st[tid].y*st[tid].y;
    for (int w = 0; w < 3; w++) {
        sred[tid] = (tid & (1 << (7 - w))) ? -p : p;
        __syncthreads();
        for (int off = 128; off > 0; off >>= 1) {
            if (tid < off) sred[tid] += sred[tid + off];
            __syncthreads();
        }
        if (tid == 0) out[b*3 + w] = sred[0];
        __syncthreads();
    }

    {
        int r = tid >> 4, c = tid & 15;
        float2 acc = make_float2(0.f, 0.f);
#pragma unroll
        for (int k = 0; k < 16; k++) {
            float2 mr = st[r*16 + k], mcv = st[c*16 + k];
            acc.x += mr.x*mcv.x + mr.y*mcv.y;
            acc.y += mr.y*mcv.x - mr.x*mcv.y;
        }
        rho[tid] = acc;
    }
    __syncthreads();

    if (tid < 128) {
        int g = tid >> 4, k = tid & 15;
        for (int sweep = 0; sweep < 6; sweep++) {
            for (int rnd = 0; rnd < 15; rnd++) {
                int pa, qa_;
                if (g == 0) { pa = 15; qa_ = rnd; }
                else {
                    pa  = (rnd + g) % 15;
                    qa_ = (rnd + 15 - g) % 15;
                }
                int pp = min(pa, qa_), qq = max(pa, qa_);
                if (k == 0) {
                    float2 apq = rho[pp*16 + qq];
                    float b2v = apq.x*apq.x + apq.y*apq.y;
                    if (b2v > 1e-26f) {
                        float app = rho[pp*16 + pp].x;
                        float aqq = rho[qq*16 + qq].x;
                        float bn  = sqrtf(b2v);
                        float tau = (aqq - app) / (2.f * bn);
                        float rt  = sqrtf(1.f + tau*tau);
                        float t   = (tau >= 0.f) ? 1.f/(tau + rt) : -1.f/(-tau + rt);
                        float cc  = rsqrtf(1.f + t*t);
                        jc[g] = cc; js[g] = t*cc;
                        jpx[g] = apq.x/bn; jpy[g] = apq.y/bn;
                    } else {
                        jc[g] = 1.f; js[g] = 0.f; jpx[g] = 1.f; jpy[g] = 0.f;
                    }
                }
                BARS128();
                float cc = jc[g], ss = js[g];
                float2 ph = make_float2(jpx[g], jpy[g]);
                {
                    float2 rp = rho[pp*16 + k], rq = rho[qq*16 + k];
                    float2 prq  = cmul(ph, rq);
                    float2 cprp = cmulcj(ph, rp);
                    rho[pp*16 + k] = make_float2(cc*rp.x - ss*prq.x,  cc*rp.y - ss*prq.y);
                    rho[qq*16 + k] = make_float2(ss*cprp.x + cc*rq.x, ss*cprp.y + cc*rq.y);
                }
                BARS128();
                {
                    float2 cp = rho[k*16 + pp], cq = rho[k*16 + qq];
                    float2 ccq = cmulcj(ph, cq);
                    float2 pcp = cmul(ph, cp);
                    rho[k*16 + pp] = make_float2(cc*cp.x - ss*ccq.x,  cc*cp.y - ss*ccq.y);
                    rho[k*16 + qq] = make_float2(ss*pcp.x + cc*cq.x, ss*pcp.y + cc*cq.y);
                }
                BARS128();
            }
        }
        if (tid == 0) {
            float ent = 0.f;
#pragma unroll
            for (int kk = 0; kk < 16; kk++) {
                float ev = rho[kk*16 + kk].x;
                ev = fminf(fmaxf(ev, 1e-10f), 1.f);
                ent -= ev * logf(ev);
            }
            out[48 + b] = ent;
        }
    }
}

// ---------------- launch ----------------
extern "C" void kernel_launch(void* const* d_in, const int* in_sizes, int n_in,
                              void* d_out, int out_size) {
    const float* x    = (const float*)d_in[0];
    const float* Wemb = (const float*)d_in[1];
    const float* bemb = (const float*)d_in[2];
    const float* Wq   = (const float*)d_in[3];
    const float* bq   = (const float*)d_in[4];
    const float* Wk   = (const float*)d_in[5];
    const float* bk   = (const float*)d_in[6];
    const float* Wv   = (const float*)d_in[7];
    const float* bv   = (const float*)d_in[8];
    const float* Wo   = (const float*)d_in[9];
    const float* bo   = (const float*)d_in[10];
    const float* ln1g = (const float*)d_in[11];
    const float* ln1b = (const float*)d_in[12];
    const float* ln2g = (const float*)d_in[13];
    const float* ln2b = (const float*)d_in[14];
    const float* Wf1  = (const float*)d_in[15];
    const float* bf1  = (const float*)d_in[16];
    const float* Wf2  = (const float*)d_in[17];
    const float* bf2  = (const float*)d_in[18];
    const float* Wp1  = (const float*)d_in[19];
    const float* bp1  = (const float*)d_in[20];
    const float* Wp2  = (const float*)d_in[21];
    const float* bp2  = (const float*)d_in[22];
    const float* qw   = (const float*)d_in[23];
    float* out = (float*)d_out;

    k_init<<<128 + NL*64, 256>>>(Wq, Wk, Wv, Wo, Wf1, Wf2);
    for (int l = 0; l < NL; l++) {
        dim3 qg(512, 3);
        k_qkv_mma<<<qg, 64>>>(bq, bk, bv, x, Wemb, bemb, l);
        dim3 ag(16, B*H);
        k_attn_mma<<<ag, 128>>>();
        k_block_mma<<<512, 64>>>(bo, ln1g, ln1b, bf1, bf2, ln2g, ln2b, l);
    }
    dim3 pg(B, 4);
    k_pool<<<pg, 256>>>();
    k_quantum<<<B, 256>>>(Wp1, bp1, Wp2, bp2, qw, out);
}

// round 13
// speedup vs baseline: 1.2793x; 1.0601x over previous
#include <cuda_runtime.h>
#include <cuda_fp16.h>
#include <math.h>

#define B   16
#define S   1024
#define NF  5
#define D   64
#define H   8
#define HD  8
#define NL  2
#define FF  128
#define NQ  8
#define QL  3
#define BS  (B*S)
#define CK2  512
#define VPAD2 520

typedef unsigned long long ull;
typedef unsigned int uint;

// ---------------- device scratch ----------------
__device__ float g_h  [BS*D];
__device__ float g_q  [BS*D];
__device__ float g_k  [BS*D];
__device__ float g_v  [BS*D];
__device__ float g_pe [S*D];
__device__ float g_part[(size_t)2*128*S*12];   // 12.6 MB partials
__device__ float g_poolp[B*4*D];               // pool partials
// prepacked half2 weights (B-fragment layout)
__device__ uint g_pWq[NL*32*68];
__device__ uint g_pWk[NL*32*68];
__device__ uint g_pWv[NL*32*68];
__device__ uint g_pWo[NL*32*68];
__device__ uint g_pW1[NL*32*132];
__device__ uint g_pW2[NL*64*68];

// ---------------- mma / f16 / async helpers ----------------
__device__ __forceinline__ void mma16n8k8_f16(uint& d0, uint& d1, uint a0, uint a1, uint b0) {
    asm volatile("mma.sync.aligned.m16n8k8.row.col.f16.f16.f16.f16 "
        "{%0,%1}, {%2,%3}, {%4}, {%5,%6};"
        : "=r"(d0), "=r"(d1)
        : "r"(a0), "r"(a1), "r"(b0), "r"(0u), "r"(0u));
}
__device__ __forceinline__ void mma16n8k16(float* d,
                                           uint a0, uint a1, uint a2, uint a3,
                                           uint b0, uint b1) {
    asm volatile("mma.sync.aligned.m16n8k16.row.col.f32.f16.f16.f32 "
        "{%0,%1,%2,%3}, {%4,%5,%6,%7}, {%8,%9}, {%0,%1,%2,%3};"
        : "+f"(d[0]), "+f"(d[1]), "+f"(d[2]), "+f"(d[3])
        : "r"(a0), "r"(a1), "r"(a2), "r"(a3), "r"(b0), "r"(b1));
}
__device__ __forceinline__ uint cvt_f16x2(float hi, float lo) {
    uint r; asm("cvt.rn.f16x2.f32 %0, %1, %2;" : "=r"(r) : "f"(hi), "f"(lo)); return r;
}
__device__ __forceinline__ uint hex2x2(uint x) {
    uint r; asm("ex2.approx.f16x2 %0, %1;" : "=r"(r) : "r"(x)); return r;
}
__device__ __forceinline__ void cpasync16(uint smem_addr, const void* gptr) {
    asm volatile("cp.async.cg.shared.global [%0], [%1], 16;" :: "r"(smem_addr), "l"(gptr));
}
#define CP_COMMIT()  asm volatile("cp.async.commit_group;" ::: "memory")
#define CP_WAIT(n)   asm volatile("cp.async.wait_group %0;" :: "n"(n) : "memory")
__device__ __forceinline__ uint smem_u32p(const void* p) {
    return (uint)__cvta_generic_to_shared(p);
}

// ---------------- complex helpers ----------------
__device__ __forceinline__ float2 cmul(float2 a, float2 b) {
    return make_float2(a.x*b.x - a.y*b.y, a.x*b.y + a.y*b.x);
}
__device__ __forceinline__ float2 cmulcj(float2 a, float2 b) {
    return make_float2(a.x*b.x + a.y*b.y, a.x*b.y - a.y*b.x);
}
__device__ __forceinline__ float2 cadd(float2 a, float2 b) {
    return make_float2(a.x + b.x, a.y + b.y);
}

// ---------------- 0) init: pe table + weight prepack ----------------
__global__ void k_init(const float* __restrict__ Wq, const float* __restrict__ Wk,
                       const float* __restrict__ Wv, const float* __restrict__ Wo,
                       const float* __restrict__ Wf1, const float* __restrict__ Wf2) {
    int bidx = blockIdx.x;
    int tid = threadIdx.x;
    if (bidx < 128) {
        int idx = bidx * 256 + tid;
        int s = idx >> 5, p = idx & 31;
        float div = __expf(-0.14391156831212787f * (float)(2*p));
        float sn, cs;
        sincosf((float)s * div, &sn, &cs);
        g_pe[s*64 + 2*p]     = sn;
        g_pe[s*64 + 2*p + 1] = cs;
    } else {
        int idx = (bidx - 128) * 256 + tid;    // < NL*16384
        int l = idx / 16384;
        int r = idx % 16384;
        if (r < 8192) {
            int m = r >> 11;
            int q = r & 2047;
            int ip = q >> 6, n = q & 63;
            const float* W = (m == 0) ? (Wq + l*4096) : (m == 1) ? (Wk + l*4096)
                           : (m == 2) ? (Wv + l*4096) : (Wo + l*4096);
            uint* dst = (m == 0) ? g_pWq : (m == 1) ? g_pWk : (m == 2) ? g_pWv : g_pWo;
            dst[l*2176 + ip*68 + n] = cvt_f16x2(W[(2*ip+1)*64 + n], W[(2*ip)*64 + n]);
        } else if (r < 12288) {
            int q = r - 8192;
            int ip = q >> 7, n = q & 127;
            const float* W = Wf1 + l*8192;
            g_pW1[l*4224 + ip*132 + n] = cvt_f16x2(W[(2*ip+1)*128 + n], W[(2*ip)*128 + n]);
        } else {
            int q = r - 12288;
            int ip = q >> 6, n = q & 63;
            const float* W = Wf2 + l*8192;
            g_pW2[l*4352 + ip*68 + n] = cvt_f16x2(W[(2*ip+1)*64 + n], W[(2*ip)*64 + n]);
        }
    }
}

// ======== MMA GEMM common fragment loaders ========
__device__ __forceinline__ void load_afrag64(uint (&a)[4][4], const uint* sA, int rbase, int gid, int tig) {
    const uint* r0 = sA + (rbase + gid)*36;
    const uint* r1 = sA + (rbase + gid + 8)*36;
#pragma unroll
    for (int kk = 0; kk < 4; kk++) {
        a[kk][0] = r0[kk*8 + tig];
        a[kk][1] = r1[kk*8 + tig];
        a[kk][2] = r0[kk*8 + 4 + tig];
        a[kk][3] = r1[kk*8 + 4 + tig];
    }
}

// ---------------- 1) QKV projection: cp.async-staged weights ----------------
__global__ void __launch_bounds__(64) k_qkv_mma(
        const float* __restrict__ bq, const float* __restrict__ bk,
        const float* __restrict__ bv,
        const float* __restrict__ x,  const float* __restrict__ Wemb,
        const float* __restrict__ bemb, int l) {
    __shared__ uint  sA [32*36];
    __shared__ uint  sW [2176];
    __shared__ float sX [32*NF];
    int tid = threadIdx.x;
    int row0 = blockIdx.x * 32;
    int m = blockIdx.y;
    const uint* pW    = ((m == 0) ? g_pWq : (m == 1) ? g_pWk : g_pWv) + l*2176;
    const float* bias = ((m == 0) ? bq : (m == 1) ? bk : bv) + l*D;
    float* out        = (m == 0) ? g_q : (m == 1) ? g_k : g_v;

    // prefetch weights -> smem (544 x 16B chunks), no wait yet
    {
        uint sw = smem_u32p(sW);
        for (int i = tid; i < 544; i += 64)
            cpasync16(sw + i*16, pW + i*4);
        CP_COMMIT();
    }

    if (l == 0) {
        for (int idx = tid; idx < 32*NF; idx += 64)
            sX[idx] = x[(size_t)(row0 + idx/NF)*NF + idx%NF];
        __syncthreads();
        for (int idx = tid; idx < 1024; idx += 64) {
            int r = idx >> 5, c2 = idx & 31;
            int row = row0 + r;
            int s = row & (S-1);
            int c = c2*2;
            float v0 = bemb[c]   + g_pe[s*64 + c];
            float v1 = bemb[c+1] + g_pe[s*64 + c + 1];
            const float* xr = sX + r*NF;
#pragma unroll
            for (int f = 0; f < NF; f++) {
                v0 += xr[f] * Wemb[f*D + c];
                v1 += xr[f] * Wemb[f*D + c + 1];
            }
            sA[r*36 + c2] = cvt_f16x2(v1, v0);
            if (m == 0) *(float2*)(g_h + (size_t)row*D + c) = make_float2(v0, v1);
        }
    } else {
        for (int idx = tid; idx < 1024; idx += 64) {
            int r = idx >> 5, c2 = idx & 31;
            float2 v = *(const float2*)(g_h + (size_t)(row0 + r)*D + c2*2);
            sA[r*36 + c2] = cvt_f16x2(v.y, v.x);
        }
    }
    CP_WAIT(0);
    __syncthreads();

    int warp = tid >> 5, lane = tid & 31;
    int gid = lane >> 2, tig = lane & 3;
    uint a[4][4];
    load_afrag64(a, sA, warp*16, gid, tig);

#pragma unroll
    for (int t = 0; t < 8; t++) {
        float acc[4] = {0,0,0,0};
#pragma unroll
        for (int kk = 0; kk < 4; kk++) {
            uint b0 = sW[(kk*8 + tig)*68 + t*8 + gid];
            uint b1 = sW[(kk*8 + 4 + tig)*68 + t*8 + gid];
            mma16n8k16(acc, a[kk][0], a[kk][1], a[kk][2], a[kk][3], b0, b1);
        }
        float2 bv2 = *(const float2*)(bias + t*8 + tig*2);
        int r = row0 + warp*16 + gid;
        *(float2*)(out + (size_t)r*D + t*8 + tig*2) =
            make_float2(acc[0] + bv2.x, acc[1] + bv2.y);
        *(float2*)(out + (size_t)(r + 8)*D + t*8 + tig*2) =
            make_float2(acc[2] + bv2.x, acc[3] + bv2.y);
    }
}

// ---------------- 2) split-K attention: split accumulator chains (E/O) ----------------
__global__ void __launch_bounds__(128) k_attn_mma() {
    __shared__ __half sK [CK2*8];
    __shared__ __half sVT[8*VPAD2];
    int tid = threadIdx.x;
    int bh  = blockIdx.y;
    int b   = bh >> 3, hh = bh & 7;
    int qt  = blockIdx.x >> 1;
    int ck  = blockIdx.x & 1;
    int k0  = ck * CK2;
    const float* kbase = g_k + (size_t)(b*S + k0)*D + hh*HD;
    const float* vbase = g_v + (size_t)(b*S + k0)*D + hh*HD;
    const float pre = 0.35355339059327373f * 1.4426950408889634f;
    for (int i = tid; i < CK2*8; i += 128) {
        int key = i >> 3, d = i & 7;
        sK[i]             = __float2half(kbase[key*D + d] * pre);
        sVT[d*VPAD2 + key] = __float2half(vbase[key*D + d]);
    }
    __syncthreads();

    int warp = tid >> 5, lane = tid & 31;
    int gid  = lane >> 2, tig = lane & 3;
    int q0   = qt * 128 + warp * 32;

    uint qa[2][2];
#pragma unroll
    for (int t2 = 0; t2 < 2; t2++) {
#pragma unroll
        for (int hf = 0; hf < 2; hf++) {
            int qrow = q0 + t2*16 + gid + hf*8;
            float2 qv = *(const float2*)(g_q + (size_t)(b*S + qrow)*D + hh*HD + tig*2);
            qa[t2][hf] = cvt_f16x2(qv.y, qv.x);
        }
    }

    float acc0E[4] = {0,0,0,0}, acc0O[4] = {0,0,0,0};
    float acc1E[4] = {0,0,0,0}, acc1O[4] = {0,0,0,0};
    float lac0E[4] = {0,0,0,0}, lac0O[4] = {0,0,0,0};
    float lac1E[4] = {0,0,0,0}, lac1O[4] = {0,0,0,0};
    const uint ones2 = 0x3C003C00u;
    const __half* kptr = sK  + gid*8 + tig*2;
    const __half* vptr = sVT + gid*VPAD2 + tig*2;

    for (int j0 = 0; j0 < CK2; j0 += 32) {
        uint kb0 = *(const uint*)(kptr + j0*8);
        uint kb1 = *(const uint*)(kptr + j0*8 + 64);
        uint kb2 = *(const uint*)(kptr + j0*8 + 128);
        uint kb3 = *(const uint*)(kptr + j0*8 + 192);
        uint vb0 = *(const uint*)(vptr + j0);
        uint vb1 = *(const uint*)(vptr + j0 + 8);
        uint vb2 = *(const uint*)(vptr + j0 + 16);
        uint vb3 = *(const uint*)(vptr + j0 + 24);
        {
            uint s01a, s23a, s01b, s23b;
            mma16n8k8_f16(s01a, s23a, qa[0][0], qa[0][1], kb0);
            mma16n8k8_f16(s01b, s23b, qa[0][0], qa[0][1], kb1);
            uint p0 = hex2x2(s01a), p1 = hex2x2(s23a);
            uint p2 = hex2x2(s01b), p3 = hex2x2(s23b);
            mma16n8k16(acc0E, p0, p1, p2, p3, vb0, vb1);
            mma16n8k16(lac0E, p0, p1, p2, p3, ones2, ones2);
        }
        {
            uint s01a, s23a, s01b, s23b;
            mma16n8k8_f16(s01a, s23a, qa[1][0], qa[1][1], kb0);
            mma16n8k8_f16(s01b, s23b, qa[1][0], qa[1][1], kb1);
            uint p0 = hex2x2(s01a), p1 = hex2x2(s23a);
            uint p2 = hex2x2(s01b), p3 = hex2x2(s23b);
            mma16n8k16(acc1E, p0, p1, p2, p3, vb0, vb1);
            mma16n8k16(lac1E, p0, p1, p2, p3, ones2, ones2);
        }
        {
            uint s01a, s23a, s01b, s23b;
            mma16n8k8_f16(s01a, s23a, qa[0][0], qa[0][1], kb2);
            mma16n8k8_f16(s01b, s23b, qa[0][0], qa[0][1], kb3);
            uint p0 = hex2x2(s01a), p1 = hex2x2(s23a);
            uint p2 = hex2x2(s01b), p3 = hex2x2(s23b);
            mma16n8k16(acc0O, p0, p1, p2, p3, vb2, vb3);
            mma16n8k16(lac0O, p0, p1, p2, p3, ones2, ones2);
        }
        {
            uint s01a, s23a, s01b, s23b;
            mma16n8k8_f16(s01a, s23a, qa[1][0], qa[1][1], kb2);
            mma16n8k8_f16(s01b, s23b, qa[1][0], qa[1][1], kb3);
            uint p0 = hex2x2(s01a), p1 = hex2x2(s23a);
            uint p2 = hex2x2(s01b), p3 = hex2x2(s23b);
            mma16n8k16(acc1O, p0, p1, p2, p3, vb2, vb3);
            mma16n8k16(lac1O, p0, p1, p2, p3, ones2, ones2);
        }
    }

    float acc0[4], acc1[4], lac0[4], lac1[4];
#pragma unroll
    for (int i = 0; i < 4; i++) {
        acc0[i] = acc0E[i] + acc0O[i];
        acc1[i] = acc1E[i] + acc1O[i];
        lac0[i] = lac0E[i] + lac0O[i];
        lac1[i] = lac1E[i] + lac1O[i];
    }

    size_t base = ((size_t)ck*128 + bh)*S;
    {
        float* pp = g_part + (base + q0 + gid)*12;
        *(float2*)(pp + tig*2) = make_float2(acc0[0], acc0[1]);
        if (tig == 0) pp[8] = lac0[0];
        pp = g_part + (base + q0 + gid + 8)*12;
        *(float2*)(pp + tig*2) = make_float2(acc0[2], acc0[3]);
        if (tig == 0) pp[8] = lac0[2];
        pp = g_part + (base + q0 + 16 + gid)*12;
        *(float2*)(pp + tig*2) = make_float2(acc1[0], acc1[1]);
        if (tig == 0) pp[8] = lac1[0];
        pp = g_part + (base + q0 + 24 + gid)*12;
        *(float2*)(pp + tig*2) = make_float2(acc1[2], acc1[3]);
        if (tig == 0) pp[8] = lac1[2];
    }
}

// ---------------- 3) FUSED block: cp.async-staged weights, pipelined waits ----------------
__global__ void __launch_bounds__(64) k_block_mma(
        const float* __restrict__ bo,
        const float* __restrict__ g1, const float* __restrict__ b1,
        const float* __restrict__ bf1, const float* __restrict__ bf2,
        const float* __restrict__ g2, const float* __restrict__ b2, int l) {
    __shared__ uint sA [32*36];
    __shared__ uint sWo[2176];
    __shared__ uint sW1[4224];
    __shared__ uint sW2[4352];
    int tid = threadIdx.x;
    int row0 = blockIdx.x * 32;

    // prefetch all three weight matrices (3 commit groups, waits deferred)
    {
        const uint* pWo = g_pWo + l*2176;
        const uint* pW1 = g_pW1 + l*4224;
        const uint* pW2 = g_pW2 + l*4352;
        uint so = smem_u32p(sWo), s1 = smem_u32p(sW1), s2 = smem_u32p(sW2);
        for (int i = tid; i < 544; i += 64)  cpasync16(so + i*16, pWo + i*4);
        CP_COMMIT();
        for (int i = tid; i < 1056; i += 64) cpasync16(s1 + i*16, pW1 + i*4);
        CP_COMMIT();
        for (int i = tid; i < 1088; i += 64) cpasync16(s2 + i*16, pW2 + i*4);
        CP_COMMIT();
    }

    // combine attention partials -> normalized attention output (fp16 A)
    for (int idx = tid; idx < 1024; idx += 64) {
        int r = idx >> 5, c2 = idx & 31;
        int grow = row0 + r;
        int q  = grow & (S-1);
        int bb = grow >> 10;
        int hh = c2 >> 2;
        int bh = bb*8 + hh;
        int off = (c2 & 3)*2;
        const float* p0 = g_part + ((size_t)(0*128 + bh)*S + q)*12;
        const float* p1 = g_part + ((size_t)(1*128 + bh)*S + q)*12;
        float inv = 1.0f / (p0[8] + p1[8]);
        float a0 = (p0[off]   + p1[off])   * inv;
        float a1 = (p0[off+1] + p1[off+1]) * inv;
        sA[r*36 + c2] = cvt_f16x2(a1, a0);
    }
    CP_WAIT(2);        // Wo ready
    __syncthreads();

    int warp = tid >> 5, lane = tid & 31;
    int gid = lane >> 2, tig = lane & 3;
    int rA = row0 + warp*16 + gid;
    int rB = rA + 8;

    // ---- oproj ----
    uint a[4][4];
    load_afrag64(a, sA, warp*16, gid, tig);
    float acc[8][4];
#pragma unroll
    for (int t = 0; t < 8; t++) {
        acc[t][0]=0; acc[t][1]=0; acc[t][2]=0; acc[t][3]=0;
#pragma unroll
        for (int kk = 0; kk < 4; kk++) {
            uint b0 = sWo[(kk*8 + tig)*68 + t*8 + gid];
            uint b1 = sWo[(kk*8 + 4 + tig)*68 + t*8 + gid];
            mma16n8k16(acc[t], a[kk][0], a[kk][1], a[kk][2], a[kk][3], b0, b1);
        }
    }
    float vA[16], vB[16];
    {
        float sumA=0, sqA=0, sumB=0, sqB=0;
#pragma unroll
        for (int t = 0; t < 8; t++) {
            float2 bo2 = *(const float2*)(bo + l*D + t*8 + tig*2);
            float2 hA = *(const float2*)(g_h + (size_t)rA*D + t*8 + tig*2);
            float2 hB = *(const float2*)(g_h + (size_t)rB*D + t*8 + tig*2);
            float a0 = acc[t][0] + bo2.x + hA.x;
            float a1 = acc[t][1] + bo2.y + hA.y;
            float b0 = acc[t][2] + bo2.x + hB.x;
            float b1 = acc[t][3] + bo2.y + hB.y;
            vA[t*2]=a0; vA[t*2+1]=a1; vB[t*2]=b0; vB[t*2+1]=b1;
            sumA += a0+a1; sqA += a0*a0+a1*a1;
            sumB += b0+b1; sqB += b0*b0+b1*b1;
        }
#pragma unroll
        for (int o = 1; o < 4; o <<= 1) {
            sumA += __shfl_xor_sync(0xffffffffu, sumA, o);
            sqA  += __shfl_xor_sync(0xffffffffu, sqA,  o);
            sumB += __shfl_xor_sync(0xffffffffu, sumB, o);
            sqB  += __shfl_xor_sync(0xffffffffu, sqB,  o);
        }
        float mA = sumA*(1.f/64.f), vrA = sqA*(1.f/64.f) - mA*mA;
        float mB = sumB*(1.f/64.f), vrB = sqB*(1.f/64.f) - mB*mB;
        float rsA = rsqrtf(vrA + 1e-5f), rsB = rsqrtf(vrB + 1e-5f);
#pragma unroll
        for (int t = 0; t < 8; t++) {
            float2 gg = *(const float2*)(g1 + l*D + t*8 + tig*2);
            float2 bb = *(const float2*)(b1 + l*D + t*8 + tig*2);
            vA[t*2]   = (vA[t*2]  -mA)*rsA*gg.x + bb.x;
            vA[t*2+1] = (vA[t*2+1]-mA)*rsA*gg.y + bb.y;
            vB[t*2]   = (vB[t*2]  -mB)*rsB*gg.x + bb.x;
            vB[t*2+1] = (vB[t*2+1]-mB)*rsB*gg.y + bb.y;
        }
    }
    __syncthreads();   // afrags consumed; safe to overwrite sA
#pragma unroll
    for (int t = 0; t < 8; t++) {
        sA[(warp*16 + gid)*36     + t*4 + tig] = cvt_f16x2(vA[t*2+1], vA[t*2]);
        sA[(warp*16 + gid + 8)*36 + t*4 + tig] = cvt_f16x2(vB[t*2+1], vB[t*2]);
    }
    CP_WAIT(1);        // W1 ready
    __syncthreads();

    // ---- FFN phase 1 ----
    uint a2[4][4];
    load_afrag64(a2, sA, warp*16, gid, tig);
    uint hA[16][2];
#pragma unroll
    for (int t = 0; t < 16; t++) {
        float facc[4] = {0,0,0,0};
#pragma unroll
        for (int kk = 0; kk < 4; kk++) {
            uint b0 = sW1[(kk*8 + tig)*132 + t*8 + gid];
            uint b1 = sW1[(kk*8 + 4 + tig)*132 + t*8 + gid];
            mma16n8k16(facc, a2[kk][0], a2[kk][1], a2[kk][2], a2[kk][3], b0, b1);
        }
        float2 bf = *(const float2*)(bf1 + l*FF + t*8 + tig*2);
        float c0 = fmaxf(facc[0] + bf.x, 0.f);
        float c1 = fmaxf(facc[1] + bf.y, 0.f);
        float c2 = fmaxf(facc[2] + bf.x, 0.f);
        float c3 = fmaxf(facc[3] + bf.y, 0.f);
        hA[t][0] = cvt_f16x2(c1, c0);
        hA[t][1] = cvt_f16x2(c3, c2);
    }
    CP_WAIT(0);        // W2 ready
    __syncthreads();

    // ---- FFN phase 2 ----
#pragma unroll
    for (int t = 0; t < 8; t++) {
        acc[t][0]=0; acc[t][1]=0; acc[t][2]=0; acc[t][3]=0;
#pragma unroll
        for (int kk = 0; kk < 8; kk++) {
            uint b0 = sW2[(kk*8 + tig)*68 + t*8 + gid];
            uint b1 = sW2[(kk*8 + 4 + tig)*68 + t*8 + gid];
            mma16n8k16(acc[t], hA[2*kk][0], hA[2*kk][1], hA[2*kk+1][0], hA[2*kk+1][1], b0, b1);
        }
    }
    {
        float sumA=0, sqA=0, sumB=0, sqB=0;
        float wA[16], wB[16];
#pragma unroll
        for (int t = 0; t < 8; t++) {
            float2 bo2 = *(const float2*)(bf2 + l*D + t*8 + tig*2);
            float a0 = acc[t][0] + bo2.x + vA[t*2];
            float a1 = acc[t][1] + bo2.y + vA[t*2+1];
            float b0 = acc[t][2] + bo2.x + vB[t*2];
            float b1 = acc[t][3] + bo2.y + vB[t*2+1];
            wA[t*2]=a0; wA[t*2+1]=a1; wB[t*2]=b0; wB[t*2+1]=b1;
            sumA += a0+a1; sqA += a0*a0+a1*a1;
            sumB += b0+b1; sqB += b0*b0+b1*b1;
        }
#pragma unroll
        for (int o = 1; o < 4; o <<= 1) {
            sumA += __shfl_xor_sync(0xffffffffu, sumA, o);
            sqA  += __shfl_xor_sync(0xffffffffu, sqA,  o);
            sumB += __shfl_xor_sync(0xffffffffu, sumB, o);
            sqB  += __shfl_xor_sync(0xffffffffu, sqB,  o);
        }
        float mA = sumA*(1.f/64.f), vrA = sqA*(1.f/64.f) - mA*mA;
        float mB = sumB*(1.f/64.f), vrB = sqB*(1.f/64.f) - mB*mB;
        float rsA = rsqrtf(vrA + 1e-5f), rsB = rsqrtf(vrB + 1e-5f);
#pragma unroll
        for (int t = 0; t < 8; t++) {
            float2 gg = *(const float2*)(g2 + l*D + t*8 + tig*2);
            float2 bb = *(const float2*)(b2 + l*D + t*8 + tig*2);
            *(float2*)(g_h + (size_t)rA*D + t*8 + tig*2) =
                make_float2((wA[t*2]-mA)*rsA*gg.x + bb.x, (wA[t*2+1]-mA)*rsA*gg.y + bb.y);
            *(float2*)(g_h + (size_t)rB*D + t*8 + tig*2) =
                make_float2((wB[t*2]-mB)*rsB*gg.x + bb.x, (wB[t*2+1]-mB)*rsB*gg.y + bb.y);
        }
    }
}

// ---------------- 4a) pool partials ----------------
__global__ void k_pool(void) {
    __shared__ float sp2[256];
    int b = blockIdx.x, sc = blockIdx.y, tid = threadIdx.x;
    int col = tid & 63, ch = tid >> 6;
    const float* hb = g_h + (size_t)b*S*D + ((size_t)sc*256 + ch*64)*D;
    float sum = 0.f;
#pragma unroll 8
    for (int s = 0; s < 64; s++) sum += hb[s*D + col];
    sp2[tid] = sum;
    __syncthreads();
    if (tid < 64)
        g_poolp[(b*4 + sc)*D + tid] = sp2[tid] + sp2[tid+64] + sp2[tid+128] + sp2[tid+192];
}

// ---------------- 4b) MLP head + quantum circuit + <Z> + entropy ----------------
#define BARS128() asm volatile("bar.sync 1, 128;" ::: "memory")

__global__ void k_quantum(const float* __restrict__ Wp1, const float* __restrict__ bp1,
                          const float* __restrict__ Wp2, const float* __restrict__ bp2,
                          const float* __restrict__ qw, float* __restrict__ out) {
    __shared__ float sp[64];
    __shared__ float sh[32];
    __shared__ float sang[8];
    __shared__ float2 st[256];
    __shared__ float2 rho[256];
    __shared__ float  sred[256];
    __shared__ float  jc[8], js[8], jpx[8], jpy[8];
    int b = blockIdx.x, tid = threadIdx.x;

    if (tid < 64) {
        const float* pp = g_poolp + b*4*D;
        sp[tid] = (pp[tid] + pp[D+tid] + pp[2*D+tid] + pp[3*D+tid]) * (1.0f/(float)S);
    }
    __syncthreads();
    if (tid < 32) {
        float a = bp1[tid];
#pragma unroll
        for (int i = 0; i < 64; i++) a += sp[i] * Wp1[i*32 + tid];
        sh[tid] = fmaxf(a, 0.f);
    }
    __syncthreads();
    if (tid < 8) {
        float a = bp2[tid];
#pragma unroll
        for (int i = 0; i < 32; i++) a += sh[i] * Wp2[i*8 + tid];
        sang[tid] = tanhf(a) * 3.14159265358979f;
    }

    st[tid] = make_float2(tid == 0 ? 1.f : 0.f, 0.f);
    __syncthreads();

    for (int l = 0; l < QL; l++) {
        for (int w = 0; w < NQ; w++) {
            int mask = 1 << (7 - w);
            float c = cosf(0.5f * sang[w]);
            float s = sinf(0.5f * sang[w]);
            if (!(tid & mask)) {
                float2 v0 = st[tid], v1 = st[tid | mask];
                st[tid]        = make_float2(c*v0.x + s*v1.y,  c*v0.y - s*v1.x);
                st[tid | mask] = make_float2(s*v0.y + c*v1.x, -s*v0.x + c*v1.y);
            }
            __syncthreads();
        }
        for (int w = 0; w < NQ; w++) {
            int mask = 1 << (7 - w);
            float phi = qw[(l*NQ + w)*3 + 0];
            float th  = qw[(l*NQ + w)*3 + 1];
            float om  = qw[(l*NQ + w)*3 + 2];
            float ct = cosf(0.5f*th), stt = sinf(0.5f*th);
            float aa = 0.5f*(phi + om), bb = 0.5f*(phi - om);
            float ca = cosf(aa), sa = sinf(aa), cb = cosf(bb), sb = sinf(bb);
            float2 U00 = make_float2( ct*ca, -ct*sa);
            float2 U01 = make_float2(-stt*cb, -stt*sb);
            float2 U10 = make_float2( stt*cb, -stt*sb);
            float2 U11 = make_float2( ct*ca,  ct*sa);
            if (!(tid & mask)) {
                float2 v0 = st[tid], v1 = st[tid | mask];
                st[tid]        = cadd(cmul(U00, v0), cmul(U01, v1));
                st[tid | mask] = cadd(cmul(U10, v0), cmul(U11, v1));
            }
            __syncthreads();
        }
        for (int w = 0; w < NQ; w++) {
            int mc = 1 << (7 - w);
            int mt = 1 << (7 - ((w + 1) & 7));
            if ((tid & mc) && !(tid & mt)) {
                float2 t0 = st[tid];
                st[tid] = st[tid | mt];
                st[tid | mt] = t0;
            }
            __syncthreads();
        }
    }

    float p = st[tid].x*st[tid].x + st[tid].y*st[tid].y;
    for (int w = 0; w < 3; w++) {
        sred[tid] = (tid & (1 << (7 - w))) ? -p : p;
        __syncthreads();
        for (int off = 128; off > 0; off >>= 1) {
            if (tid < off) sred[tid] += sred[tid + off];
            __syncthreads();
        }
        if (tid == 0) out[b*3 + w] = sred[0];
        __syncthreads();
    }

    {
        int r = tid >> 4, c = tid & 15;
        float2 acc = make_float2(0.f, 0.f);
#pragma unroll
        for (int k = 0; k < 16; k++) {
            float2 mr = st[r*16 + k], mcv = st[c*16 + k];
            acc.x += mr.x*mcv.x + mr.y*mcv.y;
            acc.y += mr.y*mcv.x - mr.x*mcv.y;
        }
        rho[tid] = acc;
    }
    __syncthreads();

    if (tid < 128) {
        int g = tid >> 4, k = tid & 15;
        for (int sweep = 0; sweep < 6; sweep++) {
            for (int rnd = 0; rnd < 15; rnd++) {
                int pa, qa_;
                if (g == 0) { pa = 15; qa_ = rnd; }
                else {
                    pa  = (rnd + g) % 15;
                    qa_ = (rnd + 15 - g) % 15;
                }
                int pp = min(pa, qa_), qq = max(pa, qa_);
                if (k == 0) {
                    float2 apq = rho[pp*16 + qq];
                    float b2v = apq.x*apq.x + apq.y*apq.y;
                    if (b2v > 1e-26f) {
                        float app = rho[pp*16 + pp].x;
                        float aqq = rho[qq*16 + qq].x;
                        float bn  = sqrtf(b2v);
                        float tau = (aqq - app) / (2.f * bn);
                        float rt  = sqrtf(1.f + tau*tau);
                        float t   = (tau >= 0.f) ? 1.f/(tau + rt) : -1.f/(-tau + rt);
                        float cc  = rsqrtf(1.f + t*t);
                        jc[g] = cc; js[g] = t*cc;
                        jpx[g] = apq.x/bn; jpy[g] = apq.y/bn;
                    } else {
                        jc[g] = 1.f; js[g] = 0.f; jpx[g] = 1.f; jpy[g] = 0.f;
                    }
                }
                BARS128();
                float cc = jc[g], ss = js[g];
                float2 ph = make_float2(jpx[g], jpy[g]);
                {
                    float2 rp = rho[pp*16 + k], rq = rho[qq*16 + k];
                    float2 prq  = cmul(ph, rq);
                    float2 cprp = cmulcj(ph, rp);
                    rho[pp*16 + k] = make_float2(cc*rp.x - ss*prq.x,  cc*rp.y - ss*prq.y);
                    rho[qq*16 + k] = make_float2(ss*cprp.x + cc*rq.x, ss*cprp.y + cc*rq.y);
                }
                BARS128();
                {
                    float2 cp = rho[k*16 + pp], cq = rho[k*16 + qq];
                    float2 ccq = cmulcj(ph, cq);
                    float2 pcp = cmul(ph, cp);
                    rho[k*16 + pp] = make_float2(cc*cp.x - ss*ccq.x,  cc*cp.y - ss*ccq.y);
                    rho[k*16 + qq] = make_float2(ss*pcp.x + cc*cq.x, ss*pcp.y + cc*cq.y);
                }
                BARS128();
            }
        }
        if (tid == 0) {
            float ent = 0.f;
#pragma unroll
            for (int kk = 0; kk < 16; kk++) {
                float ev = rho[kk*16 + kk].x;
                ev = fminf(fmaxf(ev, 1e-10f), 1.f);
                ent -= ev * logf(ev);
            }
            out[48 + b] = ent;
        }
    }
}

// ---------------- launch ----------------
extern "C" void kernel_launch(void* const* d_in, const int* in_sizes, int n_in,
                              void* d_out, int out_size) {
    const float* x    = (const float*)d_in[0];
    const float* Wemb = (const float*)d_in[1];
    const float* bemb = (const float*)d_in[2];
    const float* Wq   = (const float*)d_in[3];
    const float* bq   = (const float*)d_in[4];
    const float* Wk   = (const float*)d_in[5];
    const float* bk   = (const float*)d_in[6];
    const float* Wv   = (const float*)d_in[7];
    const float* bv   = (const float*)d_in[8];
    const float* Wo   = (const float*)d_in[9];
    const float* bo   = (const float*)d_in[10];
    const float* ln1g = (const float*)d_in[11];
    const float* ln1b = (const float*)d_in[12];
    const float* ln2g = (const float*)d_in[13];
    const float* ln2b = (const float*)d_in[14];
    const float* Wf1  = (const float*)d_in[15];
    const float* bf1  = (const float*)d_in[16];
    const float* Wf2  = (const float*)d_in[17];
    const float* bf2  = (const float*)d_in[18];
    const float* Wp1  = (const float*)d_in[19];
    const float* bp1  = (const float*)d_in[20];
    const float* Wp2  = (const float*)d_in[21];
    const float* bp2  = (const float*)d_in[22];
    const float* qw   = (const float*)d_in[23];
    float* out = (float*)d_out;

    k_init<<<128 + NL*64, 256>>>(Wq, Wk, Wv, Wo, Wf1, Wf2);
    for (int l = 0; l < NL; l++) {
        dim3 qg(512, 3);
        k_qkv_mma<<<qg, 64>>>(bq, bk, bv, x, Wemb, bemb, l);
        dim3 ag(16, B*H);
        k_attn_mma<<<ag, 128>>>();
        k_block_mma<<<512, 64>>>(bo, ln1g, ln1b, bf1, bf2, ln2g, ln2b, l);
    }
    dim3 pg(B, 4);
    k_pool<<<pg, 256>>>();
    k_quantum<<<B, 256>>>(Wp1, bp1, Wp2, bp2, qw, out);
}

// round 14
// speedup vs baseline: 1.3134x; 1.0266x over previous
#include <cuda_runtime.h>
#include <cuda_fp16.h>
#include <math.h>

#define B   16
#define S   1024
#define NF  5
#define D   64
#define H   8
#define HD  8
#define NL  2
#define FF  128
#define NQ  8
#define QL  3
#define BS  (B*S)
#define CK2  512
#define VPAD2 520

typedef unsigned long long ull;
typedef unsigned int uint;

// ---------------- device scratch ----------------
__device__ float g_h  [BS*D];
__device__ float g_q  [BS*D];
__device__ float g_k  [BS*D];
__device__ float g_v  [BS*D];
__device__ float g_pe [S*D];
__device__ uint  g_parth[(size_t)2*128*S*6];   // 6.3 MB fp16 partials (4 half2 + lsum f32 + pad)
__device__ float g_poolp[B*4*D];
// prepacked half2 weights (B-fragment layout)
__device__ uint g_pWq[NL*32*68];
__device__ uint g_pWk[NL*32*68];
__device__ uint g_pWv[NL*32*68];
__device__ uint g_pWo[NL*32*68];
__device__ uint g_pW1[NL*32*132];
__device__ uint g_pW2[NL*64*68];

// ---------------- mma / f16 / async helpers ----------------
__device__ __forceinline__ void mma16n8k8_f16(uint& d0, uint& d1, uint a0, uint a1, uint b0) {
    asm volatile("mma.sync.aligned.m16n8k8.row.col.f16.f16.f16.f16 "
        "{%0,%1}, {%2,%3}, {%4}, {%5,%6};"
        : "=r"(d0), "=r"(d1)
        : "r"(a0), "r"(a1), "r"(b0), "r"(0u), "r"(0u));
}
__device__ __forceinline__ void mma16n8k16(float* d,
                                           uint a0, uint a1, uint a2, uint a3,
                                           uint b0, uint b1) {
    asm volatile("mma.sync.aligned.m16n8k16.row.col.f32.f16.f16.f32 "
        "{%0,%1,%2,%3}, {%4,%5,%6,%7}, {%8,%9}, {%0,%1,%2,%3};"
        : "+f"(d[0]), "+f"(d[1]), "+f"(d[2]), "+f"(d[3])
        : "r"(a0), "r"(a1), "r"(a2), "r"(a3), "r"(b0), "r"(b1));
}
__device__ __forceinline__ uint cvt_f16x2(float hi, float lo) {
    uint r; asm("cvt.rn.f16x2.f32 %0, %1, %2;" : "=r"(r) : "f"(hi), "f"(lo)); return r;
}
__device__ __forceinline__ uint hex2x2(uint x) {
    uint r; asm("ex2.approx.f16x2 %0, %1;" : "=r"(r) : "r"(x)); return r;
}
__device__ __forceinline__ void cpasync16(uint smem_addr, const void* gptr) {
    asm volatile("cp.async.cg.shared.global [%0], [%1], 16;" :: "r"(smem_addr), "l"(gptr));
}
#define CP_COMMIT()  asm volatile("cp.async.commit_group;" ::: "memory")
#define CP_WAIT(n)   asm volatile("cp.async.wait_group %0;" :: "n"(n) : "memory")
__device__ __forceinline__ uint smem_u32p(const void* p) {
    return (uint)__cvta_generic_to_shared(p);
}

// ---------------- complex helpers ----------------
__device__ __forceinline__ float2 cmul(float2 a, float2 b) {
    return make_float2(a.x*b.x - a.y*b.y, a.x*b.y + a.y*b.x);
}
__device__ __forceinline__ float2 cmulcj(float2 a, float2 b) {
    return make_float2(a.x*b.x + a.y*b.y, a.x*b.y - a.y*b.x);
}
__device__ __forceinline__ float2 cadd(float2 a, float2 b) {
    return make_float2(a.x + b.x, a.y + b.y);
}

// ---------------- 0) init: pe table + weight prepack ----------------
__global__ void k_init(const float* __restrict__ Wq, const float* __restrict__ Wk,
                       const float* __restrict__ Wv, const float* __restrict__ Wo,
                       const float* __restrict__ Wf1, const float* __restrict__ Wf2) {
    int bidx = blockIdx.x;
    int tid = threadIdx.x;
    if (bidx < 128) {
        int idx = bidx * 256 + tid;
        int s = idx >> 5, p = idx & 31;
        float div = __expf(-0.14391156831212787f * (float)(2*p));
        float sn, cs;
        sincosf((float)s * div, &sn, &cs);
        g_pe[s*64 + 2*p]     = sn;
        g_pe[s*64 + 2*p + 1] = cs;
    } else {
        int idx = (bidx - 128) * 256 + tid;    // < NL*16384
        int l = idx / 16384;
        int r = idx % 16384;
        if (r < 8192) {
            int m = r >> 11;
            int q = r & 2047;
            int ip = q >> 6, n = q & 63;
            const float* W = (m == 0) ? (Wq + l*4096) : (m == 1) ? (Wk + l*4096)
                           : (m == 2) ? (Wv + l*4096) : (Wo + l*4096);
            uint* dst = (m == 0) ? g_pWq : (m == 1) ? g_pWk : (m == 2) ? g_pWv : g_pWo;
            dst[l*2176 + ip*68 + n] = cvt_f16x2(W[(2*ip+1)*64 + n], W[(2*ip)*64 + n]);
        } else if (r < 12288) {
            int q = r - 8192;
            int ip = q >> 7, n = q & 127;
            const float* W = Wf1 + l*8192;
            g_pW1[l*4224 + ip*132 + n] = cvt_f16x2(W[(2*ip+1)*128 + n], W[(2*ip)*128 + n]);
        } else {
            int q = r - 12288;
            int ip = q >> 6, n = q & 63;
            const float* W = Wf2 + l*8192;
            g_pW2[l*4352 + ip*68 + n] = cvt_f16x2(W[(2*ip+1)*64 + n], W[(2*ip)*64 + n]);
        }
    }
}

// ======== MMA GEMM common fragment loaders ========
__device__ __forceinline__ void load_afrag64(uint (&a)[4][4], const uint* sA, int rbase, int gid, int tig) {
    const uint* r0 = sA + (rbase + gid)*36;
    const uint* r1 = sA + (rbase + gid + 8)*36;
#pragma unroll
    for (int kk = 0; kk < 4; kk++) {
        a[kk][0] = r0[kk*8 + tig];
        a[kk][1] = r1[kk*8 + tig];
        a[kk][2] = r0[kk*8 + 4 + tig];
        a[kk][3] = r1[kk*8 + 4 + tig];
    }
}

// ---------------- 1) QKV projection: cp.async-staged weights ----------------
__global__ void __launch_bounds__(64) k_qkv_mma(
        const float* __restrict__ bq, const float* __restrict__ bk,
        const float* __restrict__ bv,
        const float* __restrict__ x,  const float* __restrict__ Wemb,
        const float* __restrict__ bemb, int l) {
    __shared__ uint  sA [32*36];
    __shared__ uint  sW [2176];
    __shared__ float sX [32*NF];
    int tid = threadIdx.x;
    int row0 = blockIdx.x * 32;
    int m = blockIdx.y;
    const uint* pW    = ((m == 0) ? g_pWq : (m == 1) ? g_pWk : g_pWv) + l*2176;
    const float* bias = ((m == 0) ? bq : (m == 1) ? bk : bv) + l*D;
    float* out        = (m == 0) ? g_q : (m == 1) ? g_k : g_v;

    {
        uint sw = smem_u32p(sW);
        for (int i = tid; i < 544; i += 64)
            cpasync16(sw + i*16, pW + i*4);
        CP_COMMIT();
    }

    if (l == 0) {
        for (int idx = tid; idx < 32*NF; idx += 64)
            sX[idx] = x[(size_t)(row0 + idx/NF)*NF + idx%NF];
        __syncthreads();
        for (int idx = tid; idx < 1024; idx += 64) {
            int r = idx >> 5, c2 = idx & 31;
            int row = row0 + r;
            int s = row & (S-1);
            int c = c2*2;
            float v0 = bemb[c]   + g_pe[s*64 + c];
            float v1 = bemb[c+1] + g_pe[s*64 + c + 1];
            const float* xr = sX + r*NF;
#pragma unroll
            for (int f = 0; f < NF; f++) {
                v0 += xr[f] * Wemb[f*D + c];
                v1 += xr[f] * Wemb[f*D + c + 1];
            }
            sA[r*36 + c2] = cvt_f16x2(v1, v0);
            if (m == 0) *(float2*)(g_h + (size_t)row*D + c) = make_float2(v0, v1);
        }
    } else {
        for (int idx = tid; idx < 1024; idx += 64) {
            int r = idx >> 5, c2 = idx & 31;
            float2 v = *(const float2*)(g_h + (size_t)(row0 + r)*D + c2*2);
            sA[r*36 + c2] = cvt_f16x2(v.y, v.x);
        }
    }
    CP_WAIT(0);
    __syncthreads();

    int warp = tid >> 5, lane = tid & 31;
    int gid = lane >> 2, tig = lane & 3;
    uint a[4][4];
    load_afrag64(a, sA, warp*16, gid, tig);

#pragma unroll
    for (int t = 0; t < 8; t++) {
        float acc[4] = {0,0,0,0};
#pragma unroll
        for (int kk = 0; kk < 4; kk++) {
            uint b0 = sW[(kk*8 + tig)*68 + t*8 + gid];
            uint b1 = sW[(kk*8 + 4 + tig)*68 + t*8 + gid];
            mma16n8k16(acc, a[kk][0], a[kk][1], a[kk][2], a[kk][3], b0, b1);
        }
        float2 bv2 = *(const float2*)(bias + t*8 + tig*2);
        int r = row0 + warp*16 + gid;
        *(float2*)(out + (size_t)r*D + t*8 + tig*2) =
            make_float2(acc[0] + bv2.x, acc[1] + bv2.y);
        *(float2*)(out + (size_t)(r + 8)*D + t*8 + tig*2) =
            make_float2(acc[2] + bv2.x, acc[3] + bv2.y);
    }
}

// ---------------- 2) split-K attention: E/O chains, fp16 partial store ----------------
__global__ void __launch_bounds__(128) k_attn_mma() {
    __shared__ __half sK [CK2*8];
    __shared__ __half sVT[8*VPAD2];
    int tid = threadIdx.x;
    int bh  = blockIdx.y;
    int b   = bh >> 3, hh = bh & 7;
    int qt  = blockIdx.x >> 1;
    int ck  = blockIdx.x & 1;
    int k0  = ck * CK2;
    const float* kbase = g_k + (size_t)(b*S + k0)*D + hh*HD;
    const float* vbase = g_v + (size_t)(b*S + k0)*D + hh*HD;
    const float pre = 0.35355339059327373f * 1.4426950408889634f;
    for (int i = tid; i < CK2*8; i += 128) {
        int key = i >> 3, d = i & 7;
        sK[i]             = __float2half(kbase[key*D + d] * pre);
        sVT[d*VPAD2 + key] = __float2half(vbase[key*D + d]);
    }
    __syncthreads();

    int warp = tid >> 5, lane = tid & 31;
    int gid  = lane >> 2, tig = lane & 3;
    int q0   = qt * 128 + warp * 32;

    uint qa[2][2];
#pragma unroll
    for (int t2 = 0; t2 < 2; t2++) {
#pragma unroll
        for (int hf = 0; hf < 2; hf++) {
            int qrow = q0 + t2*16 + gid + hf*8;
            float2 qv = *(const float2*)(g_q + (size_t)(b*S + qrow)*D + hh*HD + tig*2);
            qa[t2][hf] = cvt_f16x2(qv.y, qv.x);
        }
    }

    float acc0E[4] = {0,0,0,0}, acc0O[4] = {0,0,0,0};
    float acc1E[4] = {0,0,0,0}, acc1O[4] = {0,0,0,0};
    float lac0E[4] = {0,0,0,0}, lac0O[4] = {0,0,0,0};
    float lac1E[4] = {0,0,0,0}, lac1O[4] = {0,0,0,0};
    const uint ones2 = 0x3C003C00u;
    const __half* kptr = sK  + gid*8 + tig*2;
    const __half* vptr = sVT + gid*VPAD2 + tig*2;

    for (int j0 = 0; j0 < CK2; j0 += 32) {
        uint kb0 = *(const uint*)(kptr + j0*8);
        uint kb1 = *(const uint*)(kptr + j0*8 + 64);
        uint kb2 = *(const uint*)(kptr + j0*8 + 128);
        uint kb3 = *(const uint*)(kptr + j0*8 + 192);
        uint vb0 = *(const uint*)(vptr + j0);
        uint vb1 = *(const uint*)(vptr + j0 + 8);
        uint vb2 = *(const uint*)(vptr + j0 + 16);
        uint vb3 = *(const uint*)(vptr + j0 + 24);
        {
            uint s01a, s23a, s01b, s23b;
            mma16n8k8_f16(s01a, s23a, qa[0][0], qa[0][1], kb0);
            mma16n8k8_f16(s01b, s23b, qa[0][0], qa[0][1], kb1);
            uint p0 = hex2x2(s01a), p1 = hex2x2(s23a);
            uint p2 = hex2x2(s01b), p3 = hex2x2(s23b);
            mma16n8k16(acc0E, p0, p1, p2, p3, vb0, vb1);
            mma16n8k16(lac0E, p0, p1, p2, p3, ones2, ones2);
        }
        {
            uint s01a, s23a, s01b, s23b;
            mma16n8k8_f16(s01a, s23a, qa[1][0], qa[1][1], kb0);
            mma16n8k8_f16(s01b, s23b, qa[1][0], qa[1][1], kb1);
            uint p0 = hex2x2(s01a), p1 = hex2x2(s23a);
            uint p2 = hex2x2(s01b), p3 = hex2x2(s23b);
            mma16n8k16(acc1E, p0, p1, p2, p3, vb0, vb1);
            mma16n8k16(lac1E, p0, p1, p2, p3, ones2, ones2);
        }
        {
            uint s01a, s23a, s01b, s23b;
            mma16n8k8_f16(s01a, s23a, qa[0][0], qa[0][1], kb2);
            mma16n8k8_f16(s01b, s23b, qa[0][0], qa[0][1], kb3);
            uint p0 = hex2x2(s01a), p1 = hex2x2(s23a);
            uint p2 = hex2x2(s01b), p3 = hex2x2(s23b);
            mma16n8k16(acc0O, p0, p1, p2, p3, vb2, vb3);
            mma16n8k16(lac0O, p0, p1, p2, p3, ones2, ones2);
        }
        {
            uint s01a, s23a, s01b, s23b;
            mma16n8k8_f16(s01a, s23a, qa[1][0], qa[1][1], kb2);
            mma16n8k8_f16(s01b, s23b, qa[1][0], qa[1][1], kb3);
            uint p0 = hex2x2(s01a), p1 = hex2x2(s23a);
            uint p2 = hex2x2(s01b), p3 = hex2x2(s23b);
            mma16n8k16(acc1O, p0, p1, p2, p3, vb2, vb3);
            mma16n8k16(lac1O, p0, p1, p2, p3, ones2, ones2);
        }
    }

    // merge + pack to fp16; layout [ck][bh][q][6 uints]: 4 half2 + lsum f32 + pad
    size_t base = ((size_t)ck*128 + bh)*S;
    {
        uint* pp = g_parth + (base + q0 + gid)*6;
        pp[tig] = cvt_f16x2(acc0E[1] + acc0O[1], acc0E[0] + acc0O[0]);
        if (tig == 0) pp[4] = __float_as_uint(lac0E[0] + lac0O[0]);
        pp = g_parth + (base + q0 + gid + 8)*6;
        pp[tig] = cvt_f16x2(acc0E[3] + acc0O[3], acc0E[2] + acc0O[2]);
        if (tig == 0) pp[4] = __float_as_uint(lac0E[2] + lac0O[2]);
        pp = g_parth + (base + q0 + 16 + gid)*6;
        pp[tig] = cvt_f16x2(acc1E[1] + acc1O[1], acc1E[0] + acc1O[0]);
        if (tig == 0) pp[4] = __float_as_uint(lac1E[0] + lac1O[0]);
        pp = g_parth + (base + q0 + 24 + gid)*6;
        pp[tig] = cvt_f16x2(acc1E[3] + acc1O[3], acc1E[2] + acc1O[2]);
        if (tig == 0) pp[4] = __float_as_uint(lac1E[2] + lac1O[2]);
    }
}

// ---------------- 3) FUSED block: cp.async-staged weights, fp16 partial combine ----------------
__global__ void __launch_bounds__(64) k_block_mma(
        const float* __restrict__ bo,
        const float* __restrict__ g1, const float* __restrict__ b1,
        const float* __restrict__ bf1, const float* __restrict__ bf2,
        const float* __restrict__ g2, const float* __restrict__ b2, int l) {
    __shared__ uint sA [32*36];
    __shared__ uint sWo[2176];
    __shared__ uint sW1[4224];
    __shared__ uint sW2[4352];
    int tid = threadIdx.x;
    int row0 = blockIdx.x * 32;

    {
        const uint* pWo = g_pWo + l*2176;
        const uint* pW1 = g_pW1 + l*4224;
        const uint* pW2 = g_pW2 + l*4352;
        uint so = smem_u32p(sWo), s1 = smem_u32p(sW1), s2 = smem_u32p(sW2);
        for (int i = tid; i < 544; i += 64)  cpasync16(so + i*16, pWo + i*4);
        CP_COMMIT();
        for (int i = tid; i < 1056; i += 64) cpasync16(s1 + i*16, pW1 + i*4);
        CP_COMMIT();
        for (int i = tid; i < 1088; i += 64) cpasync16(s2 + i*16, pW2 + i*4);
        CP_COMMIT();
    }

    // combine fp16 partials -> normalized attention output (fp16 A)
    for (int idx = tid; idx < 1024; idx += 64) {
        int r = idx >> 5, c2 = idx & 31;
        int grow = row0 + r;
        int q  = grow & (S-1);
        int bb = grow >> 10;
        int hh = c2 >> 2;
        int bh = bb*8 + hh;
        int pi = c2 & 3;
        const uint* p0 = g_parth + ((size_t)(0*128 + bh)*S + q)*6;
        const uint* p1 = g_parth + ((size_t)(1*128 + bh)*S + q)*6;
        float2 a0 = __half22float2(*(const __half2*)&p0[pi]);
        float2 a1 = __half22float2(*(const __half2*)&p1[pi]);
        float inv = 1.0f / (__uint_as_float(p0[4]) + __uint_as_float(p1[4]));
        sA[r*36 + c2] = cvt_f16x2((a0.y + a1.y) * inv, (a0.x + a1.x) * inv);
    }
    CP_WAIT(2);        // Wo ready
    __syncthreads();

    int warp = tid >> 5, lane = tid & 31;
    int gid = lane >> 2, tig = lane & 3;
    int rA = row0 + warp*16 + gid;
    int rB = rA + 8;

    // ---- oproj ----
    uint a[4][4];
    load_afrag64(a, sA, warp*16, gid, tig);
    float acc[8][4];
#pragma unroll
    for (int t = 0; t < 8; t++) {
        acc[t][0]=0; acc[t][1]=0; acc[t][2]=0; acc[t][3]=0;
#pragma unroll
        for (int kk = 0; kk < 4; kk++) {
            uint b0 = sWo[(kk*8 + tig)*68 + t*8 + gid];
            uint b1 = sWo[(kk*8 + 4 + tig)*68 + t*8 + gid];
            mma16n8k16(acc[t], a[kk][0], a[kk][1], a[kk][2], a[kk][3], b0, b1);
        }
    }
    float vA[16], vB[16];
    {
        float sumA=0, sqA=0, sumB=0, sqB=0;
#pragma unroll
        for (int t = 0; t < 8; t++) {
            float2 bo2 = *(const float2*)(bo + l*D + t*8 + tig*2);
            float2 hA = *(const float2*)(g_h + (size_t)rA*D + t*8 + tig*2);
            float2 hB = *(const float2*)(g_h + (size_t)rB*D + t*8 + tig*2);
            float a0 = acc[t][0] + bo2.x + hA.x;
            float a1 = acc[t][1] + bo2.y + hA.y;
            float b0 = acc[t][2] + bo2.x + hB.x;
            float b1 = acc[t][3] + bo2.y + hB.y;
            vA[t*2]=a0; vA[t*2+1]=a1; vB[t*2]=b0; vB[t*2+1]=b1;
            sumA += a0+a1; sqA += a0*a0+a1*a1;
            sumB += b0+b1; sqB += b0*b0+b1*b1;
        }
#pragma unroll
        for (int o = 1; o < 4; o <<= 1) {
            sumA += __shfl_xor_sync(0xffffffffu, sumA, o);
            sqA  += __shfl_xor_sync(0xffffffffu, sqA,  o);
            sumB += __shfl_xor_sync(0xffffffffu, sumB, o);
            sqB  += __shfl_xor_sync(0xffffffffu, sqB,  o);
        }
        float mA = sumA*(1.f/64.f), vrA = sqA*(1.f/64.f) - mA*mA;
        float mB = sumB*(1.f/64.f), vrB = sqB*(1.f/64.f) - mB*mB;
        float rsA = rsqrtf(vrA + 1e-5f), rsB = rsqrtf(vrB + 1e-5f);
#pragma unroll
        for (int t = 0; t < 8; t++) {
            float2 gg = *(const float2*)(g1 + l*D + t*8 + tig*2);
            float2 bb = *(const float2*)(b1 + l*D + t*8 + tig*2);
            vA[t*2]   = (vA[t*2]  -mA)*rsA*gg.x + bb.x;
            vA[t*2+1] = (vA[t*2+1]-mA)*rsA*gg.y + bb.y;
            vB[t*2]   = (vB[t*2]  -mB)*rsB*gg.x + bb.x;
            vB[t*2+1] = (vB[t*2+1]-mB)*rsB*gg.y + bb.y;
        }
    }
    __syncthreads();
#pragma unroll
    for (int t = 0; t < 8; t++) {
        sA[(warp*16 + gid)*36     + t*4 + tig] = cvt_f16x2(vA[t*2+1], vA[t*2]);
        sA[(warp*16 + gid + 8)*36 + t*4 + tig] = cvt_f16x2(vB[t*2+1], vB[t*2]);
    }
    CP_WAIT(1);        // W1 ready
    __syncthreads();

    // ---- FFN phase 1 ----
    uint a2[4][4];
    load_afrag64(a2, sA, warp*16, gid, tig);
    uint hA[16][2];
#pragma unroll
    for (int t = 0; t < 16; t++) {
        float facc[4] = {0,0,0,0};
#pragma unroll
        for (int kk = 0; kk < 4; kk++) {
            uint b0 = sW1[(kk*8 + tig)*132 + t*8 + gid];
            uint b1 = sW1[(kk*8 + 4 + tig)*132 + t*8 + gid];
            mma16n8k16(facc, a2[kk][0], a2[kk][1], a2[kk][2], a2[kk][3], b0, b1);
        }
        float2 bf = *(const float2*)(bf1 + l*FF + t*8 + tig*2);
        float c0 = fmaxf(facc[0] + bf.x, 0.f);
        float c1 = fmaxf(facc[1] + bf.y, 0.f);
        float c2 = fmaxf(facc[2] + bf.x, 0.f);
        float c3 = fmaxf(facc[3] + bf.y, 0.f);
        hA[t][0] = cvt_f16x2(c1, c0);
        hA[t][1] = cvt_f16x2(c3, c2);
    }
    CP_WAIT(0);        // W2 ready
    __syncthreads();

    // ---- FFN phase 2 ----
#pragma unroll
    for (int t = 0; t < 8; t++) {
        acc[t][0]=0; acc[t][1]=0; acc[t][2]=0; acc[t][3]=0;
#pragma unroll
        for (int kk = 0; kk < 8; kk++) {
            uint b0 = sW2[(kk*8 + tig)*68 + t*8 + gid];
            uint b1 = sW2[(kk*8 + 4 + tig)*68 + t*8 + gid];
            mma16n8k16(acc[t], hA[2*kk][0], hA[2*kk][1], hA[2*kk+1][0], hA[2*kk+1][1], b0, b1);
        }
    }
    {
        float sumA=0, sqA=0, sumB=0, sqB=0;
        float wA[16], wB[16];
#pragma unroll
        for (int t = 0; t < 8; t++) {
            float2 bo2 = *(const float2*)(bf2 + l*D + t*8 + tig*2);
            float a0 = acc[t][0] + bo2.x + vA[t*2];
            float a1 = acc[t][1] + bo2.y + vA[t*2+1];
            float b0 = acc[t][2] + bo2.x + vB[t*2];
            float b1 = acc[t][3] + bo2.y + vB[t*2+1];
            wA[t*2]=a0; wA[t*2+1]=a1; wB[t*2]=b0; wB[t*2+1]=b1;
            sumA += a0+a1; sqA += a0*a0+a1*a1;
            sumB += b0+b1; sqB += b0*b0+b1*b1;
        }
#pragma unroll
        for (int o = 1; o < 4; o <<= 1) {
            sumA += __shfl_xor_sync(0xffffffffu, sumA, o);
            sqA  += __shfl_xor_sync(0xffffffffu, sqA,  o);
            sumB += __shfl_xor_sync(0xffffffffu, sumB, o);
            sqB  += __shfl_xor_sync(0xffffffffu, sqB,  o);
        }
        float mA = sumA*(1.f/64.f), vrA = sqA*(1.f/64.f) - mA*mA;
        float mB = sumB*(1.f/64.f), vrB = sqB*(1.f/64.f) - mB*mB;
        float rsA = rsqrtf(vrA + 1e-5f), rsB = rsqrtf(vrB + 1e-5f);
#pragma unroll
        for (int t = 0; t < 8; t++) {
            float2 gg = *(const float2*)(g2 + l*D + t*8 + tig*2);
            float2 bb = *(const float2*)(b2 + l*D + t*8 + tig*2);
            *(float2*)(g_h + (size_t)rA*D + t*8 + tig*2) =
                make_float2((wA[t*2]-mA)*rsA*gg.x + bb.x, (wA[t*2+1]-mA)*rsA*gg.y + bb.y);
            *(float2*)(g_h + (size_t)rB*D + t*8 + tig*2) =
                make_float2((wB[t*2]-mB)*rsB*gg.x + bb.x, (wB[t*2+1]-mB)*rsB*gg.y + bb.y);
        }
    }
}

// ---------------- 4a) pool partials ----------------
__global__ void k_pool(void) {
    __shared__ float sp2[256];
    int b = blockIdx.x, sc = blockIdx.y, tid = threadIdx.x;
    int col = tid & 63, ch = tid >> 6;
    const float* hb = g_h + (size_t)b*S*D + ((size_t)sc*256 + ch*64)*D;
    float sum = 0.f;
#pragma unroll 8
    for (int s = 0; s < 64; s++) sum += hb[s*D + col];
    sp2[tid] = sum;
    __syncthreads();
    if (tid < 64)
        g_poolp[(b*4 + sc)*D + tid] = sp2[tid] + sp2[tid+64] + sp2[tid+128] + sp2[tid+192];
}

// ---------------- 4b) MLP head + quantum circuit + <Z> + entropy ----------------
#define BARS128() asm volatile("bar.sync 1, 128;" ::: "memory")

__global__ void k_quantum(const float* __restrict__ Wp1, const float* __restrict__ bp1,
                          const float* __restrict__ Wp2, const float* __restrict__ bp2,
                          const float* __restrict__ qw, float* __restrict__ out) {
    __shared__ float sp[64];
    __shared__ float sh[32];
    __shared__ float sang[8];
    __shared__ float2 st[256];
    __shared__ float2 rho[256];
    __shared__ float  sred[256];
    __shared__ float  jc[8], js[8], jpx[8], jpy[8];
    int b = blockIdx.x, tid = threadIdx.x;

    if (tid < 64) {
        const float* pp = g_poolp + b*4*D;
        sp[tid] = (pp[tid] + pp[D+tid] + pp[2*D+tid] + pp[3*D+tid]) * (1.0f/(float)S);
    }
    __syncthreads();
    if (tid < 32) {
        float a = bp1[tid];
#pragma unroll
        for (int i = 0; i < 64; i++) a += sp[i] * Wp1[i*32 + tid];
        sh[tid] = fmaxf(a, 0.f);
    }
    __syncthreads();
    if (tid < 8) {
        float a = bp2[tid];
#pragma unroll
        for (int i = 0; i < 32; i++) a += sh[i] * Wp2[i*8 + tid];
        sang[tid] = tanhf(a) * 3.14159265358979f;
    }

    st[tid] = make_float2(tid == 0 ? 1.f : 0.f, 0.f);
    __syncthreads();

    for (int l = 0; l < QL; l++) {
        for (int w = 0; w < NQ; w++) {
            int mask = 1 << (7 - w);
            float c = cosf(0.5f * sang[w]);
            float s = sinf(0.5f * sang[w]);
            if (!(tid & mask)) {
                float2 v0 = st[tid], v1 = st[tid | mask];
                st[tid]        = make_float2(c*v0.x + s*v1.y,  c*v0.y - s*v1.x);
                st[tid | mask] = make_float2(s*v0.y + c*v1.x, -s*v0.x + c*v1.y);
            }
            __syncthreads();
        }
        for (int w = 0; w < NQ; w++) {
            int mask = 1 << (7 - w);
            float phi = qw[(l*NQ + w)*3 + 0];
            float th  = qw[(l*NQ + w)*3 + 1];
            float om  = qw[(l*NQ + w)*3 + 2];
            float ct = cosf(0.5f*th), stt = sinf(0.5f*th);
            float aa = 0.5f*(phi + om), bb = 0.5f*(phi - om);
            float ca = cosf(aa), sa = sinf(aa), cb = cosf(bb), sb = sinf(bb);
            float2 U00 = make_float2( ct*ca, -ct*sa);
            float2 U01 = make_float2(-stt*cb, -stt*sb);
            float2 U10 = make_float2( stt*cb, -stt*sb);
            float2 U11 = make_float2( ct*ca,  ct*sa);
            if (!(tid & mask)) {
                float2 v0 = st[tid], v1 = st[tid | mask];
                st[tid]        = cadd(cmul(U00, v0), cmul(U01, v1));
                st[tid | mask] = cadd(cmul(U10, v0), cmul(U11, v1));
            }
            __syncthreads();
        }
        for (int w = 0; w < NQ; w++) {
            int mc = 1 << (7 - w);
            int mt = 1 << (7 - ((w + 1) & 7));
            if ((tid & mc) && !(tid & mt)) {
                float2 t0 = st[tid];
                st[tid] = st[tid | mt];
                st[tid | mt] = t0;
            }
            __syncthreads();
        }
    }

    float p = st[tid].x*st[tid].x + st[tid].y*st[tid].y;
    for (int w = 0; w < 3; w++) {
        sred[tid] = (tid & (1 << (7 - w))) ? -p : p;
        __syncthreads();
        for (int off = 128; off > 0; off >>= 1) {
            if (tid < off) sred[tid] += sred[tid + off];
            __syncthreads();
        }
        if (tid == 0) out[b*3 + w] = sred[0];
        __syncthreads();
    }

    {
        int r = tid >> 4, c = tid & 15;
        float2 acc = make_float2(0.f, 0.f);
#pragma unroll
        for (int k = 0; k < 16; k++) {
            float2 mr = st[r*16 + k], mcv = st[c*16 + k];
            acc.x += mr.x*mcv.x + mr.y*mcv.y;
            acc.y += mr.y*mcv.x - mr.x*mcv.y;
        }
        rho[tid] = acc;
    }
    __syncthreads();

    if (tid < 128) {
        int g = tid >> 4, k = tid & 15;
        for (int sweep = 0; sweep < 6; sweep++) {
            for (int rnd = 0; rnd < 15; rnd++) {
                int pa, qa_;
                if (g == 0) { pa = 15; qa_ = rnd; }
                else {
                    pa  = (rnd + g) % 15;
                    qa_ = (rnd + 15 - g) % 15;
                }
                int pp = min(pa, qa_), qq = max(pa, qa_);
                if (k == 0) {
                    float2 apq = rho[pp*16 + qq];
                    float b2v = apq.x*apq.x + apq.y*apq.y;
                    if (b2v > 1e-26f) {
                        float app = rho[pp*16 + pp].x;
                        float aqq = rho[qq*16 + qq].x;
                        float bn  = sqrtf(b2v);
                        float tau = (aqq - app) / (2.f * bn);
                        float rt  = sqrtf(1.f + tau*tau);
                        float t   = (tau >= 0.f) ? 1.f/(tau + rt) : -1.f/(-tau + rt);
                        float cc  = rsqrtf(1.f + t*t);
                        jc[g] = cc; js[g] = t*cc;
                        jpx[g] = apq.x/bn; jpy[g] = apq.y/bn;
                    } else {
                        jc[g] = 1.f; js[g] = 0.f; jpx[g] = 1.f; jpy[g] = 0.f;
                    }
                }
                BARS128();
                float cc = jc[g], ss = js[g];
                float2 ph = make_float2(jpx[g], jpy[g]);
                {
                    float2 rp = rho[pp*16 + k], rq = rho[qq*16 + k];
                    float2 prq  = cmul(ph, rq);
                    float2 cprp = cmulcj(ph, rp);
                    rho[pp*16 + k] = make_float2(cc*rp.x - ss*prq.x,  cc*rp.y - ss*prq.y);
                    rho[qq*16 + k] = make_float2(ss*cprp.x + cc*rq.x, ss*cprp.y + cc*rq.y);
                }
                BARS128();
                {
                    float2 cp = rho[k*16 + pp], cq = rho[k*16 + qq];
                    float2 ccq = cmulcj(ph, cq);
                    float2 pcp = cmul(ph, cp);
                    rho[k*16 + pp] = make_float2(cc*cp.x - ss*ccq.x,  cc*cp.y - ss*ccq.y);
                    rho[k*16 + qq] = make_float2(ss*pcp.x + cc*cq.x, ss*pcp.y + cc*cq.y);
                }
                BARS128();
            }
        }
        if (tid == 0) {
            float ent = 0.f;
#pragma unroll
            for (int kk = 0; kk < 16; kk++) {
                float ev = rho[kk*16 + kk].x;
                ev = fminf(fmaxf(ev, 1e-10f), 1.f);
                ent -= ev * logf(ev);
            }
            out[48 + b] = ent;
        }
    }
}

// ---------------- launch ----------------
extern "C" void kernel_launch(void* const* d_in, const int* in_sizes, int n_in,
                              void* d_out, int out_size) {
    const float* x    = (const float*)d_in[0];
    const float* Wemb = (const float*)d_in[1];
    const float* bemb = (const float*)d_in[2];
    const float* Wq   = (const float*)d_in[3];
    const float* bq   = (const float*)d_in[4];
    const float* Wk   = (const float*)d_in[5];
    const float* bk   = (const float*)d_in[6];
    const float* Wv   = (const float*)d_in[7];
    const float* bv   = (const float*)d_in[8];
    const float* Wo   = (const float*)d_in[9];
    const float* bo   = (const float*)d_in[10];
    const float* ln1g = (const float*)d_in[11];
    const float* ln1b = (const float*)d_in[12];
    const float* ln2g = (const float*)d_in[13];
    const float* ln2b = (const float*)d_in[14];
    const float* Wf1  = (const float*)d_in[15];
    const float* bf1  = (const float*)d_in[16];
    const float* Wf2  = (const float*)d_in[17];
    const float* bf2  = (const float*)d_in[18];
    const float* Wp1  = (const float*)d_in[19];
    const float* bp1  = (const float*)d_in[20];
    const float* Wp2  = (const float*)d_in[21];
    const float* bp2  = (const float*)d_in[22];
    const float* qw   = (const float*)d_in[23];
    float* out = (float*)d_out;

    k_init<<<128 + NL*64, 256>>>(Wq, Wk, Wv, Wo, Wf1, Wf2);
    for (int l = 0; l < NL; l++) {
        dim3 qg(512, 3);
        k_qkv_mma<<<qg, 64>>>(bq, bk, bv, x, Wemb, bemb, l);
        dim3 ag(16, B*H);
        k_attn_mma<<<ag, 128>>>();
        k_block_mma<<<512, 64>>>(bo, ln1g, ln1b, bf1, bf2, ln2g, ln2b, l);
    }
    dim3 pg(B, 4);
    k_pool<<<pg, 256>>>();
    k_quantum<<<B, 256>>>(Wp1, bp1, Wp2, bp2, qw, out);
}